// round 3
// baseline (speedup 1.0000x reference)
#include <cuda_runtime.h>
#include <math.h>

static constexpr int kT = 5, kB = 512, kNA = 16, kS = 64, kA = 16;
static constexpr int kHID = 64, kH = 4, kFD = 256, kLAT = 128;
static constexpr int kN = kB * kNA;
static constexpr int kFIN = 80;

// -------- scratch (static device globals; no runtime allocation) --------
__device__ float g_y   [(size_t)kB * kT * 4 * kFD];   // aggregated layer-1 inputs (B*T,4,256)
__device__ float g_seq [(size_t)kB * kT * kFD];
__device__ float g_qkv [(size_t)kB * kT * 3 * kFD];
__device__ float g_ctx4[(size_t)kB * kFD];
__device__ float g_feat[(size_t)kB * kFD];
__device__ float g_blog[(size_t)kB * kS];
__device__ float g_v1  [2 * 4 * kFD];                 // vsrc1 (4x256) then vdst1 (4x256)

// ===================================================================
// Precompute vsrc1[h][k] = sum_c asrc1[h][c] * w1[(h*64+c)][k]  (and vdst1)
// ===================================================================
__global__ __launch_bounds__(256)
void make_v1(const float* __restrict__ w1, const float* __restrict__ asrc1,
             const float* __restrict__ adst1, float* __restrict__ v1) {
    int idx = blockIdx.x * 256 + threadIdx.x;   // 0..2047
    int which = idx >> 10;
    int h = (idx >> 8) & 3;
    int k = idx & 255;
    const float* a = which ? adst1 : asrc1;
    float acc = 0.f;
#pragma unroll
    for (int c = 0; c < 64; c++)
        acc += a[h * 64 + c] * w1[(size_t)(h * 64 + c) * kFD + k];
    v1[which * 1024 + h * 256 + k] = acc;
}

// ===================================================================
// Fused GNN: per group g (=batch b), loop t:
// features -> lin0 -> GAT0 (softmax over 16 srcs, all 16 dsts) -> +bias0,relu
// -> e1 scores via vsrc1/vdst1 -> softmax1 (dst node 0 only) -> y[h] = sum alpha1*x1
// ===================================================================
__global__ __launch_bounds__(256)
void fused_gnn(const float* __restrict__ signals,   // (T,B,64)
               const float* __restrict__ nact,      // (T,B,256)
               const float* __restrict__ w0,        // (256,80)
               const float* __restrict__ asrc0, const float* __restrict__ adst0,
               const float* __restrict__ bias0,
               const float* __restrict__ v1,        // vsrc1|vdst1
               float* __restrict__ y) {             // (B*T,4,256)
    int g = blockIdx.x;
    int tid = threadIdx.x;
    __shared__ float xs[16][256];
    __shared__ float a0s[256], a0d[256];
    __shared__ float vs1[4][256], vd1[4][256];
    __shared__ float acts[16][16];
    __shared__ float sig[64];
    __shared__ float es0[16][4], ed0[16][4];
    __shared__ float alpha0[16][16][4];     // [dst][src][h]
    __shared__ float es1[16][4], ed1[4], alpha1[16][4];

    // per-thread weights: action part of w0 (column tid)
    float Wa[16];
#pragma unroll
    for (int k = 0; k < 16; k++) Wa[k] = w0[(size_t)tid * kFIN + 64 + k];
    a0s[tid] = asrc0[tid];
    a0d[tid] = adst0[tid];
#pragma unroll
    for (int h = 0; h < 4; h++) {
        vs1[h][tid] = v1[h * 256 + tid];
        vd1[h][tid] = v1[1024 + h * 256 + tid];
    }
    float b0 = bias0[tid];

    for (int t = 0; t < kT; t++) {
        __syncthreads();
        {   // load acts (16x16) and signals (64)
            int j = tid >> 4, k = tid & 15;
            acts[j][k] = nact[((size_t)t * kB + g) * (kNA * kA) + tid];
            if (tid < 64) sig[tid] = signals[((size_t)t * kB + g) * kS + tid];
        }
        __syncthreads();
        // lin0: xl0[j][tid]
        float xl0r[16];
#pragma unroll
        for (int j = 0; j < 16; j++) {
            float acc = 0.f;
#pragma unroll
            for (int k = 0; k < 16; k++) acc += acts[j][k] * Wa[k];
            xl0r[j] = acc;
        }
        {   // belief part: only node 0 nonzero
            float acc = 0.f;
#pragma unroll
            for (int c = 0; c < 64; c++) acc += sig[c] * w0[(size_t)tid * kFIN + c];
            xl0r[0] += acc;
        }
#pragma unroll
        for (int j = 0; j < 16; j++) xs[j][tid] = xl0r[j];
        __syncthreads();
        // es0/ed0: 128 dots of length 64; 2 threads per dot (all warps fully active)
        {
            int d = tid >> 1, half = tid & 1;
            int which = d >> 6;
            int q = d & 63, j = q >> 2, h = q & 3;
            const float* av = which ? a0d : a0s;
            float acc = 0.f;
#pragma unroll
            for (int c = half * 32; c < half * 32 + 32; c++)
                acc += xs[j][h * 64 + c] * av[h * 64 + c];
            acc += __shfl_xor_sync(0xffffffffu, acc, 1);
            if (half == 0) { if (which) ed0[j][h] = acc; else es0[j][h] = acc; }
        }
        __syncthreads();
        // softmax0 per (dst n, head h) over src j (16-lane groups within full warps)
        {
            int n = tid >> 4, j = tid & 15;
#pragma unroll
            for (int h = 0; h < 4; h++) {
                float e = es0[j][h] + ed0[n][h];
                e = e > 0.f ? e : 0.2f * e;
                float mx = e;
#pragma unroll
                for (int m = 8; m; m >>= 1) mx = fmaxf(mx, __shfl_xor_sync(0xffffffffu, mx, m));
                float ex = __expf(e - mx);
                float s = ex;
#pragma unroll
                for (int m = 8; m; m >>= 1) s += __shfl_xor_sync(0xffffffffu, s, m);
                alpha0[n][j][h] = ex / s;
            }
        }
        __syncthreads();
        // x1[n][tid] = relu(sum_j alpha0[n][j][h]*xl0[j][tid] + b0)
        float x1r[16];
        {
            int h = tid >> 6;
#pragma unroll
            for (int n = 0; n < 16; n++) {
                float acc = 0.f;
#pragma unroll
                for (int j = 0; j < 16; j++) acc += alpha0[n][j][h] * xl0r[j];
                x1r[n] = fmaxf(acc + b0, 0.f);
            }
        }
        __syncthreads();
#pragma unroll
        for (int n = 0; n < 16; n++) xs[n][tid] = x1r[n];
        __syncthreads();
        // es1[j][h] = x1[j] . vsrc1[h] : 64 dots of 256, 4 threads/dot (all warps active)
        {
            int p = tid >> 2, q = tid & 3;
            int j = p >> 2, h = p & 3;
            float acc = 0.f;
#pragma unroll
            for (int c = q * 64; c < q * 64 + 64; c++) acc += xs[j][c] * vs1[h][c];
            acc += __shfl_xor_sync(0xffffffffu, acc, 1);
            acc += __shfl_xor_sync(0xffffffffu, acc, 2);
            if (q == 0) es1[j][h] = acc;
        }
        // ed1[h] = x1[0] . vdst1[h] : FULL warp 0 active (fixes R2 deadlock:
        // shuffles with full mask must have the whole warp participating)
        if (tid < 32) {
            int h = tid >> 3, q = tid & 7;
            float acc = 0.f;
#pragma unroll
            for (int c = q * 32; c < q * 32 + 32; c++) acc += xs[0][c] * vd1[h][c];
            acc += __shfl_xor_sync(0xffffffffu, acc, 1);
            acc += __shfl_xor_sync(0xffffffffu, acc, 2);
            acc += __shfl_xor_sync(0xffffffffu, acc, 4);
            if (q == 0) ed1[h] = acc;
        }
        __syncthreads();
        // softmax1 over j per h (dst node 0 only); 64 threads = 2 full warps
        if (tid < 64) {
            int h = tid >> 4, j = tid & 15;
            float e = es1[j][h] + ed1[h];
            e = e > 0.f ? e : 0.2f * e;
            float mx = e;
#pragma unroll
            for (int m = 8; m; m >>= 1) mx = fmaxf(mx, __shfl_xor_sync(0xffffffffu, mx, m));
            float ex = __expf(e - mx);
            float s = ex;
#pragma unroll
            for (int m = 8; m; m >>= 1) s += __shfl_xor_sync(0xffffffffu, s, m);
            alpha1[j][h] = ex / s;
        }
        __syncthreads();
        // y[h][tid] = sum_j alpha1[j][h] * x1[j][tid]
#pragma unroll
        for (int h = 0; h < 4; h++) {
            float acc = 0.f;
#pragma unroll
            for (int j = 0; j < 16; j++) acc += alpha1[j][h] * x1r[j];
            y[(((size_t)g * kT + t) * 4 + h) * kFD + tid] = acc;
        }
    }
}

// ===================================================================
// SGEMM: C(M,Nc) = A(M,K) @ W(Nc,K)^T (+bias)(+relu). 128x128x16 tile.
// lda/ldc generalized. M % 128 == 0, K % 16 == 0. Nc guarded.
// ===================================================================
__global__ __launch_bounds__(256)
void sgemm_bias(const float* __restrict__ Ain, const float* __restrict__ W,
                const float* __restrict__ bias, float* __restrict__ C,
                int M, int Nc, int K, int lda, int ldc, int relu) {
    __shared__ float As[16][128];
    __shared__ float Bs[16][128];
    int tid = threadIdx.x;
    int row0 = blockIdx.x * 128;
    int col0 = blockIdx.y * 128;
    int tx = tid & 15, ty = tid >> 4;
    float acc[8][8];
#pragma unroll
    for (int i = 0; i < 8; i++)
#pragma unroll
        for (int j = 0; j < 8; j++) acc[i][j] = 0.f;

    for (int k0 = 0; k0 < K; k0 += 16) {
#pragma unroll
        for (int i = 0; i < 2; i++) {
            int f = tid + i * 256;
            int r = f >> 2;
            int kq = (f & 3) * 4;
            float4 v = *(const float4*)&Ain[(size_t)(row0 + r) * lda + k0 + kq];
            As[kq + 0][r] = v.x; As[kq + 1][r] = v.y;
            As[kq + 2][r] = v.z; As[kq + 3][r] = v.w;
        }
#pragma unroll
        for (int i = 0; i < 2; i++) {
            int f = tid + i * 256;
            int r = f >> 2;
            int kq = (f & 3) * 4;
            int col = col0 + r;
            float4 v = make_float4(0.f, 0.f, 0.f, 0.f);
            if (col < Nc) v = *(const float4*)&W[(size_t)col * K + k0 + kq];
            Bs[kq + 0][r] = v.x; Bs[kq + 1][r] = v.y;
            Bs[kq + 2][r] = v.z; Bs[kq + 3][r] = v.w;
        }
        __syncthreads();
#pragma unroll
        for (int k = 0; k < 16; k++) {
            float4 a0 = *(const float4*)&As[k][ty * 8];
            float4 a1 = *(const float4*)&As[k][ty * 8 + 4];
            float4 b0 = *(const float4*)&Bs[k][tx * 8];
            float4 b1 = *(const float4*)&Bs[k][tx * 8 + 4];
            float av[8] = {a0.x, a0.y, a0.z, a0.w, a1.x, a1.y, a1.z, a1.w};
            float bv[8] = {b0.x, b0.y, b0.z, b0.w, b1.x, b1.y, b1.z, b1.w};
#pragma unroll
            for (int i = 0; i < 8; i++)
#pragma unroll
                for (int j = 0; j < 8; j++) acc[i][j] += av[i] * bv[j];
        }
        __syncthreads();
    }
#pragma unroll
    for (int i = 0; i < 8; i++) {
        int r = row0 + ty * 8 + i;
#pragma unroll
        for (int j = 0; j < 8; j++) {
            int c = col0 + tx * 8 + j;
            if (c < Nc) {
                float v = acc[i][j];
                if (bias) v += bias[c];
                if (relu) v = fmaxf(v, 0.f);
                C[(size_t)r * ldc + c] = v;
            }
        }
    }
}

// ===================================================================
// Attention: only q-row t=4; causal 0/1 additive mask is constant there.
// ===================================================================
__global__ __launch_bounds__(256)
void attn_kernel(const float* __restrict__ qkv, float* __restrict__ ctx4) {
    int b = blockIdx.x;
    __shared__ float ks[kT][256], vs[kT][256], q4[256];
    __shared__ float sc[4][kT];
    __shared__ float attn[4][kT];
    int tid = threadIdx.x;
#pragma unroll
    for (int t = 0; t < kT; t++) {
        size_t base = ((size_t)(b * kT + t)) * (3 * kFD);
        ks[t][tid] = qkv[base + kFD + tid];
        vs[t][tid] = qkv[base + 2 * kFD + tid];
    }
    q4[tid] = qkv[((size_t)(b * kT + 4)) * (3 * kFD) + tid];
    __syncthreads();
    int warp = tid >> 5, lane = tid & 31;
    for (int p = warp; p < 4 * kT; p += 8) {
        int h = p / kT, kt = p % kT;
        float s = 0.f;
        for (int d = lane; d < 64; d += 32) s += q4[h * 64 + d] * ks[kt][h * 64 + d];
#pragma unroll
        for (int m = 16; m; m >>= 1) s += __shfl_xor_sync(0xffffffffu, s, m);
        if (lane == 0) sc[h][kt] = s * 0.125f;
    }
    __syncthreads();
    if (tid < 4) {
        float mx = -1e30f;
#pragma unroll
        for (int kt = 0; kt < kT; kt++) mx = fmaxf(mx, sc[tid][kt]);
        float e[kT], sum = 0.f;
#pragma unroll
        for (int kt = 0; kt < kT; kt++) { e[kt] = __expf(sc[tid][kt] - mx); sum += e[kt]; }
#pragma unroll
        for (int kt = 0; kt < kT; kt++) attn[tid][kt] = e[kt] / sum;
    }
    __syncthreads();
    int h = tid >> 6;
    float acc = 0.f;
#pragma unroll
    for (int kt = 0; kt < kT; kt++) acc += attn[h][kt] * vs[kt][tid];
    ctx4[(size_t)b * kFD + tid] = acc;
}

__global__ __launch_bounds__(32)
void belief_softmax(const float* __restrict__ logits, float* __restrict__ out) {
    int b = blockIdx.x;
    int lane = threadIdx.x;
    float v0 = logits[(size_t)b * 64 + lane];
    float v1 = logits[(size_t)b * 64 + 32 + lane];
    float mx = fmaxf(v0, v1);
#pragma unroll
    for (int m = 16; m; m >>= 1) mx = fmaxf(mx, __shfl_xor_sync(0xffffffffu, mx, m));
    float e0 = __expf(v0 - mx), e1 = __expf(v1 - mx);
    float s = e0 + e1;
#pragma unroll
    for (int m = 16; m; m >>= 1) s += __shfl_xor_sync(0xffffffffu, s, m);
    out[(size_t)b * 64 + lane] = e0 / s;
    out[(size_t)b * 64 + 32 + lane] = e1 / s;
}

// ===================================================================
extern "C" void kernel_launch(void* const* d_in, const int* in_sizes, int n_in,
                              void* d_out, int out_size) {
    const float* signals = (const float*)d_in[0];
    const float* nact    = (const float*)d_in[1];
    const float* w0      = (const float*)d_in[2];
    const float* asrc0   = (const float*)d_in[3];
    const float* adst0   = (const float*)d_in[4];
    const float* bias0   = (const float*)d_in[5];
    const float* w1      = (const float*)d_in[6];
    const float* asrc1   = (const float*)d_in[7];
    const float* adst1   = (const float*)d_in[8];
    const float* bias1   = (const float*)d_in[9];
    const float* inw     = (const float*)d_in[10];
    const float* inb     = (const float*)d_in[11];
    const float* outw    = (const float*)d_in[12];
    const float* outb    = (const float*)d_in[13];
    const float* wmean   = (const float*)d_in[14];
    const float* bmean   = (const float*)d_in[15];
    const float* wlogv   = (const float*)d_in[16];
    const float* blogv   = (const float*)d_in[17];
    const float* wbel    = (const float*)d_in[18];
    const float* bbel    = (const float*)d_in[19];
    float* out = (float*)d_out;

    float *y, *seq, *qkv, *ctx4, *feat, *blg, *v1;
    cudaGetSymbolAddress((void**)&y,    g_y);
    cudaGetSymbolAddress((void**)&seq,  g_seq);
    cudaGetSymbolAddress((void**)&qkv,  g_qkv);
    cudaGetSymbolAddress((void**)&ctx4, g_ctx4);
    cudaGetSymbolAddress((void**)&feat, g_feat);
    cudaGetSymbolAddress((void**)&blg,  g_blog);
    cudaGetSymbolAddress((void**)&v1,   g_v1);

    // 1. vsrc1/vdst1 precompute
    make_v1<<<8, 256>>>(w1, asrc1, adst1, v1);
    // 2. fused GNN (both GAT layers, aggregated pre-projection output y)
    fused_gnn<<<kB, 256>>>(signals, nact, w0, asrc0, adst0, bias0, v1, y);
    // 3. per-head layer-1 projection: seq[.., h*64:+64] = relu(y_h @ w1_h^T + b1_h)
    for (int h = 0; h < 4; h++) {
        sgemm_bias<<<dim3(kB * kT / 128, 1), 256>>>(
            y + h * kFD, w1 + (size_t)h * 64 * kFD, bias1 + h * 64, seq + h * 64,
            kB * kT, 64, kFD, 4 * kFD, kFD, 1);
    }
    // 4. qkv projection
    sgemm_bias<<<dim3(kB * kT / 128, 6), 256>>>(seq, inw, inb, qkv,
                                                kB * kT, 3 * kFD, kFD, kFD, 3 * kFD, 0);
    // 5. attention (q row t=4 only)
    attn_kernel<<<kB, 256>>>(qkv, ctx4);
    // 6. out_proj
    sgemm_bias<<<dim3(kB / 128, 2), 256>>>(ctx4, outw, outb, feat,
                                           kB, kFD, kFD, kFD, kFD, 0);
    // 7-9. heads
    sgemm_bias<<<dim3(kB / 128, 1), 256>>>(feat, wmean, bmean, out,
                                           kB, kLAT, kFD, kFD, kLAT, 0);
    sgemm_bias<<<dim3(kB / 128, 1), 256>>>(feat, wlogv, blogv, out + (size_t)kB * kLAT,
                                           kB, kLAT, kFD, kFD, kLAT, 0);
    sgemm_bias<<<dim3(kB / 128, 1), 256>>>(feat, wbel, bbel, blg,
                                           kB, kS, kFD, kFD, kS, 0);
    // 10. belief softmax
    belief_softmax<<<kB, 32>>>(blg, out + (size_t)2 * kB * kLAT);
}

// round 5
// speedup vs baseline: 1.5587x; 1.5587x over previous
#include <cuda_runtime.h>
#include <math.h>

static constexpr int kT = 5, kB = 512, kNA = 16, kS = 64, kA = 16;
static constexpr int kHID = 64, kH = 4, kFD = 256, kLAT = 128;
static constexpr int kN = kB * kNA;
static constexpr int kFIN = 80;

// -------- scratch (static device globals; no runtime allocation) --------
__device__ float g_y   [(size_t)kB * kT * 4 * kFD];   // aggregated layer-1 inputs
__device__ float g_seq [(size_t)kB * kT * kFD];
__device__ float g_kv  [(size_t)kB * kT * 2 * kFD];   // k|v only
__device__ float g_ctx4[(size_t)kB * kFD];
__device__ float g_feat[(size_t)kB * kFD];
__device__ float g_blog[(size_t)kB * kS];
__device__ float g_v1  [2 * 4 * kFD];                 // vsrc1 | vdst1
__device__ float g_w1t [kFD * kFD];                   // w1 transposed: w1t[k][d] = w1[d][k]
__device__ float g_wqt [kFD * kFD];                   // inw rows 0..255 transposed

// ===================================================================
// Prep: v1 precompute + transpose w1 -> w1t + transpose Wq -> wqt
// grid = 136 blocks x 256 threads. Each block does one 32x32 tile:
// 256 threads x 4 elements (i = 0..3)  [R4 bug: i ran to 8 -> OOB]
// ===================================================================
__global__ __launch_bounds__(256)
void prep_kernel(const float* __restrict__ w1, const float* __restrict__ asrc1,
                 const float* __restrict__ adst1, const float* __restrict__ inw,
                 float* __restrict__ v1, float* __restrict__ w1t,
                 float* __restrict__ wqt) {
    __shared__ float tile[32][33];
    int bid = blockIdx.x, tid = threadIdx.x;
    if (bid < 8) {
        int idx = bid * 256 + tid;
        int which = idx >> 10;
        int h = (idx >> 8) & 3;
        int k = idx & 255;
        const float* a = which ? adst1 : asrc1;
        float acc = 0.f;
#pragma unroll
        for (int c = 0; c < 64; c++)
            acc += a[h * 64 + c] * w1[(size_t)(h * 64 + c) * kFD + k];
        v1[which * 1024 + h * 256 + k] = acc;
        return;
    }
    // transpose tiles: bid 8..71 -> w1, 72..135 -> inw(q rows)
    int which = (bid - 8) >> 6;
    int t = (bid - 8) & 63;
    int ti = t & 7, tj = t >> 3;
    const float* src = which ? inw : w1;
    float* dst = which ? wqt : w1t;
    int c = tid & 31;
#pragma unroll
    for (int i = 0; i < 4; i++) {
        int r = (tid >> 5) + i * 8;                    // r in [0,31]
        tile[r][c] = src[(size_t)(tj * 32 + r) * kFD + ti * 32 + c];
    }
    __syncthreads();
#pragma unroll
    for (int i = 0; i < 4; i++) {
        int r = (tid >> 5) + i * 8;
        dst[(size_t)(ti * 32 + r) * kFD + tj * 32 + c] = tile[c][r];
    }
}

// ===================================================================
// Fused GNN + layer-1 projection. One block per group g (=batch).
// Phase 1 (per t): features -> lin0 -> GAT0 softmax/agg -> relu ->
//                  GAT1 scores via v1 -> softmax (dst 0) -> y (gmem)
// Phase 2: seq[g,t][d] = relu( y[t][h(d)] . w1t[:,d] + b1[d] )
// ===================================================================
#define XS(j,c)       sm[(j)*256+(c)]
#define A0S(c)        sm[4096+(c)]
#define A0D(c)        sm[4352+(c)]
#define VS1(h,c)      sm[4608+(h)*256+(c)]
#define VD1(h,c)      sm[5632+(h)*256+(c)]
#define ACTS(j,k)     sm[6656+(j)*16+(k)]
#define SIG(c)        sm[6912+(c)]
#define ES0(j,h)      sm[6976+(j)*4+(h)]
#define ED0(j,h)      sm[7040+(j)*4+(h)]
#define ALPHA0(n,j,h) sm[7104+((n)*16+(j))*4+(h)]
#define ES1(j,h)      sm[8128+(j)*4+(h)]
#define ED1(h)        sm[8192+(h)]
#define ALPHA1(j,h)   sm[8200+(j)*4+(h)]
#define WS(k,d)       sm[(k)*256+(d)]     // phase 2 alias (0..8191)

__global__ __launch_bounds__(256)
void gnn_proj(const float* __restrict__ signals, const float* __restrict__ nact,
              const float* __restrict__ w0,
              const float* __restrict__ asrc0, const float* __restrict__ adst0,
              const float* __restrict__ bias0, const float* __restrict__ v1,
              const float* __restrict__ w1t, const float* __restrict__ bias1,
              float* __restrict__ y, float* __restrict__ seq) {
    __shared__ float sm[8264];
    int g = blockIdx.x;
    int tid = threadIdx.x;

    float Wa[16];
#pragma unroll
    for (int k = 0; k < 16; k++) Wa[k] = w0[(size_t)tid * kFIN + 64 + k];
    A0S(tid) = asrc0[tid];
    A0D(tid) = adst0[tid];
#pragma unroll
    for (int h = 0; h < 4; h++) {
        VS1(h, tid) = v1[h * 256 + tid];
        VD1(h, tid) = v1[1024 + h * 256 + tid];
    }
    float b0 = bias0[tid];

    for (int t = 0; t < kT; t++) {
        __syncthreads();
        {
            ACTS(tid >> 4, tid & 15) = nact[((size_t)t * kB + g) * (kNA * kA) + tid];
            if (tid < 64) SIG(tid) = signals[((size_t)t * kB + g) * kS + tid];
        }
        __syncthreads();
        float xl0r[16];
#pragma unroll
        for (int j = 0; j < 16; j++) {
            float acc = 0.f;
#pragma unroll
            for (int k = 0; k < 16; k++) acc += ACTS(j, k) * Wa[k];
            xl0r[j] = acc;
        }
        {
            float acc = 0.f;
#pragma unroll
            for (int c = 0; c < 64; c++) acc += SIG(c) * w0[(size_t)tid * kFIN + c];
            xl0r[0] += acc;
        }
#pragma unroll
        for (int j = 0; j < 16; j++) XS(j, tid) = xl0r[j];
        __syncthreads();
        {   // es0/ed0: 128 dots of 64; 2 threads per dot
            int d = tid >> 1, half = tid & 1;
            int which = d >> 6;
            int q = d & 63, j = q >> 2, h = q & 3;
            float acc = 0.f;
#pragma unroll
            for (int c = half * 32; c < half * 32 + 32; c++)
                acc += XS(j, h * 64 + c) * (which ? A0D(h * 64 + c) : A0S(h * 64 + c));
            acc += __shfl_xor_sync(0xffffffffu, acc, 1);
            if (half == 0) { if (which) ED0(j, h) = acc; else ES0(j, h) = acc; }
        }
        __syncthreads();
        {   // softmax0 per (dst n, head h)
            int n = tid >> 4, j = tid & 15;
#pragma unroll
            for (int h = 0; h < 4; h++) {
                float e = ES0(j, h) + ED0(n, h);
                e = e > 0.f ? e : 0.2f * e;
                float mx = e;
#pragma unroll
                for (int m = 8; m; m >>= 1) mx = fmaxf(mx, __shfl_xor_sync(0xffffffffu, mx, m));
                float ex = __expf(e - mx);
                float s = ex;
#pragma unroll
                for (int m = 8; m; m >>= 1) s += __shfl_xor_sync(0xffffffffu, s, m);
                ALPHA0(n, j, h) = ex / s;
            }
        }
        __syncthreads();
        float x1r[16];
        {
            int h = tid >> 6;
#pragma unroll
            for (int n = 0; n < 16; n++) {
                float acc = 0.f;
#pragma unroll
                for (int j = 0; j < 16; j++) acc += ALPHA0(n, j, h) * xl0r[j];
                x1r[n] = fmaxf(acc + b0, 0.f);
            }
        }
        __syncthreads();
#pragma unroll
        for (int n = 0; n < 16; n++) XS(n, tid) = x1r[n];
        __syncthreads();
        {   // es1[j][h] = x1[j].vsrc1[h]; 4 threads/dot
            int p = tid >> 2, q = tid & 3;
            int j = p >> 2, h = p & 3;
            float acc = 0.f;
#pragma unroll
            for (int c = q * 64; c < q * 64 + 64; c++) acc += XS(j, c) * VS1(h, c);
            acc += __shfl_xor_sync(0xffffffffu, acc, 1);
            acc += __shfl_xor_sync(0xffffffffu, acc, 2);
            if (q == 0) ES1(j, h) = acc;
        }
        if (tid < 32) {   // ed1[h] = x1[0].vdst1[h]; full warp 0
            int h = tid >> 3, q = tid & 7;
            float acc = 0.f;
#pragma unroll
            for (int c = q * 32; c < q * 32 + 32; c++) acc += XS(0, c) * VD1(h, c);
            acc += __shfl_xor_sync(0xffffffffu, acc, 1);
            acc += __shfl_xor_sync(0xffffffffu, acc, 2);
            acc += __shfl_xor_sync(0xffffffffu, acc, 4);
            if (q == 0) ED1(h) = acc;
        }
        __syncthreads();
        if (tid < 64) {   // softmax1 over j per h (2 full warps)
            int h = tid >> 4, j = tid & 15;
            float e = ES1(j, h) + ED1(h);
            e = e > 0.f ? e : 0.2f * e;
            float mx = e;
#pragma unroll
            for (int m = 8; m; m >>= 1) mx = fmaxf(mx, __shfl_xor_sync(0xffffffffu, mx, m));
            float ex = __expf(e - mx);
            float s = ex;
#pragma unroll
            for (int m = 8; m; m >>= 1) s += __shfl_xor_sync(0xffffffffu, s, m);
            ALPHA1(j, h) = ex / s;
        }
        __syncthreads();
#pragma unroll
        for (int h = 0; h < 4; h++) {
            float acc = 0.f;
#pragma unroll
            for (int j = 0; j < 16; j++) acc += ALPHA1(j, h) * x1r[j];
            y[(((size_t)g * kT + t) * 4 + h) * kFD + tid] = acc;
        }
    }

    // ---------- Phase 2: layer-1 projection (y -> seq), w1t staged in smem ----------
    int h = tid >> 6;
    float b1v = bias1[tid];
    float accp[kT] = {0.f, 0.f, 0.f, 0.f, 0.f};
    const float* yb = y + (size_t)g * kT * 4 * kFD + h * kFD;   // + t*4*256 + k
    for (int k0 = 0; k0 < 256; k0 += 32) {
        __syncthreads();   // protect alias region + previous chunk use
#pragma unroll
        for (int i = 0; i < 8; i++) {
            int f = tid + i * 256;          // float4 index: row = f>>6, col4 = f&63
            int row = f >> 6, col4 = f & 63;
            float4 v = *(const float4*)&w1t[(size_t)(k0 + row) * kFD + col4 * 4];
            *(float4*)&WS(row, col4 * 4) = v;
        }
        __syncthreads();
#pragma unroll
        for (int k = 0; k < 32; k++) {
            float w = WS(k, tid);
#pragma unroll
            for (int t = 0; t < kT; t++)
                accp[t] += yb[t * 4 * kFD + k0 + k] * w;
        }
    }
#pragma unroll
    for (int t = 0; t < kT; t++)
        seq[((size_t)g * kT + t) * kFD + tid] = fmaxf(accp[t] + b1v, 0.f);
}

// ===================================================================
// SGEMM 128x128x16 (for the kv projection): C = A @ W^T + bias
// ===================================================================
__global__ __launch_bounds__(256)
void sgemm_bias(const float* __restrict__ Ain, const float* __restrict__ W,
                const float* __restrict__ bias, float* __restrict__ C,
                int M, int Nc, int K, int lda, int ldc) {
    __shared__ float As[16][128];
    __shared__ float Bs[16][128];
    int tid = threadIdx.x;
    int row0 = blockIdx.x * 128;
    int col0 = blockIdx.y * 128;
    int tx = tid & 15, ty = tid >> 4;
    float acc[8][8];
#pragma unroll
    for (int i = 0; i < 8; i++)
#pragma unroll
        for (int j = 0; j < 8; j++) acc[i][j] = 0.f;

    for (int k0 = 0; k0 < K; k0 += 16) {
#pragma unroll
        for (int i = 0; i < 2; i++) {
            int f = tid + i * 256;
            int r = f >> 2;
            int kq = (f & 3) * 4;
            float4 v = *(const float4*)&Ain[(size_t)(row0 + r) * lda + k0 + kq];
            As[kq + 0][r] = v.x; As[kq + 1][r] = v.y;
            As[kq + 2][r] = v.z; As[kq + 3][r] = v.w;
        }
#pragma unroll
        for (int i = 0; i < 2; i++) {
            int f = tid + i * 256;
            int r = f >> 2;
            int kq = (f & 3) * 4;
            float4 v = *(const float4*)&W[(size_t)(col0 + r) * K + k0 + kq];
            Bs[kq + 0][r] = v.x; Bs[kq + 1][r] = v.y;
            Bs[kq + 2][r] = v.z; Bs[kq + 3][r] = v.w;
        }
        __syncthreads();
#pragma unroll
        for (int k = 0; k < 16; k++) {
            float4 a0 = *(const float4*)&As[k][ty * 8];
            float4 a1 = *(const float4*)&As[k][ty * 8 + 4];
            float4 b0 = *(const float4*)&Bs[k][tx * 8];
            float4 b1 = *(const float4*)&Bs[k][tx * 8 + 4];
            float av[8] = {a0.x, a0.y, a0.z, a0.w, a1.x, a1.y, a1.z, a1.w};
            float bv[8] = {b0.x, b0.y, b0.z, b0.w, b1.x, b1.y, b1.z, b1.w};
#pragma unroll
            for (int i = 0; i < 8; i++)
#pragma unroll
                for (int j = 0; j < 8; j++) acc[i][j] += av[i] * bv[j];
        }
        __syncthreads();
    }
#pragma unroll
    for (int i = 0; i < 8; i++) {
        int r = row0 + ty * 8 + i;
#pragma unroll
        for (int j = 0; j < 8; j++) {
            int c = col0 + tx * 8 + j;
            C[(size_t)r * ldc + c] = acc[i][j] + bias[c];
        }
    }
}

// ===================================================================
// Attention with fused q-projection. One block per batch b.
// ===================================================================
__global__ __launch_bounds__(256)
void attn_kernel(const float* __restrict__ kv, const float* __restrict__ seq,
                 const float* __restrict__ wqt, const float* __restrict__ inb,
                 float* __restrict__ ctx4) {
    int b = blockIdx.x;
    __shared__ float ks[kT][256], vs[kT][256], q4[256], s4[256];
    __shared__ float sc[4][kT], attnw[4][kT];
    int tid = threadIdx.x;
#pragma unroll
    for (int t = 0; t < kT; t++) {
        size_t base = ((size_t)(b * kT + t)) * (2 * kFD);
        ks[t][tid] = kv[base + tid];
        vs[t][tid] = kv[base + kFD + tid];
    }
    s4[tid] = seq[((size_t)(b * kT + 4)) * kFD + tid];
    __syncthreads();
    {   // q4 = s4 @ Wq^T + bq  (wqt transposed, coalesced)
        float acc = 0.f;
#pragma unroll 8
        for (int k = 0; k < 256; k++) acc += s4[k] * wqt[(size_t)k * kFD + tid];
        q4[tid] = acc + inb[tid];
    }
    __syncthreads();
    int warp = tid >> 5, lane = tid & 31;
    for (int p = warp; p < 4 * kT; p += 8) {
        int h = p / kT, kt = p % kT;
        float s = 0.f;
        for (int d = lane; d < 64; d += 32) s += q4[h * 64 + d] * ks[kt][h * 64 + d];
#pragma unroll
        for (int m = 16; m; m >>= 1) s += __shfl_xor_sync(0xffffffffu, s, m);
        if (lane == 0) sc[h][kt] = s * 0.125f;
    }
    __syncthreads();
    if (tid < 32) {   // softmax over kt for 4 heads (full warp)
        int h = tid & 3;
        float mx = -1e30f;
#pragma unroll
        for (int kt = 0; kt < kT; kt++) mx = fmaxf(mx, sc[h][kt]);
        float e[kT], sum = 0.f;
#pragma unroll
        for (int kt = 0; kt < kT; kt++) { e[kt] = __expf(sc[h][kt] - mx); sum += e[kt]; }
        if (tid < 4)
#pragma unroll
            for (int kt = 0; kt < kT; kt++) attnw[h][kt] = e[kt] / sum;
    }
    __syncthreads();
    int h = tid >> 6;
    float acc = 0.f;
#pragma unroll
    for (int kt = 0; kt < kT; kt++) acc += attnw[h][kt] * vs[kt][tid];
    ctx4[(size_t)b * kFD + tid] = acc;
}

// ===================================================================
// 32x128 tile GEMM body for small-M tails
// ===================================================================
__device__ __forceinline__
void tile32_body(const float* __restrict__ A, int lda, const float* __restrict__ W,
                 const float* __restrict__ bias, float* __restrict__ C, int ldc,
                 int K, int Nc, int row0, int col0, float* As, float* Bs) {
    int tid = threadIdx.x;
    int tx = tid & 31, ty = tid >> 5;
    float acc[4][4];
#pragma unroll
    for (int i = 0; i < 4; i++)
#pragma unroll
        for (int j = 0; j < 4; j++) acc[i][j] = 0.f;
    for (int k0 = 0; k0 < K; k0 += 16) {
        if (tid < 128) {
            int r = tid >> 2, kq = (tid & 3) * 4;
            float4 v = *(const float4*)&A[(size_t)(row0 + r) * lda + k0 + kq];
            As[(kq + 0) * 32 + r] = v.x; As[(kq + 1) * 32 + r] = v.y;
            As[(kq + 2) * 32 + r] = v.z; As[(kq + 3) * 32 + r] = v.w;
        }
#pragma unroll
        for (int i = 0; i < 2; i++) {
            int f = tid + i * 256;
            int r = f >> 2, kq = (f & 3) * 4;
            int col = col0 + r;
            float4 v = make_float4(0.f, 0.f, 0.f, 0.f);
            if (col < Nc) v = *(const float4*)&W[(size_t)col * K + k0 + kq];
            Bs[(kq + 0) * 128 + r] = v.x; Bs[(kq + 1) * 128 + r] = v.y;
            Bs[(kq + 2) * 128 + r] = v.z; Bs[(kq + 3) * 128 + r] = v.w;
        }
        __syncthreads();
#pragma unroll
        for (int k = 0; k < 16; k++) {
            float4 a4 = *(const float4*)&As[k * 32 + ty * 4];
            float4 b4 = *(const float4*)&Bs[k * 128 + tx * 4];
            float av[4] = {a4.x, a4.y, a4.z, a4.w};
            float bv[4] = {b4.x, b4.y, b4.z, b4.w};
#pragma unroll
            for (int i = 0; i < 4; i++)
#pragma unroll
                for (int j = 0; j < 4; j++) acc[i][j] += av[i] * bv[j];
        }
        __syncthreads();
    }
#pragma unroll
    for (int i = 0; i < 4; i++) {
        int r = row0 + ty * 4 + i;
#pragma unroll
        for (int j = 0; j < 4; j++) {
            int c = col0 + tx * 4 + j;
            if (c < Nc) C[(size_t)r * ldc + c] = acc[i][j] + bias[c];
        }
    }
}

__global__ __launch_bounds__(256)
void tile32_gemm(const float* __restrict__ A, const float* __restrict__ W,
                 const float* __restrict__ bias, float* __restrict__ C,
                 int lda, int ldc, int K, int Nc) {
    __shared__ float As[16 * 32], Bs[16 * 128];
    tile32_body(A, lda, W, bias, C, ldc, K, Nc, blockIdx.x * 32, blockIdx.y * 128, As, Bs);
}

// heads: blockIdx.y selects {mean, logvar, belief-logits}
__global__ __launch_bounds__(256)
void heads_gemm(const float* __restrict__ feat,
                const float* __restrict__ wmean, const float* __restrict__ bmean,
                const float* __restrict__ wlogv, const float* __restrict__ blogv,
                const float* __restrict__ wbel,  const float* __restrict__ bbel,
                float* __restrict__ out, float* __restrict__ blog) {
    __shared__ float As[16 * 32], Bs[16 * 128];
    const float* W; const float* bias; float* C; int Nc;
    if (blockIdx.y == 0)      { W = wmean; bias = bmean; C = out; Nc = kLAT; }
    else if (blockIdx.y == 1) { W = wlogv; bias = blogv; C = out + (size_t)kB * kLAT; Nc = kLAT; }
    else                      { W = wbel;  bias = bbel;  C = blog; Nc = kS; }
    tile32_body(feat, kFD, W, bias, C, Nc, kFD, Nc, blockIdx.x * 32, 0, As, Bs);
}

__global__ __launch_bounds__(32)
void belief_softmax(const float* __restrict__ logits, float* __restrict__ out) {
    int b = blockIdx.x;
    int lane = threadIdx.x;
    float v0 = logits[(size_t)b * 64 + lane];
    float v1 = logits[(size_t)b * 64 + 32 + lane];
    float mx = fmaxf(v0, v1);
#pragma unroll
    for (int m = 16; m; m >>= 1) mx = fmaxf(mx, __shfl_xor_sync(0xffffffffu, mx, m));
    float e0 = __expf(v0 - mx), e1 = __expf(v1 - mx);
    float s = e0 + e1;
#pragma unroll
    for (int m = 16; m; m >>= 1) s += __shfl_xor_sync(0xffffffffu, s, m);
    out[(size_t)b * 64 + lane] = e0 / s;
    out[(size_t)b * 64 + 32 + lane] = e1 / s;
}

// ===================================================================
extern "C" void kernel_launch(void* const* d_in, const int* in_sizes, int n_in,
                              void* d_out, int out_size) {
    const float* signals = (const float*)d_in[0];
    const float* nact    = (const float*)d_in[1];
    const float* w0      = (const float*)d_in[2];
    const float* asrc0   = (const float*)d_in[3];
    const float* adst0   = (const float*)d_in[4];
    const float* bias0   = (const float*)d_in[5];
    const float* w1      = (const float*)d_in[6];
    const float* asrc1   = (const float*)d_in[7];
    const float* adst1   = (const float*)d_in[8];
    const float* bias1   = (const float*)d_in[9];
    const float* inw     = (const float*)d_in[10];
    const float* inb     = (const float*)d_in[11];
    const float* outw    = (const float*)d_in[12];
    const float* outb    = (const float*)d_in[13];
    const float* wmean   = (const float*)d_in[14];
    const float* bmean   = (const float*)d_in[15];
    const float* wlogv   = (const float*)d_in[16];
    const float* blogv   = (const float*)d_in[17];
    const float* wbel    = (const float*)d_in[18];
    const float* bbel    = (const float*)d_in[19];
    float* out = (float*)d_out;

    float *y, *seq, *kv, *ctx4, *feat, *blg, *v1, *w1t, *wqt;
    cudaGetSymbolAddress((void**)&y,    g_y);
    cudaGetSymbolAddress((void**)&seq,  g_seq);
    cudaGetSymbolAddress((void**)&kv,   g_kv);
    cudaGetSymbolAddress((void**)&ctx4, g_ctx4);
    cudaGetSymbolAddress((void**)&feat, g_feat);
    cudaGetSymbolAddress((void**)&blg,  g_blog);
    cudaGetSymbolAddress((void**)&v1,   g_v1);
    cudaGetSymbolAddress((void**)&w1t,  g_w1t);
    cudaGetSymbolAddress((void**)&wqt,  g_wqt);

    // 1. prep: v1 + transposes
    prep_kernel<<<136, 256>>>(w1, asrc1, adst1, inw, v1, w1t, wqt);
    // 2. fused GNN + layer-1 projection -> seq
    gnn_proj<<<kB, 256>>>(signals, nact, w0, asrc0, adst0, bias0, v1, w1t, bias1, y, seq);
    // 3. kv projection: (2560 x 512) = seq @ inw[256:768]^T + inb[256:768]
    sgemm_bias<<<dim3(kB * kT / 128, 4), 256>>>(seq, inw + 256 * kFD, inb + 256, kv,
                                                kB * kT, 2 * kFD, kFD, kFD, 2 * kFD);
    // 4. attention (fused q projection; q row t=4 only)
    attn_kernel<<<kB, 256>>>(kv, seq, wqt, inb, ctx4);
    // 5. out_proj: feat = ctx4 @ outw^T + outb
    tile32_gemm<<<dim3(kB / 32, 2), 256>>>(ctx4, outw, outb, feat, kFD, kFD, kFD, kFD);
    // 6. heads (mean | logvar | belief logits) in one launch
    heads_gemm<<<dim3(kB / 32, 3), 256>>>(feat, wmean, bmean, wlogv, blogv, wbel, bbel,
                                          out, blg);
    // 7. belief softmax
    belief_softmax<<<kB, 32>>>(blg, out + (size_t)2 * kB * kLAT);
}

// round 6
// speedup vs baseline: 2.0234x; 1.2981x over previous
#include <cuda_runtime.h>
#include <math.h>

static constexpr int kT = 5, kB = 512, kNA = 16, kS = 64, kA = 16;
static constexpr int kHID = 64, kH = 4, kFD = 256, kLAT = 128;
static constexpr int kN = kB * kNA;
static constexpr int kFIN = 80;

// -------- scratch (static device globals; no runtime allocation) --------
__device__ float g_y   [(size_t)kB * kT * 4 * kFD];   // aggregated layer-1 inputs
__device__ float g_seq [(size_t)kB * kT * kFD];
__device__ float g_kv  [(size_t)kB * kT * 2 * kFD];   // k|v
__device__ float g_q4  [(size_t)kB * kFD];            // q row t=4 per batch
__device__ float g_ctx4[(size_t)kB * kFD];
__device__ float g_feat[(size_t)kB * kFD];
__device__ float g_blog[(size_t)kB * kS];
__device__ float g_v1  [2 * 4 * kFD];                 // vsrc1 | vdst1
__device__ float g_w1t [kFD * kFD];                   // w1^T
__device__ float g_w0t [kFIN * kFD];                  // w0^T (80 x 256)

// ===================================================================
// Prep: v1 + transpose w1 -> w1t + transpose w0 -> w0t. grid = 152.
// ===================================================================
__global__ __launch_bounds__(256)
void prep_kernel(const float* __restrict__ w1, const float* __restrict__ asrc1,
                 const float* __restrict__ adst1, const float* __restrict__ w0,
                 float* __restrict__ v1, float* __restrict__ w1t,
                 float* __restrict__ w0t) {
    __shared__ float tile[32][33];
    int bid = blockIdx.x, tid = threadIdx.x;
    if (bid < 8) {
        int idx = bid * 256 + tid;
        int which = idx >> 10;
        int h = (idx >> 8) & 3;
        int k = idx & 255;
        const float* a = which ? adst1 : asrc1;
        float acc = 0.f;
#pragma unroll
        for (int c = 0; c < 64; c++)
            acc += a[h * 64 + c] * w1[(size_t)(h * 64 + c) * kFD + k];
        v1[which * 1024 + h * 256 + k] = acc;
        return;
    }
    if (bid < 72) {   // w1 transpose: 64 tiles of 32x32, 4 elems/thread
        int t = bid - 8;
        int ti = t & 7, tj = t >> 3;
        int c = tid & 31;
#pragma unroll
        for (int i = 0; i < 4; i++) {
            int r = (tid >> 5) + i * 8;
            tile[r][c] = w1[(size_t)(tj * 32 + r) * kFD + ti * 32 + c];
        }
        __syncthreads();
#pragma unroll
        for (int i = 0; i < 4; i++) {
            int r = (tid >> 5) + i * 8;
            w1t[(size_t)(ti * 32 + r) * kFD + tj * 32 + c] = tile[c][r];
        }
        return;
    }
    // w0t: one block per input column c (80 blocks)
    int c = bid - 72;
    w0t[(size_t)c * kFD + tid] = w0[(size_t)tid * kFIN + c];
}

// ===================================================================
// Fused GNN + layer-1 projection. One block per group g (=batch).
// ===================================================================
#define XS(j,c)       sm[(j)*256+(c)]
#define A0S(c)        sm[4096+(c)]
#define A0D(c)        sm[4352+(c)]
#define VS1(h,c)      sm[4608+(h)*256+(c)]
#define VD1(h,c)      sm[5632+(h)*256+(c)]
#define ACTS(j,k)     sm[6656+(j)*16+(k)]
#define SIG(c)        sm[6912+(c)]
#define ES0(j,h)      sm[6976+(j)*4+(h)]
#define ED0(j,h)      sm[7040+(j)*4+(h)]
#define ALPHA0(n,j,h) sm[7104+((n)*16+(j))*4+(h)]
#define ES1(j,h)      sm[8128+(j)*4+(h)]
#define ED1(h)        sm[8192+(h)]
#define ALPHA1(j,h)   sm[8200+(j)*4+(h)]
#define WS(k,d)       sm[(k)*256+(d)]     // phase 2 alias

__global__ __launch_bounds__(256)
void gnn_proj(const float* __restrict__ signals, const float* __restrict__ nact,
              const float* __restrict__ w0, const float* __restrict__ w0t,
              const float* __restrict__ asrc0, const float* __restrict__ adst0,
              const float* __restrict__ bias0, const float* __restrict__ v1,
              const float* __restrict__ w1t, const float* __restrict__ bias1,
              float* __restrict__ y, float* __restrict__ seq) {
    __shared__ float sm[8264];
    int g = blockIdx.x;
    int tid = threadIdx.x;

    float Wa[16];
#pragma unroll
    for (int k = 0; k < 16; k++) Wa[k] = w0[(size_t)tid * kFIN + 64 + k];
    A0S(tid) = asrc0[tid];
    A0D(tid) = adst0[tid];
#pragma unroll
    for (int h = 0; h < 4; h++) {
        VS1(h, tid) = v1[h * 256 + tid];
        VD1(h, tid) = v1[1024 + h * 256 + tid];
    }
    float b0 = bias0[tid];

    for (int t = 0; t < kT; t++) {
        __syncthreads();
        {
            ACTS(tid >> 4, tid & 15) = nact[((size_t)t * kB + g) * (kNA * kA) + tid];
            if (tid < 64) SIG(tid) = signals[((size_t)t * kB + g) * kS + tid];
        }
        __syncthreads();
        float xl0r[16];
#pragma unroll
        for (int j = 0; j < 16; j++) {
            float acc = 0.f;
#pragma unroll
            for (int k = 0; k < 16; k++) acc += ACTS(j, k) * Wa[k];
            xl0r[j] = acc;
        }
        {   // belief part (node 0 only) — coalesced via w0t
            float acc = 0.f;
#pragma unroll
            for (int c = 0; c < 64; c++) acc += SIG(c) * w0t[(size_t)c * kFD + tid];
            xl0r[0] += acc;
        }
#pragma unroll
        for (int j = 0; j < 16; j++) XS(j, tid) = xl0r[j];
        __syncthreads();
        {   // es0/ed0: 128 dots of 64; 2 threads per dot
            int d = tid >> 1, half = tid & 1;
            int which = d >> 6;
            int q = d & 63, j = q >> 2, h = q & 3;
            float acc = 0.f;
#pragma unroll
            for (int c = half * 32; c < half * 32 + 32; c++)
                acc += XS(j, h * 64 + c) * (which ? A0D(h * 64 + c) : A0S(h * 64 + c));
            acc += __shfl_xor_sync(0xffffffffu, acc, 1);
            if (half == 0) { if (which) ED0(j, h) = acc; else ES0(j, h) = acc; }
        }
        __syncthreads();
        {   // softmax0 per (dst n, head h)
            int n = tid >> 4, j = tid & 15;
#pragma unroll
            for (int h = 0; h < 4; h++) {
                float e = ES0(j, h) + ED0(n, h);
                e = e > 0.f ? e : 0.2f * e;
                float mx = e;
#pragma unroll
                for (int m = 8; m; m >>= 1) mx = fmaxf(mx, __shfl_xor_sync(0xffffffffu, mx, m));
                float ex = __expf(e - mx);
                float s = ex;
#pragma unroll
                for (int m = 8; m; m >>= 1) s += __shfl_xor_sync(0xffffffffu, s, m);
                ALPHA0(n, j, h) = ex / s;
            }
        }
        __syncthreads();
        float x1r[16];
        {
            int h = tid >> 6;
#pragma unroll
            for (int n = 0; n < 16; n++) {
                float acc = 0.f;
#pragma unroll
                for (int j = 0; j < 16; j++) acc += ALPHA0(n, j, h) * xl0r[j];
                x1r[n] = fmaxf(acc + b0, 0.f);
            }
        }
        __syncthreads();
#pragma unroll
        for (int n = 0; n < 16; n++) XS(n, tid) = x1r[n];
        __syncthreads();
        {   // es1[j][h] = x1[j].vsrc1[h]; 4 threads/dot
            int p = tid >> 2, q = tid & 3;
            int j = p >> 2, h = p & 3;
            float acc = 0.f;
#pragma unroll
            for (int c = q * 64; c < q * 64 + 64; c++) acc += XS(j, c) * VS1(h, c);
            acc += __shfl_xor_sync(0xffffffffu, acc, 1);
            acc += __shfl_xor_sync(0xffffffffu, acc, 2);
            if (q == 0) ES1(j, h) = acc;
        }
        if (tid < 32) {   // ed1[h] = x1[0].vdst1[h]; full warp 0
            int h = tid >> 3, q = tid & 7;
            float acc = 0.f;
#pragma unroll
            for (int c = q * 32; c < q * 32 + 32; c++) acc += XS(0, c) * VD1(h, c);
            acc += __shfl_xor_sync(0xffffffffu, acc, 1);
            acc += __shfl_xor_sync(0xffffffffu, acc, 2);
            acc += __shfl_xor_sync(0xffffffffu, acc, 4);
            if (q == 0) ED1(h) = acc;
        }
        __syncthreads();
        if (tid < 64) {   // softmax1 over j per h
            int h = tid >> 4, j = tid & 15;
            float e = ES1(j, h) + ED1(h);
            e = e > 0.f ? e : 0.2f * e;
            float mx = e;
#pragma unroll
            for (int m = 8; m; m >>= 1) mx = fmaxf(mx, __shfl_xor_sync(0xffffffffu, mx, m));
            float ex = __expf(e - mx);
            float s = ex;
#pragma unroll
            for (int m = 8; m; m >>= 1) s += __shfl_xor_sync(0xffffffffu, s, m);
            ALPHA1(j, h) = ex / s;
        }
        __syncthreads();
#pragma unroll
        for (int h = 0; h < 4; h++) {
            float acc = 0.f;
#pragma unroll
            for (int j = 0; j < 16; j++) acc += ALPHA1(j, h) * x1r[j];
            y[(((size_t)g * kT + t) * 4 + h) * kFD + tid] = acc;
        }
    }

    // ---------- Phase 2: layer-1 projection (y -> seq) ----------
    int h = tid >> 6;
    float b1v = bias1[tid];
    float accp[kT] = {0.f, 0.f, 0.f, 0.f, 0.f};
    const float* yb = y + (size_t)g * kT * 4 * kFD + h * kFD;
    for (int k0 = 0; k0 < 256; k0 += 32) {
        __syncthreads();
#pragma unroll
        for (int i = 0; i < 8; i++) {
            int f = tid + i * 256;
            int row = f >> 6, col4 = f & 63;
            float4 v = *(const float4*)&w1t[(size_t)(k0 + row) * kFD + col4 * 4];
            *(float4*)&WS(row, col4 * 4) = v;
        }
        __syncthreads();
#pragma unroll
        for (int k = 0; k < 32; k++) {
            float w = WS(k, tid);
#pragma unroll
            for (int t = 0; t < kT; t++)
                accp[t] += yb[t * 4 * kFD + k0 + k] * w;
        }
    }
#pragma unroll
    for (int t = 0; t < kT; t++)
        seq[((size_t)g * kT + t) * kFD + tid] = fmaxf(accp[t] + b1v, 0.f);
}

// ===================================================================
// Unified q + kv projection GEMM, double-buffered 128x128x16.
// by<4: kv = seq(2560x256) @ Wkv(512x256)^T    by==4: q4 = seq[t=4] @ Wq^T
// ===================================================================
__global__ __launch_bounds__(256)
void qkv_gemm(const float* __restrict__ seq, const float* __restrict__ inw,
              const float* __restrict__ inb, float* __restrict__ kv,
              float* __restrict__ q4) {
    __shared__ float As[2][16][128];
    __shared__ float Bs[2][16][128];
    int tid = threadIdx.x;
    const float *A, *W, *bias;
    float* C;
    int lda, ldc, row0, col0;
    if (blockIdx.y == 4) {
        int rt = blockIdx.x & 3, ct = blockIdx.x >> 2;
        if (ct >= 2) return;                       // uniform early-exit
        row0 = rt * 128; col0 = ct * 128;
        A = seq + 4 * kFD; lda = kT * kFD;          // every 5th row (t=4)
        W = inw; bias = inb;                        // q rows of in_proj
        C = q4; ldc = kFD;
    } else {
        row0 = blockIdx.x * 128; col0 = blockIdx.y * 128;
        A = seq; lda = kFD;
        W = inw + 256 * kFD; bias = inb + 256;      // k|v rows
        C = kv; ldc = 2 * kFD;
    }
    int tx = tid & 15, ty = tid >> 4;
    float acc[8][8];
#pragma unroll
    for (int i = 0; i < 8; i++)
#pragma unroll
        for (int j = 0; j < 8; j++) acc[i][j] = 0.f;

    // initial tile load
    {
#pragma unroll
        for (int i = 0; i < 2; i++) {
            int f = tid + i * 256;
            int r = f >> 2, kq = (f & 3) * 4;
            float4 v = *(const float4*)&A[(size_t)(row0 + r) * lda + kq];
            As[0][kq + 0][r] = v.x; As[0][kq + 1][r] = v.y;
            As[0][kq + 2][r] = v.z; As[0][kq + 3][r] = v.w;
            float4 w = *(const float4*)&W[(size_t)(col0 + r) * kFD + kq];
            Bs[0][kq + 0][r] = w.x; Bs[0][kq + 1][r] = w.y;
            Bs[0][kq + 2][r] = w.z; Bs[0][kq + 3][r] = w.w;
        }
    }
    __syncthreads();
    int buf = 0;
    for (int k0 = 0; k0 < 256; k0 += 16, buf ^= 1) {
        if (k0 + 16 < 256) {   // prefetch next tile into other buffer
            int kn = k0 + 16;
#pragma unroll
            for (int i = 0; i < 2; i++) {
                int f = tid + i * 256;
                int r = f >> 2, kq = (f & 3) * 4;
                float4 v = *(const float4*)&A[(size_t)(row0 + r) * lda + kn + kq];
                As[buf ^ 1][kq + 0][r] = v.x; As[buf ^ 1][kq + 1][r] = v.y;
                As[buf ^ 1][kq + 2][r] = v.z; As[buf ^ 1][kq + 3][r] = v.w;
                float4 w = *(const float4*)&W[(size_t)(col0 + r) * kFD + kn + kq];
                Bs[buf ^ 1][kq + 0][r] = w.x; Bs[buf ^ 1][kq + 1][r] = w.y;
                Bs[buf ^ 1][kq + 2][r] = w.z; Bs[buf ^ 1][kq + 3][r] = w.w;
            }
        }
#pragma unroll
        for (int k = 0; k < 16; k++) {
            float4 a0 = *(const float4*)&As[buf][k][ty * 8];
            float4 a1 = *(const float4*)&As[buf][k][ty * 8 + 4];
            float4 b0 = *(const float4*)&Bs[buf][k][tx * 8];
            float4 b1 = *(const float4*)&Bs[buf][k][tx * 8 + 4];
            float av[8] = {a0.x, a0.y, a0.z, a0.w, a1.x, a1.y, a1.z, a1.w};
            float bv[8] = {b0.x, b0.y, b0.z, b0.w, b1.x, b1.y, b1.z, b1.w};
#pragma unroll
            for (int i = 0; i < 8; i++)
#pragma unroll
                for (int j = 0; j < 8; j++) acc[i][j] += av[i] * bv[j];
        }
        __syncthreads();
    }
#pragma unroll
    for (int i = 0; i < 8; i++) {
        int r = row0 + ty * 8 + i;
#pragma unroll
        for (int j = 0; j < 8; j++) {
            int c = col0 + tx * 8 + j;
            C[(size_t)r * ldc + c] = acc[i][j] + bias[c];
        }
    }
}

// ===================================================================
// Attention (q prebatched). One block per batch b. Light.
// ===================================================================
__global__ __launch_bounds__(256)
void attn_kernel(const float* __restrict__ kv, const float* __restrict__ q4g,
                 float* __restrict__ ctx4) {
    int b = blockIdx.x;
    __shared__ float ks[kT][256], vs[kT][256], q4[256];
    __shared__ float sc[4][kT], attnw[4][kT];
    int tid = threadIdx.x;
#pragma unroll
    for (int t = 0; t < kT; t++) {
        size_t base = ((size_t)(b * kT + t)) * (2 * kFD);
        ks[t][tid] = kv[base + tid];
        vs[t][tid] = kv[base + kFD + tid];
    }
    q4[tid] = q4g[(size_t)b * kFD + tid];
    __syncthreads();
    int warp = tid >> 5, lane = tid & 31;
    for (int p = warp; p < 4 * kT; p += 8) {
        int h = p / kT, kt = p % kT;
        float s = 0.f;
        for (int d = lane; d < 64; d += 32) s += q4[h * 64 + d] * ks[kt][h * 64 + d];
#pragma unroll
        for (int m = 16; m; m >>= 1) s += __shfl_xor_sync(0xffffffffu, s, m);
        if (lane == 0) sc[h][kt] = s * 0.125f;
    }
    __syncthreads();
    if (tid < 32) {
        int h = tid & 3;
        float mx = -1e30f;
#pragma unroll
        for (int kt = 0; kt < kT; kt++) mx = fmaxf(mx, sc[h][kt]);
        float e[kT], sum = 0.f;
#pragma unroll
        for (int kt = 0; kt < kT; kt++) { e[kt] = __expf(sc[h][kt] - mx); sum += e[kt]; }
        if (tid < 4)
#pragma unroll
            for (int kt = 0; kt < kT; kt++) attnw[h][kt] = e[kt] / sum;
    }
    __syncthreads();
    int h = tid >> 6;
    float acc = 0.f;
#pragma unroll
    for (int kt = 0; kt < kT; kt++) acc += attnw[h][kt] * vs[kt][tid];
    ctx4[(size_t)b * kFD + tid] = acc;
}

// ===================================================================
// 32x128 tile GEMM body (small-M tails)
// ===================================================================
__device__ __forceinline__
void tile32_body(const float* __restrict__ A, int lda, const float* __restrict__ W,
                 const float* __restrict__ bias, float* __restrict__ C, int ldc,
                 int K, int Nc, int row0, int col0, float* As, float* Bs) {
    int tid = threadIdx.x;
    int tx = tid & 31, ty = tid >> 5;
    float acc[4][4];
#pragma unroll
    for (int i = 0; i < 4; i++)
#pragma unroll
        for (int j = 0; j < 4; j++) acc[i][j] = 0.f;
    for (int k0 = 0; k0 < K; k0 += 16) {
        if (tid < 128) {
            int r = tid >> 2, kq = (tid & 3) * 4;
            float4 v = *(const float4*)&A[(size_t)(row0 + r) * lda + k0 + kq];
            As[(kq + 0) * 32 + r] = v.x; As[(kq + 1) * 32 + r] = v.y;
            As[(kq + 2) * 32 + r] = v.z; As[(kq + 3) * 32 + r] = v.w;
        }
#pragma unroll
        for (int i = 0; i < 2; i++) {
            int f = tid + i * 256;
            int r = f >> 2, kq = (f & 3) * 4;
            int col = col0 + r;
            float4 v = make_float4(0.f, 0.f, 0.f, 0.f);
            if (col < Nc) v = *(const float4*)&W[(size_t)col * K + k0 + kq];
            Bs[(kq + 0) * 128 + r] = v.x; Bs[(kq + 1) * 128 + r] = v.y;
            Bs[(kq + 2) * 128 + r] = v.z; Bs[(kq + 3) * 128 + r] = v.w;
        }
        __syncthreads();
#pragma unroll
        for (int k = 0; k < 16; k++) {
            float4 a4 = *(const float4*)&As[k * 32 + ty * 4];
            float4 b4 = *(const float4*)&Bs[k * 128 + tx * 4];
            float av[4] = {a4.x, a4.y, a4.z, a4.w};
            float bv[4] = {b4.x, b4.y, b4.z, b4.w};
#pragma unroll
            for (int i = 0; i < 4; i++)
#pragma unroll
                for (int j = 0; j < 4; j++) acc[i][j] += av[i] * bv[j];
        }
        __syncthreads();
    }
#pragma unroll
    for (int i = 0; i < 4; i++) {
        int r = row0 + ty * 4 + i;
#pragma unroll
        for (int j = 0; j < 4; j++) {
            int c = col0 + tx * 4 + j;
            if (c < Nc) C[(size_t)r * ldc + c] = acc[i][j] + bias[c];
        }
    }
}

__global__ __launch_bounds__(256)
void tile32_gemm(const float* __restrict__ A, const float* __restrict__ W,
                 const float* __restrict__ bias, float* __restrict__ C,
                 int lda, int ldc, int K, int Nc) {
    __shared__ float As[16 * 32], Bs[16 * 128];
    tile32_body(A, lda, W, bias, C, ldc, K, Nc, blockIdx.x * 32, blockIdx.y * 128, As, Bs);
}

// heads: by selects {mean, logvar, belief}; belief fuses its softmax.
__global__ __launch_bounds__(256)
void heads_gemm(const float* __restrict__ feat,
                const float* __restrict__ wmean, const float* __restrict__ bmean,
                const float* __restrict__ wlogv, const float* __restrict__ blogv,
                const float* __restrict__ wbel,  const float* __restrict__ bbel,
                float* __restrict__ out, float* __restrict__ blog) {
    __shared__ float As[16 * 32], Bs[16 * 128];
    int row0 = blockIdx.x * 32;
    if (blockIdx.y == 0) {
        tile32_body(feat, kFD, wmean, bmean, out, kLAT, kFD, kLAT, row0, 0, As, Bs);
        return;
    }
    if (blockIdx.y == 1) {
        tile32_body(feat, kFD, wlogv, blogv, out + (size_t)kB * kLAT, kLAT, kFD, kLAT,
                    row0, 0, As, Bs);
        return;
    }
    // belief logits -> blog, then in-block softmax -> out
    tile32_body(feat, kFD, wbel, bbel, blog, kS, kFD, kS, row0, 0, As, Bs);
    __syncthreads();   // block's own gmem writes visible to block
    int tid = threadIdx.x;
    int r = tid >> 3, q = tid & 7;        // 32 rows x 8 lanes, 8 cols each
    float v[8];
    float mx = -1e30f;
#pragma unroll
    for (int j = 0; j < 8; j++) {
        v[j] = blog[(size_t)(row0 + r) * kS + q * 8 + j];
        mx = fmaxf(mx, v[j]);
    }
#pragma unroll
    for (int m = 4; m; m >>= 1) mx = fmaxf(mx, __shfl_xor_sync(0xffffffffu, mx, m));
    float sum = 0.f;
#pragma unroll
    for (int j = 0; j < 8; j++) { v[j] = __expf(v[j] - mx); sum += v[j]; }
#pragma unroll
    for (int m = 4; m; m >>= 1) sum += __shfl_xor_sync(0xffffffffu, sum, m);
    float inv = 1.f / sum;
    float* ob = out + (size_t)2 * kB * kLAT;
#pragma unroll
    for (int j = 0; j < 8; j++)
        ob[(size_t)(row0 + r) * kS + q * 8 + j] = v[j] * inv;
}

// ===================================================================
extern "C" void kernel_launch(void* const* d_in, const int* in_sizes, int n_in,
                              void* d_out, int out_size) {
    const float* signals = (const float*)d_in[0];
    const float* nact    = (const float*)d_in[1];
    const float* w0      = (const float*)d_in[2];
    const float* asrc0   = (const float*)d_in[3];
    const float* adst0   = (const float*)d_in[4];
    const float* bias0   = (const float*)d_in[5];
    const float* w1      = (const float*)d_in[6];
    const float* asrc1   = (const float*)d_in[7];
    const float* adst1   = (const float*)d_in[8];
    const float* bias1   = (const float*)d_in[9];
    const float* inw     = (const float*)d_in[10];
    const float* inb     = (const float*)d_in[11];
    const float* outw    = (const float*)d_in[12];
    const float* outb    = (const float*)d_in[13];
    const float* wmean   = (const float*)d_in[14];
    const float* bmean   = (const float*)d_in[15];
    const float* wlogv   = (const float*)d_in[16];
    const float* blogv   = (const float*)d_in[17];
    const float* wbel    = (const float*)d_in[18];
    const float* bbel    = (const float*)d_in[19];
    float* out = (float*)d_out;

    float *y, *seq, *kv, *q4, *ctx4, *feat, *blg, *v1, *w1t, *w0t;
    cudaGetSymbolAddress((void**)&y,    g_y);
    cudaGetSymbolAddress((void**)&seq,  g_seq);
    cudaGetSymbolAddress((void**)&kv,   g_kv);
    cudaGetSymbolAddress((void**)&q4,   g_q4);
    cudaGetSymbolAddress((void**)&ctx4, g_ctx4);
    cudaGetSymbolAddress((void**)&feat, g_feat);
    cudaGetSymbolAddress((void**)&blg,  g_blog);
    cudaGetSymbolAddress((void**)&v1,   g_v1);
    cudaGetSymbolAddress((void**)&w1t,  g_w1t);
    cudaGetSymbolAddress((void**)&w0t,  g_w0t);

    // 1. prep: v1 + w1t + w0t
    prep_kernel<<<152, 256>>>(w1, asrc1, adst1, w0, v1, w1t, w0t);
    // 2. fused GNN + layer-1 projection -> seq
    gnn_proj<<<kB, 256>>>(signals, nact, w0, w0t, asrc0, adst0, bias0, v1, w1t, bias1,
                          y, seq);
    // 3. unified q + kv projection (double-buffered)
    qkv_gemm<<<dim3(kB * kT / 128, 5), 256>>>(seq, inw, inb, kv, q4);
    // 4. attention (light)
    attn_kernel<<<kB, 256>>>(kv, q4, ctx4);
    // 5. out_proj
    tile32_gemm<<<dim3(kB / 32, 2), 256>>>(ctx4, outw, outb, feat, kFD, kFD, kFD, kFD);
    // 6. heads (mean | logvar | belief+softmax)
    heads_gemm<<<dim3(kB / 32, 3), 256>>>(feat, wmean, bmean, wlogv, blogv, wbel, bbel,
                                          out, blg);
}

// round 7
// speedup vs baseline: 2.2498x; 1.1119x over previous
#include <cuda_runtime.h>
#include <math.h>

static constexpr int kT = 5, kB = 512, kNA = 16, kS = 64, kA = 16;
static constexpr int kHID = 64, kH = 4, kFD = 256, kLAT = 128;
static constexpr int kN = kB * kNA;
static constexpr int kFIN = 80;

// -------- scratch (static device globals; no runtime allocation) --------
__device__ float g_y   [(size_t)kB * kT * 4 * kFD];   // aggregated layer-1 inputs
__device__ float g_seq [(size_t)kB * kT * kFD];
__device__ float g_kv  [(size_t)kB * kT * 2 * kFD];   // k|v
__device__ float g_q4  [(size_t)kB * kFD];            // q row t=4 per batch
__device__ float g_ctx4[(size_t)kB * kFD];
__device__ float g_feat[(size_t)kB * kFD];
__device__ float g_blog[(size_t)kB * kS];
__device__ float g_v1  [2 * 4 * kFD];                 // vsrc1 | vdst1
__device__ float g_w0t [kFIN * kFD];                  // w0^T (80 x 256)

// ===================================================================
// Prep: v1 + transpose w0 -> w0t. grid = 88.
// ===================================================================
__global__ __launch_bounds__(256)
void prep_kernel(const float* __restrict__ w1, const float* __restrict__ asrc1,
                 const float* __restrict__ adst1, const float* __restrict__ w0,
                 float* __restrict__ v1, float* __restrict__ w0t) {
    int bid = blockIdx.x, tid = threadIdx.x;
    if (bid < 8) {
        int idx = bid * 256 + tid;
        int which = idx >> 10;
        int h = (idx >> 8) & 3;
        int k = idx & 255;
        const float* a = which ? adst1 : asrc1;
        float acc = 0.f;
#pragma unroll
        for (int c = 0; c < 64; c++)
            acc += a[h * 64 + c] * w1[(size_t)(h * 64 + c) * kFD + k];
        v1[which * 1024 + h * 256 + k] = acc;
        return;
    }
    int c = bid - 8;                       // 80 blocks
    w0t[(size_t)c * kFD + tid] = w0[(size_t)tid * kFIN + c];
}

// ===================================================================
// GNN phase 1: one block per (t, g). 2560 blocks.
// features -> lin0 -> GAT0 softmax/agg -> relu -> GAT1 scores -> softmax
// (dst node 0) -> y[(g,t),h,:]
// ===================================================================
#define XS(j,c)       sm[(j)*256+(c)]
#define A0S(c)        sm[4096+(c)]
#define A0D(c)        sm[4352+(c)]
#define VS1(h,c)      sm[4608+(h)*256+(c)]
#define VD1(h,c)      sm[5632+(h)*256+(c)]
#define ACTS(j,k)     sm[6656+(j)*16+(k)]
#define SIG(c)        sm[6912+(c)]
#define ES0(j,h)      sm[6976+(j)*4+(h)]
#define ED0(j,h)      sm[7040+(j)*4+(h)]
#define ALPHA0(n,j,h) sm[7104+((n)*16+(j))*4+(h)]
#define ES1(j,h)      sm[8128+(j)*4+(h)]
#define ED1(h)        sm[8192+(h)]
#define ALPHA1(j,h)   sm[8200+(j)*4+(h)]

__global__ __launch_bounds__(256)
void gnn_phase1(const float* __restrict__ signals, const float* __restrict__ nact,
                const float* __restrict__ w0, const float* __restrict__ w0t,
                const float* __restrict__ asrc0, const float* __restrict__ adst0,
                const float* __restrict__ bias0, const float* __restrict__ v1,
                float* __restrict__ y) {
    __shared__ float sm[8264];
    int bid = blockIdx.x;
    int t = bid >> 9;          // bid = t*512 + g
    int g = bid & 511;
    int tid = threadIdx.x;

    float Wa[16];
#pragma unroll
    for (int k = 0; k < 16; k++) Wa[k] = w0[(size_t)tid * kFIN + 64 + k];
    A0S(tid) = asrc0[tid];
    A0D(tid) = adst0[tid];
#pragma unroll
    for (int h = 0; h < 4; h++) {
        VS1(h, tid) = v1[h * 256 + tid];
        VD1(h, tid) = v1[1024 + h * 256 + tid];
    }
    float b0 = bias0[tid];
    {
        ACTS(tid >> 4, tid & 15) = nact[((size_t)t * kB + g) * (kNA * kA) + tid];
        if (tid < 64) SIG(tid) = signals[((size_t)t * kB + g) * kS + tid];
    }
    __syncthreads();
    float xl0r[16];
#pragma unroll
    for (int j = 0; j < 16; j++) {
        float acc = 0.f;
#pragma unroll
        for (int k = 0; k < 16; k++) acc += ACTS(j, k) * Wa[k];
        xl0r[j] = acc;
    }
    {   // belief part (node 0 only) — coalesced via w0t
        float acc = 0.f;
#pragma unroll
        for (int c = 0; c < 64; c++) acc += SIG(c) * w0t[(size_t)c * kFD + tid];
        xl0r[0] += acc;
    }
#pragma unroll
    for (int j = 0; j < 16; j++) XS(j, tid) = xl0r[j];
    __syncthreads();
    {   // es0/ed0: 128 dots of 64; 2 threads per dot
        int d = tid >> 1, half = tid & 1;
        int which = d >> 6;
        int q = d & 63, j = q >> 2, h = q & 3;
        float acc = 0.f;
#pragma unroll
        for (int c = half * 32; c < half * 32 + 32; c++)
            acc += XS(j, h * 64 + c) * (which ? A0D(h * 64 + c) : A0S(h * 64 + c));
        acc += __shfl_xor_sync(0xffffffffu, acc, 1);
        if (half == 0) { if (which) ED0(j, h) = acc; else ES0(j, h) = acc; }
    }
    __syncthreads();
    {   // softmax0 per (dst n, head h)
        int n = tid >> 4, j = tid & 15;
#pragma unroll
        for (int h = 0; h < 4; h++) {
            float e = ES0(j, h) + ED0(n, h);
            e = e > 0.f ? e : 0.2f * e;
            float mx = e;
#pragma unroll
            for (int m = 8; m; m >>= 1) mx = fmaxf(mx, __shfl_xor_sync(0xffffffffu, mx, m));
            float ex = __expf(e - mx);
            float s = ex;
#pragma unroll
            for (int m = 8; m; m >>= 1) s += __shfl_xor_sync(0xffffffffu, s, m);
            ALPHA0(n, j, h) = ex / s;
        }
    }
    __syncthreads();
    float x1r[16];
    {
        int h = tid >> 6;
#pragma unroll
        for (int n = 0; n < 16; n++) {
            float acc = 0.f;
#pragma unroll
            for (int j = 0; j < 16; j++) acc += ALPHA0(n, j, h) * xl0r[j];
            x1r[n] = fmaxf(acc + b0, 0.f);
        }
    }
    __syncthreads();
#pragma unroll
    for (int n = 0; n < 16; n++) XS(n, tid) = x1r[n];
    __syncthreads();
    {   // es1[j][h] = x1[j].vsrc1[h]; 4 threads/dot
        int p = tid >> 2, q = tid & 3;
        int j = p >> 2, h = p & 3;
        float acc = 0.f;
#pragma unroll
        for (int c = q * 64; c < q * 64 + 64; c++) acc += XS(j, c) * VS1(h, c);
        acc += __shfl_xor_sync(0xffffffffu, acc, 1);
        acc += __shfl_xor_sync(0xffffffffu, acc, 2);
        if (q == 0) ES1(j, h) = acc;
    }
    if (tid < 32) {   // ed1[h] = x1[0].vdst1[h]; full warp 0
        int h = tid >> 3, q = tid & 7;
        float acc = 0.f;
#pragma unroll
        for (int c = q * 32; c < q * 32 + 32; c++) acc += XS(0, c) * VD1(h, c);
        acc += __shfl_xor_sync(0xffffffffu, acc, 1);
        acc += __shfl_xor_sync(0xffffffffu, acc, 2);
        acc += __shfl_xor_sync(0xffffffffu, acc, 4);
        if (q == 0) ED1(h) = acc;
    }
    __syncthreads();
    if (tid < 64) {   // softmax1 over j per h
        int h = tid >> 4, j = tid & 15;
        float e = ES1(j, h) + ED1(h);
        e = e > 0.f ? e : 0.2f * e;
        float mx = e;
#pragma unroll
        for (int m = 8; m; m >>= 1) mx = fmaxf(mx, __shfl_xor_sync(0xffffffffu, mx, m));
        float ex = __expf(e - mx);
        float s = ex;
#pragma unroll
        for (int m = 8; m; m >>= 1) s += __shfl_xor_sync(0xffffffffu, s, m);
        ALPHA1(j, h) = ex / s;
    }
    __syncthreads();
#pragma unroll
    for (int h = 0; h < 4; h++) {
        float acc = 0.f;
#pragma unroll
        for (int j = 0; j < 16; j++) acc += ALPHA1(j, h) * x1r[j];
        y[(((size_t)g * kT + t) * 4 + h) * kFD + tid] = acc;
    }
}

// ===================================================================
// Layer-1 projection GEMM: seq[r][h*64+c] = relu(y[r,h,:] . w1[h*64+c,:] + b1)
// 128x64 tiles, double-buffered. grid (20, 4=h).
// ===================================================================
__global__ __launch_bounds__(256)
void proj_gemm(const float* __restrict__ y, const float* __restrict__ w1,
               const float* __restrict__ bias1, float* __restrict__ seq) {
    __shared__ float As[2][16][128];
    __shared__ float Ws[2][16][64];
    int tid = threadIdx.x;
    int row0 = blockIdx.x * 128;
    int h = blockIdx.y;
    const float* A = y + h * kFD;                 // lda = 4*kFD
    const float* W = w1 + (size_t)h * 64 * kFD;   // ldw = kFD
    int ty = tid >> 4, tx = tid & 15;             // 16x16 threads: 8 rows x 4 cols each
    float acc[8][4];
#pragma unroll
    for (int i = 0; i < 8; i++)
#pragma unroll
        for (int j = 0; j < 4; j++) acc[i][j] = 0.f;

    // initial loads (k0 = 0)
#pragma unroll
    for (int i = 0; i < 2; i++) {
        int f = tid + i * 256;
        int r = f >> 2, kq = (f & 3) * 4;
        float4 v = *(const float4*)&A[(size_t)(row0 + r) * (4 * kFD) + kq];
        As[0][kq + 0][r] = v.x; As[0][kq + 1][r] = v.y;
        As[0][kq + 2][r] = v.z; As[0][kq + 3][r] = v.w;
    }
    {
        int r = tid >> 2, kq = (tid & 3) * 4;     // 64 rows x 4 f4
        float4 w = *(const float4*)&W[(size_t)r * kFD + kq];
        Ws[0][kq + 0][r] = w.x; Ws[0][kq + 1][r] = w.y;
        Ws[0][kq + 2][r] = w.z; Ws[0][kq + 3][r] = w.w;
    }
    __syncthreads();
    int buf = 0;
    for (int k0 = 0; k0 < kFD; k0 += 16, buf ^= 1) {
        if (k0 + 16 < kFD) {
            int kn = k0 + 16;
#pragma unroll
            for (int i = 0; i < 2; i++) {
                int f = tid + i * 256;
                int r = f >> 2, kq = (f & 3) * 4;
                float4 v = *(const float4*)&A[(size_t)(row0 + r) * (4 * kFD) + kn + kq];
                As[buf ^ 1][kq + 0][r] = v.x; As[buf ^ 1][kq + 1][r] = v.y;
                As[buf ^ 1][kq + 2][r] = v.z; As[buf ^ 1][kq + 3][r] = v.w;
            }
            {
                int r = tid >> 2, kq = (tid & 3) * 4;
                float4 w = *(const float4*)&W[(size_t)r * kFD + kn + kq];
                Ws[buf ^ 1][kq + 0][r] = w.x; Ws[buf ^ 1][kq + 1][r] = w.y;
                Ws[buf ^ 1][kq + 2][r] = w.z; Ws[buf ^ 1][kq + 3][r] = w.w;
            }
        }
#pragma unroll
        for (int k = 0; k < 16; k++) {
            float4 a0 = *(const float4*)&As[buf][k][ty * 8];
            float4 a1 = *(const float4*)&As[buf][k][ty * 8 + 4];
            float4 b4 = *(const float4*)&Ws[buf][k][tx * 4];
            float av[8] = {a0.x, a0.y, a0.z, a0.w, a1.x, a1.y, a1.z, a1.w};
            float bv[4] = {b4.x, b4.y, b4.z, b4.w};
#pragma unroll
            for (int i = 0; i < 8; i++)
#pragma unroll
                for (int j = 0; j < 4; j++) acc[i][j] += av[i] * bv[j];
        }
        __syncthreads();
    }
#pragma unroll
    for (int i = 0; i < 8; i++) {
        int r = row0 + ty * 8 + i;
#pragma unroll
        for (int j = 0; j < 4; j++) {
            int c = h * 64 + tx * 4 + j;
            seq[(size_t)r * kFD + c] = fmaxf(acc[i][j] + bias1[c], 0.f);
        }
    }
}

// ===================================================================
// Unified q + kv projection GEMM, double-buffered 128x128x16.
// ===================================================================
__global__ __launch_bounds__(256)
void qkv_gemm(const float* __restrict__ seq, const float* __restrict__ inw,
              const float* __restrict__ inb, float* __restrict__ kv,
              float* __restrict__ q4) {
    __shared__ float As[2][16][128];
    __shared__ float Bs[2][16][128];
    int tid = threadIdx.x;
    const float *A, *W, *bias;
    float* C;
    int lda, ldc, row0, col0;
    if (blockIdx.y == 4) {
        int rt = blockIdx.x & 3, ct = blockIdx.x >> 2;
        if (ct >= 2) return;
        row0 = rt * 128; col0 = ct * 128;
        A = seq + 4 * kFD; lda = kT * kFD;
        W = inw; bias = inb;
        C = q4; ldc = kFD;
    } else {
        row0 = blockIdx.x * 128; col0 = blockIdx.y * 128;
        A = seq; lda = kFD;
        W = inw + 256 * kFD; bias = inb + 256;
        C = kv; ldc = 2 * kFD;
    }
    int tx = tid & 15, ty = tid >> 4;
    float acc[8][8];
#pragma unroll
    for (int i = 0; i < 8; i++)
#pragma unroll
        for (int j = 0; j < 8; j++) acc[i][j] = 0.f;

#pragma unroll
    for (int i = 0; i < 2; i++) {
        int f = tid + i * 256;
        int r = f >> 2, kq = (f & 3) * 4;
        float4 v = *(const float4*)&A[(size_t)(row0 + r) * lda + kq];
        As[0][kq + 0][r] = v.x; As[0][kq + 1][r] = v.y;
        As[0][kq + 2][r] = v.z; As[0][kq + 3][r] = v.w;
        float4 w = *(const float4*)&W[(size_t)(col0 + r) * kFD + kq];
        Bs[0][kq + 0][r] = w.x; Bs[0][kq + 1][r] = w.y;
        Bs[0][kq + 2][r] = w.z; Bs[0][kq + 3][r] = w.w;
    }
    __syncthreads();
    int buf = 0;
    for (int k0 = 0; k0 < 256; k0 += 16, buf ^= 1) {
        if (k0 + 16 < 256) {
            int kn = k0 + 16;
#pragma unroll
            for (int i = 0; i < 2; i++) {
                int f = tid + i * 256;
                int r = f >> 2, kq = (f & 3) * 4;
                float4 v = *(const float4*)&A[(size_t)(row0 + r) * lda + kn + kq];
                As[buf ^ 1][kq + 0][r] = v.x; As[buf ^ 1][kq + 1][r] = v.y;
                As[buf ^ 1][kq + 2][r] = v.z; As[buf ^ 1][kq + 3][r] = v.w;
                float4 w = *(const float4*)&W[(size_t)(col0 + r) * kFD + kn + kq];
                Bs[buf ^ 1][kq + 0][r] = w.x; Bs[buf ^ 1][kq + 1][r] = w.y;
                Bs[buf ^ 1][kq + 2][r] = w.z; Bs[buf ^ 1][kq + 3][r] = w.w;
            }
        }
#pragma unroll
        for (int k = 0; k < 16; k++) {
            float4 a0 = *(const float4*)&As[buf][k][ty * 8];
            float4 a1 = *(const float4*)&As[buf][k][ty * 8 + 4];
            float4 b0 = *(const float4*)&Bs[buf][k][tx * 8];
            float4 b1 = *(const float4*)&Bs[buf][k][tx * 8 + 4];
            float av[8] = {a0.x, a0.y, a0.z, a0.w, a1.x, a1.y, a1.z, a1.w};
            float bv[8] = {b0.x, b0.y, b0.z, b0.w, b1.x, b1.y, b1.z, b1.w};
#pragma unroll
            for (int i = 0; i < 8; i++)
#pragma unroll
                for (int j = 0; j < 8; j++) acc[i][j] += av[i] * bv[j];
        }
        __syncthreads();
    }
#pragma unroll
    for (int i = 0; i < 8; i++) {
        int r = row0 + ty * 8 + i;
#pragma unroll
        for (int j = 0; j < 8; j++) {
            int c = col0 + tx * 8 + j;
            C[(size_t)r * ldc + c] = acc[i][j] + bias[c];
        }
    }
}

// ===================================================================
// Attention (q prebatched). One block per batch b.
// ===================================================================
__global__ __launch_bounds__(256)
void attn_kernel(const float* __restrict__ kv, const float* __restrict__ q4g,
                 float* __restrict__ ctx4) {
    int b = blockIdx.x;
    __shared__ float ks[kT][256], vs[kT][256], q4[256];
    __shared__ float sc[4][kT], attnw[4][kT];
    int tid = threadIdx.x;
#pragma unroll
    for (int t = 0; t < kT; t++) {
        size_t base = ((size_t)(b * kT + t)) * (2 * kFD);
        ks[t][tid] = kv[base + tid];
        vs[t][tid] = kv[base + kFD + tid];
    }
    q4[tid] = q4g[(size_t)b * kFD + tid];
    __syncthreads();
    int warp = tid >> 5, lane = tid & 31;
    for (int p = warp; p < 4 * kT; p += 8) {
        int h = p / kT, kt = p % kT;
        float s = 0.f;
        for (int d = lane; d < 64; d += 32) s += q4[h * 64 + d] * ks[kt][h * 64 + d];
#pragma unroll
        for (int m = 16; m; m >>= 1) s += __shfl_xor_sync(0xffffffffu, s, m);
        if (lane == 0) sc[h][kt] = s * 0.125f;
    }
    __syncthreads();
    if (tid < 32) {
        int h = tid & 3;
        float mx = -1e30f;
#pragma unroll
        for (int kt = 0; kt < kT; kt++) mx = fmaxf(mx, sc[h][kt]);
        float e[kT], sum = 0.f;
#pragma unroll
        for (int kt = 0; kt < kT; kt++) { e[kt] = __expf(sc[h][kt] - mx); sum += e[kt]; }
        if (tid < 4)
#pragma unroll
            for (int kt = 0; kt < kT; kt++) attnw[h][kt] = e[kt] / sum;
    }
    __syncthreads();
    int h = tid >> 6;
    float acc = 0.f;
#pragma unroll
    for (int kt = 0; kt < kT; kt++) acc += attnw[h][kt] * vs[kt][tid];
    ctx4[(size_t)b * kFD + tid] = acc;
}

// ===================================================================
// 32x128 tile GEMM body (small-M tails)
// ===================================================================
__device__ __forceinline__
void tile32_body(const float* __restrict__ A, int lda, const float* __restrict__ W,
                 const float* __restrict__ bias, float* __restrict__ C, int ldc,
                 int K, int Nc, int row0, int col0, float* As, float* Bs) {
    int tid = threadIdx.x;
    int tx = tid & 31, ty = tid >> 5;
    float acc[4][4];
#pragma unroll
    for (int i = 0; i < 4; i++)
#pragma unroll
        for (int j = 0; j < 4; j++) acc[i][j] = 0.f;
    for (int k0 = 0; k0 < K; k0 += 16) {
        if (tid < 128) {
            int r = tid >> 2, kq = (tid & 3) * 4;
            float4 v = *(const float4*)&A[(size_t)(row0 + r) * lda + k0 + kq];
            As[(kq + 0) * 32 + r] = v.x; As[(kq + 1) * 32 + r] = v.y;
            As[(kq + 2) * 32 + r] = v.z; As[(kq + 3) * 32 + r] = v.w;
        }
#pragma unroll
        for (int i = 0; i < 2; i++) {
            int f = tid + i * 256;
            int r = f >> 2, kq = (f & 3) * 4;
            int col = col0 + r;
            float4 v = make_float4(0.f, 0.f, 0.f, 0.f);
            if (col < Nc) v = *(const float4*)&W[(size_t)col * K + k0 + kq];
            Bs[(kq + 0) * 128 + r] = v.x; Bs[(kq + 1) * 128 + r] = v.y;
            Bs[(kq + 2) * 128 + r] = v.z; Bs[(kq + 3) * 128 + r] = v.w;
        }
        __syncthreads();
#pragma unroll
        for (int k = 0; k < 16; k++) {
            float4 a4 = *(const float4*)&As[k * 32 + ty * 4];
            float4 b4 = *(const float4*)&Bs[k * 128 + tx * 4];
            float av[4] = {a4.x, a4.y, a4.z, a4.w};
            float bv[4] = {b4.x, b4.y, b4.z, b4.w};
#pragma unroll
            for (int i = 0; i < 4; i++)
#pragma unroll
                for (int j = 0; j < 4; j++) acc[i][j] += av[i] * bv[j];
        }
        __syncthreads();
    }
#pragma unroll
    for (int i = 0; i < 4; i++) {
        int r = row0 + ty * 4 + i;
#pragma unroll
        for (int j = 0; j < 4; j++) {
            int c = col0 + tx * 4 + j;
            if (c < Nc) C[(size_t)r * ldc + c] = acc[i][j] + bias[c];
        }
    }
}

__global__ __launch_bounds__(256)
void tile32_gemm(const float* __restrict__ A, const float* __restrict__ W,
                 const float* __restrict__ bias, float* __restrict__ C,
                 int lda, int ldc, int K, int Nc) {
    __shared__ float As[16 * 32], Bs[16 * 128];
    tile32_body(A, lda, W, bias, C, ldc, K, Nc, blockIdx.x * 32, blockIdx.y * 128, As, Bs);
}

// heads: by selects {mean, logvar, belief}; belief fuses its softmax.
__global__ __launch_bounds__(256)
void heads_gemm(const float* __restrict__ feat,
                const float* __restrict__ wmean, const float* __restrict__ bmean,
                const float* __restrict__ wlogv, const float* __restrict__ blogv,
                const float* __restrict__ wbel,  const float* __restrict__ bbel,
                float* __restrict__ out, float* __restrict__ blog) {
    __shared__ float As[16 * 32], Bs[16 * 128];
    int row0 = blockIdx.x * 32;
    if (blockIdx.y == 0) {
        tile32_body(feat, kFD, wmean, bmean, out, kLAT, kFD, kLAT, row0, 0, As, Bs);
        return;
    }
    if (blockIdx.y == 1) {
        tile32_body(feat, kFD, wlogv, blogv, out + (size_t)kB * kLAT, kLAT, kFD, kLAT,
                    row0, 0, As, Bs);
        return;
    }
    tile32_body(feat, kFD, wbel, bbel, blog, kS, kFD, kS, row0, 0, As, Bs);
    __syncthreads();
    int tid = threadIdx.x;
    int r = tid >> 3, q = tid & 7;
    float v[8];
    float mx = -1e30f;
#pragma unroll
    for (int j = 0; j < 8; j++) {
        v[j] = blog[(size_t)(row0 + r) * kS + q * 8 + j];
        mx = fmaxf(mx, v[j]);
    }
#pragma unroll
    for (int m = 4; m; m >>= 1) mx = fmaxf(mx, __shfl_xor_sync(0xffffffffu, mx, m));
    float sum = 0.f;
#pragma unroll
    for (int j = 0; j < 8; j++) { v[j] = __expf(v[j] - mx); sum += v[j]; }
#pragma unroll
    for (int m = 4; m; m >>= 1) sum += __shfl_xor_sync(0xffffffffu, sum, m);
    float inv = 1.f / sum;
    float* ob = out + (size_t)2 * kB * kLAT;
#pragma unroll
    for (int j = 0; j < 8; j++)
        ob[(size_t)(row0 + r) * kS + q * 8 + j] = v[j] * inv;
}

// ===================================================================
extern "C" void kernel_launch(void* const* d_in, const int* in_sizes, int n_in,
                              void* d_out, int out_size) {
    const float* signals = (const float*)d_in[0];
    const float* nact    = (const float*)d_in[1];
    const float* w0      = (const float*)d_in[2];
    const float* asrc0   = (const float*)d_in[3];
    const float* adst0   = (const float*)d_in[4];
    const float* bias0   = (const float*)d_in[5];
    const float* w1      = (const float*)d_in[6];
    const float* asrc1   = (const float*)d_in[7];
    const float* adst1   = (const float*)d_in[8];
    const float* bias1   = (const float*)d_in[9];
    const float* inw     = (const float*)d_in[10];
    const float* inb     = (const float*)d_in[11];
    const float* outw    = (const float*)d_in[12];
    const float* outb    = (const float*)d_in[13];
    const float* wmean   = (const float*)d_in[14];
    const float* bmean   = (const float*)d_in[15];
    const float* wlogv   = (const float*)d_in[16];
    const float* blogv   = (const float*)d_in[17];
    const float* wbel    = (const float*)d_in[18];
    const float* bbel    = (const float*)d_in[19];
    float* out = (float*)d_out;

    float *y, *seq, *kv, *q4, *ctx4, *feat, *blg, *v1, *w0t;
    cudaGetSymbolAddress((void**)&y,    g_y);
    cudaGetSymbolAddress((void**)&seq,  g_seq);
    cudaGetSymbolAddress((void**)&kv,   g_kv);
    cudaGetSymbolAddress((void**)&q4,   g_q4);
    cudaGetSymbolAddress((void**)&ctx4, g_ctx4);
    cudaGetSymbolAddress((void**)&feat, g_feat);
    cudaGetSymbolAddress((void**)&blg,  g_blog);
    cudaGetSymbolAddress((void**)&v1,   g_v1);
    cudaGetSymbolAddress((void**)&w0t,  g_w0t);

    // 1. prep: v1 + w0t
    prep_kernel<<<88, 256>>>(w1, asrc1, adst1, w0, v1, w0t);
    // 2. GNN phase 1: one block per (t,g) -> y
    gnn_phase1<<<kT * kB, 256>>>(signals, nact, w0, w0t, asrc0, adst0, bias0, v1, y);
    // 3. layer-1 projection GEMM -> seq
    proj_gemm<<<dim3(kB * kT / 128, 4), 256>>>(y, w1, bias1, seq);
    // 4. unified q + kv projection
    qkv_gemm<<<dim3(kB * kT / 128, 5), 256>>>(seq, inw, inb, kv, q4);
    // 5. attention
    attn_kernel<<<kB, 256>>>(kv, q4, ctx4);
    // 6. out_proj
    tile32_gemm<<<dim3(kB / 32, 2), 256>>>(ctx4, outw, outb, feat, kFD, kFD, kFD, kFD);
    // 7. heads (mean | logvar | belief+softmax)
    heads_gemm<<<dim3(kB / 32, 3), 256>>>(feat, wmean, bmean, wlogv, blogv, wbel, bbel,
                                          out, blg);
}

// round 8
// speedup vs baseline: 2.6553x; 1.1803x over previous
#include <cuda_runtime.h>
#include <math.h>

static constexpr int kT = 5, kB = 512, kNA = 16, kS = 64, kA = 16;
static constexpr int kHID = 64, kH = 4, kFD = 256, kLAT = 128;
static constexpr int kN = kB * kNA;
static constexpr int kFIN = 80;

// -------- scratch (static device globals; no runtime allocation) --------
__device__ float g_y   [(size_t)kB * kT * 4 * kFD];
__device__ float g_seq [(size_t)kB * kT * kFD];
__device__ float g_kv  [(size_t)kB * kT * 2 * kFD];
__device__ float g_q4  [(size_t)kB * kFD];
__device__ float g_ctx4[(size_t)kB * kFD];
__device__ float g_feat[(size_t)kB * kFD];
__device__ float g_blog[(size_t)kB * kS];
__device__ float g_v1  [2 * 4 * kFD];
__device__ float g_w0t [kFIN * kFD];

// ===================================================================
// Prep: v1 + transpose w0 -> w0t. grid = 88.
// ===================================================================
__global__ __launch_bounds__(256)
void prep_kernel(const float* __restrict__ w1, const float* __restrict__ asrc1,
                 const float* __restrict__ adst1, const float* __restrict__ w0,
                 float* __restrict__ v1, float* __restrict__ w0t) {
    int bid = blockIdx.x, tid = threadIdx.x;
    if (bid < 8) {
        int idx = bid * 256 + tid;
        int which = idx >> 10;
        int h = (idx >> 8) & 3;
        int k = idx & 255;
        const float* a = which ? adst1 : asrc1;
        float acc = 0.f;
#pragma unroll
        for (int c = 0; c < 64; c++)
            acc += a[h * 64 + c] * w1[(size_t)(h * 64 + c) * kFD + k];
        v1[which * 1024 + h * 256 + k] = acc;
        return;
    }
    int c = bid - 8;
    w0t[(size_t)c * kFD + tid] = w0[(size_t)tid * kFIN + c];
}

// ===================================================================
// GNN phase 1: one block per (t, g). 2560 blocks. (unchanged from R7)
// ===================================================================
#define XS(j,c)       sm[(j)*256+(c)]
#define A0S(c)        sm[4096+(c)]
#define A0D(c)        sm[4352+(c)]
#define VS1(h,c)      sm[4608+(h)*256+(c)]
#define VD1(h,c)      sm[5632+(h)*256+(c)]
#define ACTS(j,k)     sm[6656+(j)*16+(k)]
#define SIG(c)        sm[6912+(c)]
#define ES0(j,h)      sm[6976+(j)*4+(h)]
#define ED0(j,h)      sm[7040+(j)*4+(h)]
#define ALPHA0(n,j,h) sm[7104+((n)*16+(j))*4+(h)]
#define ES1(j,h)      sm[8128+(j)*4+(h)]
#define ED1(h)        sm[8192+(h)]
#define ALPHA1(j,h)   sm[8200+(j)*4+(h)]

__global__ __launch_bounds__(256)
void gnn_phase1(const float* __restrict__ signals, const float* __restrict__ nact,
                const float* __restrict__ w0, const float* __restrict__ w0t,
                const float* __restrict__ asrc0, const float* __restrict__ adst0,
                const float* __restrict__ bias0, const float* __restrict__ v1,
                float* __restrict__ y) {
    __shared__ float sm[8264];
    int bid = blockIdx.x;
    int t = bid >> 9;
    int g = bid & 511;
    int tid = threadIdx.x;

    float Wa[16];
#pragma unroll
    for (int k = 0; k < 16; k++) Wa[k] = w0[(size_t)tid * kFIN + 64 + k];
    A0S(tid) = asrc0[tid];
    A0D(tid) = adst0[tid];
#pragma unroll
    for (int h = 0; h < 4; h++) {
        VS1(h, tid) = v1[h * 256 + tid];
        VD1(h, tid) = v1[1024 + h * 256 + tid];
    }
    float b0 = bias0[tid];
    {
        ACTS(tid >> 4, tid & 15) = nact[((size_t)t * kB + g) * (kNA * kA) + tid];
        if (tid < 64) SIG(tid) = signals[((size_t)t * kB + g) * kS + tid];
    }
    __syncthreads();
    float xl0r[16];
#pragma unroll
    for (int j = 0; j < 16; j++) {
        float acc = 0.f;
#pragma unroll
        for (int k = 0; k < 16; k++) acc += ACTS(j, k) * Wa[k];
        xl0r[j] = acc;
    }
    {
        float acc = 0.f;
#pragma unroll
        for (int c = 0; c < 64; c++) acc += SIG(c) * w0t[(size_t)c * kFD + tid];
        xl0r[0] += acc;
    }
#pragma unroll
    for (int j = 0; j < 16; j++) XS(j, tid) = xl0r[j];
    __syncthreads();
    {
        int d = tid >> 1, half = tid & 1;
        int which = d >> 6;
        int q = d & 63, j = q >> 2, h = q & 3;
        float acc = 0.f;
#pragma unroll
        for (int c = half * 32; c < half * 32 + 32; c++)
            acc += XS(j, h * 64 + c) * (which ? A0D(h * 64 + c) : A0S(h * 64 + c));
        acc += __shfl_xor_sync(0xffffffffu, acc, 1);
        if (half == 0) { if (which) ED0(j, h) = acc; else ES0(j, h) = acc; }
    }
    __syncthreads();
    {
        int n = tid >> 4, j = tid & 15;
#pragma unroll
        for (int h = 0; h < 4; h++) {
            float e = ES0(j, h) + ED0(n, h);
            e = e > 0.f ? e : 0.2f * e;
            float mx = e;
#pragma unroll
            for (int m = 8; m; m >>= 1) mx = fmaxf(mx, __shfl_xor_sync(0xffffffffu, mx, m));
            float ex = __expf(e - mx);
            float s = ex;
#pragma unroll
            for (int m = 8; m; m >>= 1) s += __shfl_xor_sync(0xffffffffu, s, m);
            ALPHA0(n, j, h) = ex / s;
        }
    }
    __syncthreads();
    float x1r[16];
    {
        int h = tid >> 6;
#pragma unroll
        for (int n = 0; n < 16; n++) {
            float acc = 0.f;
#pragma unroll
            for (int j = 0; j < 16; j++) acc += ALPHA0(n, j, h) * xl0r[j];
            x1r[n] = fmaxf(acc + b0, 0.f);
        }
    }
    __syncthreads();
#pragma unroll
    for (int n = 0; n < 16; n++) XS(n, tid) = x1r[n];
    __syncthreads();
    {
        int p = tid >> 2, q = tid & 3;
        int j = p >> 2, h = p & 3;
        float acc = 0.f;
#pragma unroll
        for (int c = q * 64; c < q * 64 + 64; c++) acc += XS(j, c) * VS1(h, c);
        acc += __shfl_xor_sync(0xffffffffu, acc, 1);
        acc += __shfl_xor_sync(0xffffffffu, acc, 2);
        if (q == 0) ES1(j, h) = acc;
    }
    if (tid < 32) {
        int h = tid >> 3, q = tid & 7;
        float acc = 0.f;
#pragma unroll
        for (int c = q * 32; c < q * 32 + 32; c++) acc += XS(0, c) * VD1(h, c);
        acc += __shfl_xor_sync(0xffffffffu, acc, 1);
        acc += __shfl_xor_sync(0xffffffffu, acc, 2);
        acc += __shfl_xor_sync(0xffffffffu, acc, 4);
        if (q == 0) ED1(h) = acc;
    }
    __syncthreads();
    if (tid < 64) {
        int h = tid >> 4, j = tid & 15;
        float e = ES1(j, h) + ED1(h);
        e = e > 0.f ? e : 0.2f * e;
        float mx = e;
#pragma unroll
        for (int m = 8; m; m >>= 1) mx = fmaxf(mx, __shfl_xor_sync(0xffffffffu, mx, m));
        float ex = __expf(e - mx);
        float s = ex;
#pragma unroll
        for (int m = 8; m; m >>= 1) s += __shfl_xor_sync(0xffffffffu, s, m);
        ALPHA1(j, h) = ex / s;
    }
    __syncthreads();
#pragma unroll
    for (int h = 0; h < 4; h++) {
        float acc = 0.f;
#pragma unroll
        for (int j = 0; j < 16; j++) acc += ALPHA1(j, h) * x1r[j];
        y[(((size_t)g * kT + t) * 4 + h) * kFD + tid] = acc;
    }
}

// ===================================================================
// TF32 tensor-core GEMM tile: C[128 x 64] = A[128 x 256] @ W[64 x 256]^T
// mma.sync.m16n8k8 tf32. 8 warps as 4x2; warp tile 32x32 (2 mtiles x 4 ntiles).
// K chunks of 16, double-buffered padded smem (conflict-free frag loads).
// A: row-major lda; W: row-major ld=256 (pre-offset to tile rows);
// bias/C pre-offset to tile col base. K = 256 fixed.
// ===================================================================
__device__ __forceinline__ unsigned f2tf(float x) {
    unsigned u;
    asm("cvt.rna.tf32.f32 %0, %1;" : "=r"(u) : "f"(x));
    return u;
}

#define SA(b,r,c) sA[(b)*(128*20) + (r)*20 + (c)]
#define SB(b,r,c) sB[(b)*(64*20)  + (r)*20 + (c)]

__device__ __forceinline__
void tf32_tile(const float* __restrict__ A, int lda,
               const float* __restrict__ Wt,      // + tilecol*256
               const float* __restrict__ bias,    // + tilecol
               float* __restrict__ C, int ldc,    // + tilecol
               int row0, int relu,
               unsigned* sA, unsigned* sB) {
    int tid = threadIdx.x;
    int lane = tid & 31, warp = tid >> 5;
    int wm = warp & 3, wn = warp >> 2;
    int g4 = lane >> 2, l4 = lane & 3;

    float c[2][4][4];
#pragma unroll
    for (int mt = 0; mt < 2; mt++)
#pragma unroll
        for (int nt = 0; nt < 4; nt++)
#pragma unroll
            for (int i = 0; i < 4; i++) c[mt][nt][i] = 0.f;

    // initial chunk 0 (k0 = 0)
    {
#pragma unroll
        for (int i = 0; i < 2; i++) {
            int idx = tid + i * 256;            // 0..511
            int r = idx >> 2, c4 = idx & 3;
            float4 v = *(const float4*)&A[(size_t)(row0 + r) * lda + c4 * 4];
            SA(0, r, c4 * 4 + 0) = f2tf(v.x); SA(0, r, c4 * 4 + 1) = f2tf(v.y);
            SA(0, r, c4 * 4 + 2) = f2tf(v.z); SA(0, r, c4 * 4 + 3) = f2tf(v.w);
        }
        int r = tid >> 2, c4 = tid & 3;
        float4 w = *(const float4*)&Wt[(size_t)r * 256 + c4 * 4];
        SB(0, r, c4 * 4 + 0) = f2tf(w.x); SB(0, r, c4 * 4 + 1) = f2tf(w.y);
        SB(0, r, c4 * 4 + 2) = f2tf(w.z); SB(0, r, c4 * 4 + 3) = f2tf(w.w);
    }
    __syncthreads();

    for (int ch = 0; ch < 16; ch++) {
        int buf = ch & 1;
        float4 pa0, pa1, pb;
        if (ch < 15) {
            int k0 = (ch + 1) * 16;
            {
                int idx = tid;
                int r = idx >> 2, c4 = idx & 3;
                pa0 = *(const float4*)&A[(size_t)(row0 + r) * lda + k0 + c4 * 4];
            }
            {
                int idx = tid + 256;
                int r = idx >> 2, c4 = idx & 3;
                pa1 = *(const float4*)&A[(size_t)(row0 + r) * lda + k0 + c4 * 4];
            }
            {
                int r = tid >> 2, c4 = tid & 3;
                pb = *(const float4*)&Wt[(size_t)r * 256 + k0 + c4 * 4];
            }
        }
        // 2 k-steps of 8
#pragma unroll
        for (int kk = 0; kk < 2; kk++) {
            unsigned af[2][4], bf[4][2];
#pragma unroll
            for (int mt = 0; mt < 2; mt++) {
                int ar = wm * 32 + mt * 16 + g4;
                int ac = kk * 8 + l4;
                af[mt][0] = SA(buf, ar, ac);
                af[mt][1] = SA(buf, ar + 8, ac);
                af[mt][2] = SA(buf, ar, ac + 4);
                af[mt][3] = SA(buf, ar + 8, ac + 4);
            }
#pragma unroll
            for (int nt = 0; nt < 4; nt++) {
                int br = wn * 32 + nt * 8 + g4;
                bf[nt][0] = SB(buf, br, kk * 8 + l4);
                bf[nt][1] = SB(buf, br, kk * 8 + l4 + 4);
            }
#pragma unroll
            for (int mt = 0; mt < 2; mt++)
#pragma unroll
                for (int nt = 0; nt < 4; nt++) {
                    asm volatile(
                        "mma.sync.aligned.m16n8k8.row.col.f32.tf32.tf32.f32 "
                        "{%0,%1,%2,%3}, {%4,%5,%6,%7}, {%8,%9}, {%0,%1,%2,%3};"
                        : "+f"(c[mt][nt][0]), "+f"(c[mt][nt][1]),
                          "+f"(c[mt][nt][2]), "+f"(c[mt][nt][3])
                        : "r"(af[mt][0]), "r"(af[mt][1]), "r"(af[mt][2]), "r"(af[mt][3]),
                          "r"(bf[nt][0]), "r"(bf[nt][1]));
                }
        }
        if (ch < 15) {
            int nb = buf ^ 1;
            {
                int idx = tid;
                int r = idx >> 2, c4 = idx & 3;
                SA(nb, r, c4 * 4 + 0) = f2tf(pa0.x); SA(nb, r, c4 * 4 + 1) = f2tf(pa0.y);
                SA(nb, r, c4 * 4 + 2) = f2tf(pa0.z); SA(nb, r, c4 * 4 + 3) = f2tf(pa0.w);
            }
            {
                int idx = tid + 256;
                int r = idx >> 2, c4 = idx & 3;
                SA(nb, r, c4 * 4 + 0) = f2tf(pa1.x); SA(nb, r, c4 * 4 + 1) = f2tf(pa1.y);
                SA(nb, r, c4 * 4 + 2) = f2tf(pa1.z); SA(nb, r, c4 * 4 + 3) = f2tf(pa1.w);
            }
            {
                int r = tid >> 2, c4 = tid & 3;
                SB(nb, r, c4 * 4 + 0) = f2tf(pb.x); SB(nb, r, c4 * 4 + 1) = f2tf(pb.y);
                SB(nb, r, c4 * 4 + 2) = f2tf(pb.z); SB(nb, r, c4 * 4 + 3) = f2tf(pb.w);
            }
        }
        __syncthreads();
    }

    // epilogue
#pragma unroll
    for (int mt = 0; mt < 2; mt++) {
        int r = row0 + wm * 32 + mt * 16 + g4;
#pragma unroll
        for (int nt = 0; nt < 4; nt++) {
            int cc = wn * 32 + nt * 8 + 2 * l4;
            float b0v = bias[cc], b1v = bias[cc + 1];
            float v0 = c[mt][nt][0] + b0v, v1 = c[mt][nt][1] + b1v;
            float v2 = c[mt][nt][2] + b0v, v3 = c[mt][nt][3] + b1v;
            if (relu) {
                v0 = fmaxf(v0, 0.f); v1 = fmaxf(v1, 0.f);
                v2 = fmaxf(v2, 0.f); v3 = fmaxf(v3, 0.f);
            }
            C[(size_t)r * ldc + cc] = v0;
            C[(size_t)r * ldc + cc + 1] = v1;
            C[(size_t)(r + 8) * ldc + cc] = v2;
            C[(size_t)(r + 8) * ldc + cc + 1] = v3;
        }
    }
}

// layer-1 projection: seq[:, h*64:+64] = relu(y[:,h,:] @ w1_h^T + b1_h). grid (20,4)
__global__ __launch_bounds__(256)
void proj_tf32(const float* __restrict__ y, const float* __restrict__ w1,
               const float* __restrict__ bias1, float* __restrict__ seq) {
    __shared__ unsigned sA[2 * 128 * 20], sB[2 * 64 * 20];
    int h = blockIdx.y;
    tf32_tile(y + h * kFD, 4 * kFD,
              w1 + (size_t)h * 64 * kFD, bias1 + h * 64,
              seq + h * 64, kFD, blockIdx.x * 128, 1, sA, sB);
}

// q+kv projection: grid (20, 9). y<8: kv col tile y; y==8: q (16 blocks).
__global__ __launch_bounds__(256)
void qkv_tf32(const float* __restrict__ seq, const float* __restrict__ inw,
              const float* __restrict__ inb, float* __restrict__ kv,
              float* __restrict__ q4) {
    __shared__ unsigned sA[2 * 128 * 20], sB[2 * 64 * 20];
    int by = blockIdx.y, bx = blockIdx.x;
    if (by < 8) {
        tf32_tile(seq, kFD,
                  inw + (size_t)(256 + by * 64) * kFD, inb + 256 + by * 64,
                  kv + by * 64, 2 * kFD, bx * 128, 0, sA, sB);
    } else {
        if (bx >= 16) return;
        int rt = bx & 3, ct = bx >> 2;
        tf32_tile(seq + 4 * kFD, kT * kFD,
                  inw + (size_t)ct * 64 * kFD, inb + ct * 64,
                  q4 + ct * 64, kFD, rt * 128, 0, sA, sB);
    }
}

// ===================================================================
// Attention (q prebatched). One block per batch b. (unchanged)
// ===================================================================
__global__ __launch_bounds__(256)
void attn_kernel(const float* __restrict__ kv, const float* __restrict__ q4g,
                 float* __restrict__ ctx4) {
    int b = blockIdx.x;
    __shared__ float ks[kT][256], vs[kT][256], q4[256];
    __shared__ float sc[4][kT], attnw[4][kT];
    int tid = threadIdx.x;
#pragma unroll
    for (int t = 0; t < kT; t++) {
        size_t base = ((size_t)(b * kT + t)) * (2 * kFD);
        ks[t][tid] = kv[base + tid];
        vs[t][tid] = kv[base + kFD + tid];
    }
    q4[tid] = q4g[(size_t)b * kFD + tid];
    __syncthreads();
    int warp = tid >> 5, lane = tid & 31;
    for (int p = warp; p < 4 * kT; p += 8) {
        int h = p / kT, kt = p % kT;
        float s = 0.f;
        for (int d = lane; d < 64; d += 32) s += q4[h * 64 + d] * ks[kt][h * 64 + d];
#pragma unroll
        for (int m = 16; m; m >>= 1) s += __shfl_xor_sync(0xffffffffu, s, m);
        if (lane == 0) sc[h][kt] = s * 0.125f;
    }
    __syncthreads();
    if (tid < 32) {
        int h = tid & 3;
        float mx = -1e30f;
#pragma unroll
        for (int kt = 0; kt < kT; kt++) mx = fmaxf(mx, sc[h][kt]);
        float e[kT], sum = 0.f;
#pragma unroll
        for (int kt = 0; kt < kT; kt++) { e[kt] = __expf(sc[h][kt] - mx); sum += e[kt]; }
        if (tid < 4)
#pragma unroll
            for (int kt = 0; kt < kT; kt++) attnw[h][kt] = e[kt] / sum;
    }
    __syncthreads();
    int h = tid >> 6;
    float acc = 0.f;
#pragma unroll
    for (int kt = 0; kt < kT; kt++) acc += attnw[h][kt] * vs[kt][tid];
    ctx4[(size_t)b * kFD + tid] = acc;
}

// ===================================================================
// 32x128 tile GEMM body (small-M tails, unchanged)
// ===================================================================
__device__ __forceinline__
void tile32_body(const float* __restrict__ A, int lda, const float* __restrict__ W,
                 const float* __restrict__ bias, float* __restrict__ C, int ldc,
                 int K, int Nc, int row0, int col0, float* As, float* Bs) {
    int tid = threadIdx.x;
    int tx = tid & 31, ty = tid >> 5;
    float acc[4][4];
#pragma unroll
    for (int i = 0; i < 4; i++)
#pragma unroll
        for (int j = 0; j < 4; j++) acc[i][j] = 0.f;
    for (int k0 = 0; k0 < K; k0 += 16) {
        if (tid < 128) {
            int r = tid >> 2, kq = (tid & 3) * 4;
            float4 v = *(const float4*)&A[(size_t)(row0 + r) * lda + k0 + kq];
            As[(kq + 0) * 32 + r] = v.x; As[(kq + 1) * 32 + r] = v.y;
            As[(kq + 2) * 32 + r] = v.z; As[(kq + 3) * 32 + r] = v.w;
        }
#pragma unroll
        for (int i = 0; i < 2; i++) {
            int f = tid + i * 256;
            int r = f >> 2, kq = (f & 3) * 4;
            int col = col0 + r;
            float4 v = make_float4(0.f, 0.f, 0.f, 0.f);
            if (col < Nc) v = *(const float4*)&W[(size_t)col * K + k0 + kq];
            Bs[(kq + 0) * 128 + r] = v.x; Bs[(kq + 1) * 128 + r] = v.y;
            Bs[(kq + 2) * 128 + r] = v.z; Bs[(kq + 3) * 128 + r] = v.w;
        }
        __syncthreads();
#pragma unroll
        for (int k = 0; k < 16; k++) {
            float4 a4 = *(const float4*)&As[k * 32 + ty * 4];
            float4 b4 = *(const float4*)&Bs[k * 128 + tx * 4];
            float av[4] = {a4.x, a4.y, a4.z, a4.w};
            float bv[4] = {b4.x, b4.y, b4.z, b4.w};
#pragma unroll
            for (int i = 0; i < 4; i++)
#pragma unroll
                for (int j = 0; j < 4; j++) acc[i][j] += av[i] * bv[j];
        }
        __syncthreads();
    }
#pragma unroll
    for (int i = 0; i < 4; i++) {
        int r = row0 + ty * 4 + i;
#pragma unroll
        for (int j = 0; j < 4; j++) {
            int c = col0 + tx * 4 + j;
            if (c < Nc) C[(size_t)r * ldc + c] = acc[i][j] + bias[c];
        }
    }
}

__global__ __launch_bounds__(256)
void tile32_gemm(const float* __restrict__ A, const float* __restrict__ W,
                 const float* __restrict__ bias, float* __restrict__ C,
                 int lda, int ldc, int K, int Nc) {
    __shared__ float As[16 * 32], Bs[16 * 128];
    tile32_body(A, lda, W, bias, C, ldc, K, Nc, blockIdx.x * 32, blockIdx.y * 128, As, Bs);
}

__global__ __launch_bounds__(256)
void heads_gemm(const float* __restrict__ feat,
                const float* __restrict__ wmean, const float* __restrict__ bmean,
                const float* __restrict__ wlogv, const float* __restrict__ blogv,
                const float* __restrict__ wbel,  const float* __restrict__ bbel,
                float* __restrict__ out, float* __restrict__ blog) {
    __shared__ float As[16 * 32], Bs[16 * 128];
    int row0 = blockIdx.x * 32;
    if (blockIdx.y == 0) {
        tile32_body(feat, kFD, wmean, bmean, out, kLAT, kFD, kLAT, row0, 0, As, Bs);
        return;
    }
    if (blockIdx.y == 1) {
        tile32_body(feat, kFD, wlogv, blogv, out + (size_t)kB * kLAT, kLAT, kFD, kLAT,
                    row0, 0, As, Bs);
        return;
    }
    tile32_body(feat, kFD, wbel, bbel, blog, kS, kFD, kS, row0, 0, As, Bs);
    __syncthreads();
    int tid = threadIdx.x;
    int r = tid >> 3, q = tid & 7;
    float v[8];
    float mx = -1e30f;
#pragma unroll
    for (int j = 0; j < 8; j++) {
        v[j] = blog[(size_t)(row0 + r) * kS + q * 8 + j];
        mx = fmaxf(mx, v[j]);
    }
#pragma unroll
    for (int m = 4; m; m >>= 1) mx = fmaxf(mx, __shfl_xor_sync(0xffffffffu, mx, m));
    float sum = 0.f;
#pragma unroll
    for (int j = 0; j < 8; j++) { v[j] = __expf(v[j] - mx); sum += v[j]; }
#pragma unroll
    for (int m = 4; m; m >>= 1) sum += __shfl_xor_sync(0xffffffffu, sum, m);
    float inv = 1.f / sum;
    float* ob = out + (size_t)2 * kB * kLAT;
#pragma unroll
    for (int j = 0; j < 8; j++)
        ob[(size_t)(row0 + r) * kS + q * 8 + j] = v[j] * inv;
}

// ===================================================================
extern "C" void kernel_launch(void* const* d_in, const int* in_sizes, int n_in,
                              void* d_out, int out_size) {
    const float* signals = (const float*)d_in[0];
    const float* nact    = (const float*)d_in[1];
    const float* w0      = (const float*)d_in[2];
    const float* asrc0   = (const float*)d_in[3];
    const float* adst0   = (const float*)d_in[4];
    const float* bias0   = (const float*)d_in[5];
    const float* w1      = (const float*)d_in[6];
    const float* asrc1   = (const float*)d_in[7];
    const float* adst1   = (const float*)d_in[8];
    const float* bias1   = (const float*)d_in[9];
    const float* inw     = (const float*)d_in[10];
    const float* inb     = (const float*)d_in[11];
    const float* outw    = (const float*)d_in[12];
    const float* outb    = (const float*)d_in[13];
    const float* wmean   = (const float*)d_in[14];
    const float* bmean   = (const float*)d_in[15];
    const float* wlogv   = (const float*)d_in[16];
    const float* blogv   = (const float*)d_in[17];
    const float* wbel    = (const float*)d_in[18];
    const float* bbel    = (const float*)d_in[19];
    float* out = (float*)d_out;

    float *y, *seq, *kv, *q4, *ctx4, *feat, *blg, *v1, *w0t;
    cudaGetSymbolAddress((void**)&y,    g_y);
    cudaGetSymbolAddress((void**)&seq,  g_seq);
    cudaGetSymbolAddress((void**)&kv,   g_kv);
    cudaGetSymbolAddress((void**)&q4,   g_q4);
    cudaGetSymbolAddress((void**)&ctx4, g_ctx4);
    cudaGetSymbolAddress((void**)&feat, g_feat);
    cudaGetSymbolAddress((void**)&blg,  g_blog);
    cudaGetSymbolAddress((void**)&v1,   g_v1);
    cudaGetSymbolAddress((void**)&w0t,  g_w0t);

    // 1. prep
    prep_kernel<<<88, 256>>>(w1, asrc1, adst1, w0, v1, w0t);
    // 2. GNN phase 1 -> y
    gnn_phase1<<<kT * kB, 256>>>(signals, nact, w0, w0t, asrc0, adst0, bias0, v1, y);
    // 3. layer-1 projection (tf32 tensor cores) -> seq
    proj_tf32<<<dim3(kB * kT / 128, 4), 256>>>(y, w1, bias1, seq);
    // 4. q + kv projection (tf32 tensor cores)
    qkv_tf32<<<dim3(kB * kT / 128, 9), 256>>>(seq, inw, inb, kv, q4);
    // 5. attention
    attn_kernel<<<kB, 256>>>(kv, q4, ctx4);
    // 6. out_proj
    tile32_gemm<<<dim3(kB / 32, 2), 256>>>(ctx4, outw, outb, feat, kFD, kFD, kFD, kFD);
    // 7. heads
    heads_gemm<<<dim3(kB / 32, 3), 256>>>(feat, wmean, bmean, wlogv, blogv, wbel, bbel,
                                          out, blg);
}

// round 9
// speedup vs baseline: 3.5168x; 1.3244x over previous
#include <cuda_runtime.h>
#include <math.h>

static constexpr int kT = 5, kB = 512, kNA = 16, kS = 64, kA = 16;
static constexpr int kHID = 64, kH = 4, kFD = 256, kLAT = 128;
static constexpr int kN = kB * kNA;
static constexpr int kFIN = 80;

// -------- scratch (static device globals) --------
__device__ float g_y   [(size_t)kB * kT * 4 * kFD];
__device__ float g_seq [(size_t)kB * kT * kFD];
__device__ float g_kv  [(size_t)kB * kT * 2 * kFD];
__device__ float g_q4  [(size_t)kB * kFD];
__device__ float g_ctx4[(size_t)kB * kFD];
__device__ float g_feat[(size_t)kB * kFD];
__device__ float g_blog[(size_t)kB * kS];
__device__ float g_v1  [2 * 4 * kFD];     // vsrc1 | vdst1 (layer-1, FD-space)
__device__ float g_u0  [2 * 4 * kFIN];    // usrc0 | udst0 (layer-0, input-space)
__device__ float g_w0t [kFIN * kFD];      // w0^T

// ===================================================================
// Prep: v1 + w0t + u0. grid = 91.
// ===================================================================
__global__ __launch_bounds__(256)
void prep_kernel(const float* __restrict__ w1, const float* __restrict__ asrc1,
                 const float* __restrict__ adst1, const float* __restrict__ w0,
                 const float* __restrict__ asrc0, const float* __restrict__ adst0,
                 float* __restrict__ v1, float* __restrict__ w0t,
                 float* __restrict__ u0) {
    int bid = blockIdx.x, tid = threadIdx.x;
    if (bid < 8) {
        int idx = bid * 256 + tid;
        int which = idx >> 10;
        int h = (idx >> 8) & 3;
        int k = idx & 255;
        const float* a = which ? adst1 : asrc1;
        float acc = 0.f;
#pragma unroll
        for (int c = 0; c < 64; c++)
            acc += a[h * 64 + c] * w1[(size_t)(h * 64 + c) * kFD + k];
        v1[which * 1024 + h * 256 + k] = acc;
        return;
    }
    if (bid < 88) {
        int c = bid - 8;
        w0t[(size_t)c * kFD + tid] = w0[(size_t)tid * kFIN + c];
        return;
    }
    // u0: [which*320 + h*80 + f] = sum_c a0[h*64+c] * w0[(h*64+c)*80 + f]
    int idx = (bid - 88) * 256 + tid;
    if (idx >= 640) return;
    int which = idx / 320;
    int r = idx % 320;
    int h = r / 80, f = r % 80;
    const float* a = which ? adst0 : asrc0;
    float acc = 0.f;
#pragma unroll
    for (int c = 0; c < 64; c++)
        acc += a[h * 64 + c] * w0[(size_t)(h * 64 + c) * kFIN + f];
    u0[idx] = acc;
}

// ===================================================================
// GNN phase 1 (restructured): one block per (t, g). 2560 blocks.
// Input-space scores via u0; thread-serial softmaxes (no shuffle chains);
// xl0 never materialized (beta/gamma aggregation).
// ===================================================================
__global__ __launch_bounds__(256)
void gnn_phase1(const float* __restrict__ signals, const float* __restrict__ nact,
                const float* __restrict__ w0t, const float* __restrict__ u0,
                const float* __restrict__ bias0, const float* __restrict__ v1,
                float* __restrict__ y) {
    __shared__ float acts[16][16];
    __shared__ float sig[64];
    __shared__ float us[320], ud[320];
    __shared__ float sigproj[256];
    __shared__ float es0[16][4], ed0[16][4];
    __shared__ float alpha0[16][16][4];   // [n][j][h]
    __shared__ float beta[16][4][16];     // [n][h][k]
    __shared__ float gam[16][4];
    __shared__ float x1s[16][256];
    __shared__ float vs1[4][256], vd1[4][256];
    __shared__ float es1[16][4], ed1s[4], alpha1[16][4];

    int bid = blockIdx.x;
    int t = bid >> 9;
    int g = bid & 511;
    int tid = threadIdx.x;

    // per-thread weights (coalesced via w0t rows 64..79)
    float Wa[16];
#pragma unroll
    for (int k = 0; k < 16; k++) Wa[k] = w0t[(size_t)(64 + k) * kFD + tid];
    float b0 = bias0[tid];

    // phase 1: loads
    acts[tid >> 4][tid & 15] = nact[((size_t)t * kB + g) * (kNA * kA) + tid];
    if (tid < 64) sig[tid] = signals[((size_t)t * kB + g) * kS + tid];
#pragma unroll
    for (int i = 0; i < 2; i++) {
        int f = tid + i * 256;
        if (f < 320) { us[f] = u0[f]; ud[f] = u0[320 + f]; }
    }
#pragma unroll
    for (int h = 0; h < 4; h++) {
        vs1[h][tid] = v1[h * 256 + tid];
        vd1[h][tid] = v1[1024 + h * 256 + tid];
    }
    __syncthreads();

    // phase 2: sigproj (all threads) + es0/ed0 (threads < 128)
    {
        float acc = 0.f;
#pragma unroll
        for (int c = 0; c < 64; c++) acc += sig[c] * w0t[(size_t)c * kFD + tid];
        sigproj[tid] = acc;
    }
    if (tid < 128) {
        int which = tid >> 6;
        int p = tid & 63;
        int j = p >> 2, h = p & 3;
        const float* u = which ? ud : us;
        float e = 0.f;
#pragma unroll
        for (int k = 0; k < 16; k++) e += acts[j][k] * u[h * 80 + 64 + k];
        if (j == 0) {
#pragma unroll
            for (int c = 0; c < 64; c++) e += sig[c] * u[h * 80 + c];
        }
        if (which) ed0[j][h] = e; else es0[j][h] = e;
    }
    __syncthreads();

    // phase 3: softmax0, thread-serial, one thread per (n,h)
    if (tid < 64) {
        int n = tid >> 2, h = tid & 3;
        float base = ed0[n][h];
        float ev[16];
        float mx = -1e30f;
#pragma unroll
        for (int j = 0; j < 16; j++) {
            float e = es0[j][h] + base;
            e = e > 0.f ? e : 0.2f * e;
            ev[j] = e;
            mx = fmaxf(mx, e);
        }
        float sum = 0.f;
#pragma unroll
        for (int j = 0; j < 16; j++) { ev[j] = __expf(ev[j] - mx); sum += ev[j]; }
        float inv = 1.f / sum;
#pragma unroll
        for (int j = 0; j < 16; j++) alpha0[n][j][h] = ev[j] * inv;
    }
    __syncthreads();

    // phase 4: beta[n][h][k] = sum_j alpha0[n][j][h] * acts[j][k]; gam = alpha0[n][0][h]
    {
        int n = tid >> 4, h = (tid >> 2) & 3, kg = tid & 3;
        float bacc[4] = {0.f, 0.f, 0.f, 0.f};
#pragma unroll
        for (int j = 0; j < 16; j++) {
            float a = alpha0[n][j][h];
#pragma unroll
            for (int kk = 0; kk < 4; kk++) bacc[kk] += a * acts[j][kg * 4 + kk];
        }
#pragma unroll
        for (int kk = 0; kk < 4; kk++) beta[n][h][kg * 4 + kk] = bacc[kk];
        if (kg == 0) gam[n][h] = alpha0[n][0][h];
    }
    __syncthreads();

    // phase 5: x1[n][tid] = relu(beta[n][h]·Wa + gam·sigproj + b0)
    int hd = tid >> 6;
    float x1r[16];
    {
        float sp = sigproj[tid];
#pragma unroll
        for (int n = 0; n < 16; n++) {
            float acc = gam[n][hd] * sp;
#pragma unroll
            for (int k = 0; k < 16; k++) acc += beta[n][hd][k] * Wa[k];
            acc = fmaxf(acc + b0, 0.f);
            x1r[n] = acc;
            x1s[n][tid] = acc;
        }
    }
    __syncthreads();

    // phase 6: es1[j][h] = x1[j]·vs1[h]; ed1[h] = x1[0]·vd1[h]
    {
        int p = tid >> 2, q = tid & 3;
        int j = p >> 2, h = p & 3;
        float acc = 0.f;
#pragma unroll
        for (int c = q * 64; c < q * 64 + 64; c++) acc += x1s[j][c] * vs1[h][c];
        acc += __shfl_xor_sync(0xffffffffu, acc, 1);
        acc += __shfl_xor_sync(0xffffffffu, acc, 2);
        if (q == 0) es1[j][h] = acc;
    }
    if (tid < 32) {
        int h = tid >> 3, q = tid & 7;
        float acc = 0.f;
#pragma unroll
        for (int c = q * 32; c < q * 32 + 32; c++) acc += x1s[0][c] * vd1[h][c];
        acc += __shfl_xor_sync(0xffffffffu, acc, 1);
        acc += __shfl_xor_sync(0xffffffffu, acc, 2);
        acc += __shfl_xor_sync(0xffffffffu, acc, 4);
        if (q == 0) ed1s[h] = acc;
    }
    __syncthreads();

    // phase 7: softmax1, thread-serial, 4 threads
    if (tid < 4) {
        int h = tid;
        float base = ed1s[h];
        float ev[16];
        float mx = -1e30f;
#pragma unroll
        for (int j = 0; j < 16; j++) {
            float e = es1[j][h] + base;
            e = e > 0.f ? e : 0.2f * e;
            ev[j] = e;
            mx = fmaxf(mx, e);
        }
        float sum = 0.f;
#pragma unroll
        for (int j = 0; j < 16; j++) { ev[j] = __expf(ev[j] - mx); sum += ev[j]; }
        float inv = 1.f / sum;
#pragma unroll
        for (int j = 0; j < 16; j++) alpha1[j][h] = ev[j] * inv;
    }
    __syncthreads();

    // phase 8: y
#pragma unroll
    for (int h = 0; h < 4; h++) {
        float acc = 0.f;
#pragma unroll
        for (int j = 0; j < 16; j++) acc += alpha1[j][h] * x1r[j];
        y[(((size_t)g * kT + t) * 4 + h) * kFD + tid] = acc;
    }
}

// ===================================================================
// TF32 tensor-core GEMM tile: C[64 x 64] = A[64 x 256] @ W[64 x 256]^T
// 8 warps as 2(m)x4(n); warp tile 32x16 (2x2 mma tiles). K chunks of 16,
// double-buffered padded smem. K = 256 fixed.
// ===================================================================
__device__ __forceinline__ unsigned f2tf(float x) {
    unsigned u;
    asm("cvt.rna.tf32.f32 %0, %1;" : "=r"(u) : "f"(x));
    return u;
}

#define SA64(b,r,c) sA[(b)*(64*20) + (r)*20 + (c)]
#define SB64(b,r,c) sB[(b)*(64*20) + (r)*20 + (c)]

__device__ __forceinline__
void tf32_tile64(const float* __restrict__ A, int lda,
                 const float* __restrict__ Wt, const float* __restrict__ bias,
                 float* __restrict__ C, int ldc, int row0, int relu,
                 unsigned* sA, unsigned* sB) {
    int tid = threadIdx.x;
    int lane = tid & 31, warp = tid >> 5;
    int wm = warp & 1, wn = warp >> 1;
    int g4 = lane >> 2, l4 = lane & 3;
    int r = tid >> 2, c4 = tid & 3;

    float c[2][2][4];
#pragma unroll
    for (int mt = 0; mt < 2; mt++)
#pragma unroll
        for (int nt = 0; nt < 2; nt++)
#pragma unroll
            for (int i = 0; i < 4; i++) c[mt][nt][i] = 0.f;

    {   // initial chunk
        float4 v = *(const float4*)&A[(size_t)(row0 + r) * lda + c4 * 4];
        SA64(0, r, c4 * 4 + 0) = f2tf(v.x); SA64(0, r, c4 * 4 + 1) = f2tf(v.y);
        SA64(0, r, c4 * 4 + 2) = f2tf(v.z); SA64(0, r, c4 * 4 + 3) = f2tf(v.w);
        float4 w = *(const float4*)&Wt[(size_t)r * 256 + c4 * 4];
        SB64(0, r, c4 * 4 + 0) = f2tf(w.x); SB64(0, r, c4 * 4 + 1) = f2tf(w.y);
        SB64(0, r, c4 * 4 + 2) = f2tf(w.z); SB64(0, r, c4 * 4 + 3) = f2tf(w.w);
    }
    __syncthreads();

    for (int ch = 0; ch < 16; ch++) {
        int buf = ch & 1;
        float4 pa, pb;
        if (ch < 15) {
            int k0 = (ch + 1) * 16;
            pa = *(const float4*)&A[(size_t)(row0 + r) * lda + k0 + c4 * 4];
            pb = *(const float4*)&Wt[(size_t)r * 256 + k0 + c4 * 4];
        }
#pragma unroll
        for (int kk = 0; kk < 2; kk++) {
            unsigned af[2][4], bf[2][2];
#pragma unroll
            for (int mt = 0; mt < 2; mt++) {
                int ar = wm * 32 + mt * 16 + g4;
                int ac = kk * 8 + l4;
                af[mt][0] = SA64(buf, ar, ac);
                af[mt][1] = SA64(buf, ar + 8, ac);
                af[mt][2] = SA64(buf, ar, ac + 4);
                af[mt][3] = SA64(buf, ar + 8, ac + 4);
            }
#pragma unroll
            for (int nt = 0; nt < 2; nt++) {
                int br = wn * 16 + nt * 8 + g4;
                bf[nt][0] = SB64(buf, br, kk * 8 + l4);
                bf[nt][1] = SB64(buf, br, kk * 8 + l4 + 4);
            }
#pragma unroll
            for (int mt = 0; mt < 2; mt++)
#pragma unroll
                for (int nt = 0; nt < 2; nt++) {
                    asm volatile(
                        "mma.sync.aligned.m16n8k8.row.col.f32.tf32.tf32.f32 "
                        "{%0,%1,%2,%3}, {%4,%5,%6,%7}, {%8,%9}, {%0,%1,%2,%3};"
                        : "+f"(c[mt][nt][0]), "+f"(c[mt][nt][1]),
                          "+f"(c[mt][nt][2]), "+f"(c[mt][nt][3])
                        : "r"(af[mt][0]), "r"(af[mt][1]), "r"(af[mt][2]), "r"(af[mt][3]),
                          "r"(bf[nt][0]), "r"(bf[nt][1]));
                }
        }
        if (ch < 15) {
            int nb = buf ^ 1;
            SA64(nb, r, c4 * 4 + 0) = f2tf(pa.x); SA64(nb, r, c4 * 4 + 1) = f2tf(pa.y);
            SA64(nb, r, c4 * 4 + 2) = f2tf(pa.z); SA64(nb, r, c4 * 4 + 3) = f2tf(pa.w);
            SB64(nb, r, c4 * 4 + 0) = f2tf(pb.x); SB64(nb, r, c4 * 4 + 1) = f2tf(pb.y);
            SB64(nb, r, c4 * 4 + 2) = f2tf(pb.z); SB64(nb, r, c4 * 4 + 3) = f2tf(pb.w);
        }
        __syncthreads();
    }

#pragma unroll
    for (int mt = 0; mt < 2; mt++) {
        int rr = row0 + wm * 32 + mt * 16 + g4;
#pragma unroll
        for (int nt = 0; nt < 2; nt++) {
            int cc = wn * 16 + nt * 8 + 2 * l4;
            float b0v = bias[cc], b1v = bias[cc + 1];
            float v0 = c[mt][nt][0] + b0v, v1 = c[mt][nt][1] + b1v;
            float v2 = c[mt][nt][2] + b0v, v3 = c[mt][nt][3] + b1v;
            if (relu) {
                v0 = fmaxf(v0, 0.f); v1 = fmaxf(v1, 0.f);
                v2 = fmaxf(v2, 0.f); v3 = fmaxf(v3, 0.f);
            }
            C[(size_t)rr * ldc + cc] = v0;
            C[(size_t)rr * ldc + cc + 1] = v1;
            C[(size_t)(rr + 8) * ldc + cc] = v2;
            C[(size_t)(rr + 8) * ldc + cc + 1] = v3;
        }
    }
}

// layer-1 projection: grid (40, 4)
__global__ __launch_bounds__(256)
void proj_tf32(const float* __restrict__ y, const float* __restrict__ w1,
               const float* __restrict__ bias1, float* __restrict__ seq) {
    __shared__ unsigned sA[2 * 64 * 20], sB[2 * 64 * 20];
    int h = blockIdx.y;
    tf32_tile64(y + h * kFD, 4 * kFD,
                w1 + (size_t)h * 64 * kFD, bias1 + h * 64,
                seq + h * 64, kFD, blockIdx.x * 64, 1, sA, sB);
}

// q+kv projection: grid (40, 9). by<8: kv col tile; by==8: q (32 blocks).
__global__ __launch_bounds__(256)
void qkv_tf32(const float* __restrict__ seq, const float* __restrict__ inw,
              const float* __restrict__ inb, float* __restrict__ kv,
              float* __restrict__ q4) {
    __shared__ unsigned sA[2 * 64 * 20], sB[2 * 64 * 20];
    int by = blockIdx.y, bx = blockIdx.x;
    if (by < 8) {
        tf32_tile64(seq, kFD,
                    inw + (size_t)(256 + by * 64) * kFD, inb + 256 + by * 64,
                    kv + by * 64, 2 * kFD, bx * 64, 0, sA, sB);
    } else {
        if (bx >= 32) return;
        int rt = bx & 7, ct = bx >> 3;
        tf32_tile64(seq + 4 * kFD, kT * kFD,
                    inw + (size_t)ct * 64 * kFD, inb + ct * 64,
                    q4 + ct * 64, kFD, rt * 64, 0, sA, sB);
    }
}

// ===================================================================
// Attention (unchanged)
// ===================================================================
__global__ __launch_bounds__(256)
void attn_kernel(const float* __restrict__ kv, const float* __restrict__ q4g,
                 float* __restrict__ ctx4) {
    int b = blockIdx.x;
    __shared__ float ks[kT][256], vs[kT][256], q4[256];
    __shared__ float sc[4][kT], attnw[4][kT];
    int tid = threadIdx.x;
#pragma unroll
    for (int t = 0; t < kT; t++) {
        size_t base = ((size_t)(b * kT + t)) * (2 * kFD);
        ks[t][tid] = kv[base + tid];
        vs[t][tid] = kv[base + kFD + tid];
    }
    q4[tid] = q4g[(size_t)b * kFD + tid];
    __syncthreads();
    int warp = tid >> 5, lane = tid & 31;
    for (int p = warp; p < 4 * kT; p += 8) {
        int h = p / kT, kt = p % kT;
        float s = 0.f;
        for (int d = lane; d < 64; d += 32) s += q4[h * 64 + d] * ks[kt][h * 64 + d];
#pragma unroll
        for (int m = 16; m; m >>= 1) s += __shfl_xor_sync(0xffffffffu, s, m);
        if (lane == 0) sc[h][kt] = s * 0.125f;
    }
    __syncthreads();
    if (tid < 4) {
        int h = tid;
        float mx = -1e30f;
#pragma unroll
        for (int kt = 0; kt < kT; kt++) mx = fmaxf(mx, sc[h][kt]);
        float e[kT], sum = 0.f;
#pragma unroll
        for (int kt = 0; kt < kT; kt++) { e[kt] = __expf(sc[h][kt] - mx); sum += e[kt]; }
#pragma unroll
        for (int kt = 0; kt < kT; kt++) attnw[h][kt] = e[kt] / sum;
    }
    __syncthreads();
    int h = tid >> 6;
    float acc = 0.f;
#pragma unroll
    for (int kt = 0; kt < kT; kt++) acc += attnw[h][kt] * vs[kt][tid];
    ctx4[(size_t)b * kFD + tid] = acc;
}

// ===================================================================
// 32x128 tile GEMM body (small-M tails, unchanged)
// ===================================================================
__device__ __forceinline__
void tile32_body(const float* __restrict__ A, int lda, const float* __restrict__ W,
                 const float* __restrict__ bias, float* __restrict__ C, int ldc,
                 int K, int Nc, int row0, int col0, float* As, float* Bs) {
    int tid = threadIdx.x;
    int tx = tid & 31, ty = tid >> 5;
    float acc[4][4];
#pragma unroll
    for (int i = 0; i < 4; i++)
#pragma unroll
        for (int j = 0; j < 4; j++) acc[i][j] = 0.f;
    for (int k0 = 0; k0 < K; k0 += 16) {
        if (tid < 128) {
            int r = tid >> 2, kq = (tid & 3) * 4;
            float4 v = *(const float4*)&A[(size_t)(row0 + r) * lda + k0 + kq];
            As[(kq + 0) * 32 + r] = v.x; As[(kq + 1) * 32 + r] = v.y;
            As[(kq + 2) * 32 + r] = v.z; As[(kq + 3) * 32 + r] = v.w;
        }
#pragma unroll
        for (int i = 0; i < 2; i++) {
            int f = tid + i * 256;
            int r = f >> 2, kq = (f & 3) * 4;
            int col = col0 + r;
            float4 v = make_float4(0.f, 0.f, 0.f, 0.f);
            if (col < Nc) v = *(const float4*)&W[(size_t)col * K + k0 + kq];
            Bs[(kq + 0) * 128 + r] = v.x; Bs[(kq + 1) * 128 + r] = v.y;
            Bs[(kq + 2) * 128 + r] = v.z; Bs[(kq + 3) * 128 + r] = v.w;
        }
        __syncthreads();
#pragma unroll
        for (int k = 0; k < 16; k++) {
            float4 a4 = *(const float4*)&As[k * 32 + ty * 4];
            float4 b4 = *(const float4*)&Bs[k * 128 + tx * 4];
            float av[4] = {a4.x, a4.y, a4.z, a4.w};
            float bv[4] = {b4.x, b4.y, b4.z, b4.w};
#pragma unroll
            for (int i = 0; i < 4; i++)
#pragma unroll
                for (int j = 0; j < 4; j++) acc[i][j] += av[i] * bv[j];
        }
        __syncthreads();
    }
#pragma unroll
    for (int i = 0; i < 4; i++) {
        int r = row0 + ty * 4 + i;
#pragma unroll
        for (int j = 0; j < 4; j++) {
            int c = col0 + tx * 4 + j;
            if (c < Nc) C[(size_t)r * ldc + c] = acc[i][j] + bias[c];
        }
    }
}

__global__ __launch_bounds__(256)
void tile32_gemm(const float* __restrict__ A, const float* __restrict__ W,
                 const float* __restrict__ bias, float* __restrict__ C,
                 int lda, int ldc, int K, int Nc) {
    __shared__ float As[16 * 32], Bs[16 * 128];
    tile32_body(A, lda, W, bias, C, ldc, K, Nc, blockIdx.x * 32, blockIdx.y * 128, As, Bs);
}

__global__ __launch_bounds__(256)
void heads_gemm(const float* __restrict__ feat,
                const float* __restrict__ wmean, const float* __restrict__ bmean,
                const float* __restrict__ wlogv, const float* __restrict__ blogv,
                const float* __restrict__ wbel,  const float* __restrict__ bbel,
                float* __restrict__ out, float* __restrict__ blog) {
    __shared__ float As[16 * 32], Bs[16 * 128];
    int row0 = blockIdx.x * 32;
    if (blockIdx.y == 0) {
        tile32_body(feat, kFD, wmean, bmean, out, kLAT, kFD, kLAT, row0, 0, As, Bs);
        return;
    }
    if (blockIdx.y == 1) {
        tile32_body(feat, kFD, wlogv, blogv, out + (size_t)kB * kLAT, kLAT, kFD, kLAT,
                    row0, 0, As, Bs);
        return;
    }
    tile32_body(feat, kFD, wbel, bbel, blog, kS, kFD, kS, row0, 0, As, Bs);
    __syncthreads();
    int tid = threadIdx.x;
    int r = tid >> 3, q = tid & 7;
    float v[8];
    float mx = -1e30f;
#pragma unroll
    for (int j = 0; j < 8; j++) {
        v[j] = blog[(size_t)(row0 + r) * kS + q * 8 + j];
        mx = fmaxf(mx, v[j]);
    }
#pragma unroll
    for (int m = 4; m; m >>= 1) mx = fmaxf(mx, __shfl_xor_sync(0xffffffffu, mx, m));
    float sum = 0.f;
#pragma unroll
    for (int j = 0; j < 8; j++) { v[j] = __expf(v[j] - mx); sum += v[j]; }
#pragma unroll
    for (int m = 4; m; m >>= 1) sum += __shfl_xor_sync(0xffffffffu, sum, m);
    float inv = 1.f / sum;
    float* ob = out + (size_t)2 * kB * kLAT;
#pragma unroll
    for (int j = 0; j < 8; j++)
        ob[(size_t)(row0 + r) * kS + q * 8 + j] = v[j] * inv;
}

// ===================================================================
extern "C" void kernel_launch(void* const* d_in, const int* in_sizes, int n_in,
                              void* d_out, int out_size) {
    const float* signals = (const float*)d_in[0];
    const float* nact    = (const float*)d_in[1];
    const float* w0      = (const float*)d_in[2];
    const float* asrc0   = (const float*)d_in[3];
    const float* adst0   = (const float*)d_in[4];
    const float* bias0   = (const float*)d_in[5];
    const float* w1      = (const float*)d_in[6];
    const float* asrc1   = (const float*)d_in[7];
    const float* adst1   = (const float*)d_in[8];
    const float* bias1   = (const float*)d_in[9];
    const float* inw     = (const float*)d_in[10];
    const float* inb     = (const float*)d_in[11];
    const float* outw    = (const float*)d_in[12];
    const float* outb    = (const float*)d_in[13];
    const float* wmean   = (const float*)d_in[14];
    const float* bmean   = (const float*)d_in[15];
    const float* wlogv   = (const float*)d_in[16];
    const float* blogv   = (const float*)d_in[17];
    const float* wbel    = (const float*)d_in[18];
    const float* bbel    = (const float*)d_in[19];
    float* out = (float*)d_out;

    float *y, *seq, *kv, *q4, *ctx4, *feat, *blg, *v1, *u0, *w0t;
    cudaGetSymbolAddress((void**)&y,    g_y);
    cudaGetSymbolAddress((void**)&seq,  g_seq);
    cudaGetSymbolAddress((void**)&kv,   g_kv);
    cudaGetSymbolAddress((void**)&q4,   g_q4);
    cudaGetSymbolAddress((void**)&ctx4, g_ctx4);
    cudaGetSymbolAddress((void**)&feat, g_feat);
    cudaGetSymbolAddress((void**)&blg,  g_blog);
    cudaGetSymbolAddress((void**)&v1,   g_v1);
    cudaGetSymbolAddress((void**)&u0,   g_u0);
    cudaGetSymbolAddress((void**)&w0t,  g_w0t);

    // 1. prep: v1 + w0t + u0
    prep_kernel<<<91, 256>>>(w1, asrc1, adst1, w0, asrc0, adst0, v1, w0t, u0);
    // 2. GNN phase 1 (restructured) -> y
    gnn_phase1<<<kT * kB, 256>>>(signals, nact, w0t, u0, bias0, v1, y);
    // 3. layer-1 projection (tf32, 64x64 tiles) -> seq
    proj_tf32<<<dim3(kB * kT / 64, 4), 256>>>(y, w1, bias1, seq);
    // 4. q + kv projection (tf32, 64x64 tiles)
    qkv_tf32<<<dim3(kB * kT / 64, 9), 256>>>(seq, inw, inb, kv, q4);
    // 5. attention
    attn_kernel<<<kB, 256>>>(kv, q4, ctx4);
    // 6. out_proj
    tile32_gemm<<<dim3(kB / 32, 2), 256>>>(ctx4, outw, outb, feat, kFD, kFD, kFD, kFD);
    // 7. heads
    heads_gemm<<<dim3(kB / 32, 3), 256>>>(feat, wmean, bmean, wlogv, blogv, wbel, bbel,
                                          out, blg);
}

// round 10
// speedup vs baseline: 3.8340x; 1.0902x over previous
#include <cuda_runtime.h>
#include <math.h>

static constexpr int kT = 5, kB = 512, kNA = 16, kS = 64, kA = 16;
static constexpr int kHID = 64, kH = 4, kFD = 256, kLAT = 128;
static constexpr int kN = kB * kNA;
static constexpr int kFIN = 80;

// -------- scratch (static device globals) --------
__device__ float g_y   [(size_t)kB * kT * 4 * kFD];
__device__ float g_seq [(size_t)kB * kT * kFD];
__device__ float g_kv  [(size_t)kB * kT * 2 * kFD];
__device__ float g_q4  [(size_t)kB * kFD];
__device__ float g_ctx4[(size_t)kB * kFD];
__device__ float g_feat[(size_t)kB * kFD];
__device__ float g_blog[(size_t)kB * kS];
__device__ float g_v1  [2 * 4 * kFD];
__device__ float g_u0  [2 * 4 * kFIN];
__device__ float g_w0t [kFIN * kFD];

// ===================================================================
// Prep: v1 + w0t + u0. grid = 91.
// ===================================================================
__global__ __launch_bounds__(256)
void prep_kernel(const float* __restrict__ w1, const float* __restrict__ asrc1,
                 const float* __restrict__ adst1, const float* __restrict__ w0,
                 const float* __restrict__ asrc0, const float* __restrict__ adst0,
                 float* __restrict__ v1, float* __restrict__ w0t,
                 float* __restrict__ u0) {
    int bid = blockIdx.x, tid = threadIdx.x;
    if (bid < 8) {
        int idx = bid * 256 + tid;
        int which = idx >> 10;
        int h = (idx >> 8) & 3;
        int k = idx & 255;
        const float* a = which ? adst1 : asrc1;
        float acc = 0.f;
#pragma unroll
        for (int c = 0; c < 64; c++)
            acc += a[h * 64 + c] * w1[(size_t)(h * 64 + c) * kFD + k];
        v1[which * 1024 + h * 256 + k] = acc;
        return;
    }
    if (bid < 88) {
        int c = bid - 8;
        w0t[(size_t)c * kFD + tid] = w0[(size_t)tid * kFIN + c];
        return;
    }
    int idx = (bid - 88) * 256 + tid;
    if (idx >= 640) return;
    int which = idx / 320;
    int r = idx % 320;
    int h = r / 80, f = r % 80;
    const float* a = which ? adst0 : asrc0;
    float acc = 0.f;
#pragma unroll
    for (int c = 0; c < 64; c++)
        acc += a[h * 64 + c] * w0[(size_t)(h * 64 + c) * kFIN + f];
    u0[idx] = acc;
}

// ===================================================================
// GNN phase 1 (R9, unchanged): one block per (t, g). 2560 blocks.
// ===================================================================
__global__ __launch_bounds__(256)
void gnn_phase1(const float* __restrict__ signals, const float* __restrict__ nact,
                const float* __restrict__ w0t, const float* __restrict__ u0,
                const float* __restrict__ bias0, const float* __restrict__ v1,
                float* __restrict__ y) {
    __shared__ float acts[16][16];
    __shared__ float sig[64];
    __shared__ float us[320], ud[320];
    __shared__ float sigproj[256];
    __shared__ float es0[16][4], ed0[16][4];
    __shared__ float alpha0[16][16][4];
    __shared__ float beta[16][4][16];
    __shared__ float gam[16][4];
    __shared__ float x1s[16][256];
    __shared__ float vs1[4][256], vd1[4][256];
    __shared__ float es1[16][4], ed1s[4], alpha1[16][4];

    int bid = blockIdx.x;
    int t = bid >> 9;
    int g = bid & 511;
    int tid = threadIdx.x;

    float Wa[16];
#pragma unroll
    for (int k = 0; k < 16; k++) Wa[k] = w0t[(size_t)(64 + k) * kFD + tid];
    float b0 = bias0[tid];

    acts[tid >> 4][tid & 15] = nact[((size_t)t * kB + g) * (kNA * kA) + tid];
    if (tid < 64) sig[tid] = signals[((size_t)t * kB + g) * kS + tid];
#pragma unroll
    for (int i = 0; i < 2; i++) {
        int f = tid + i * 256;
        if (f < 320) { us[f] = u0[f]; ud[f] = u0[320 + f]; }
    }
#pragma unroll
    for (int h = 0; h < 4; h++) {
        vs1[h][tid] = v1[h * 256 + tid];
        vd1[h][tid] = v1[1024 + h * 256 + tid];
    }
    __syncthreads();

    {
        float acc = 0.f;
#pragma unroll
        for (int c = 0; c < 64; c++) acc += sig[c] * w0t[(size_t)c * kFD + tid];
        sigproj[tid] = acc;
    }
    if (tid < 128) {
        int which = tid >> 6;
        int p = tid & 63;
        int j = p >> 2, h = p & 3;
        const float* u = which ? ud : us;
        float e = 0.f;
#pragma unroll
        for (int k = 0; k < 16; k++) e += acts[j][k] * u[h * 80 + 64 + k];
        if (j == 0) {
#pragma unroll
            for (int c = 0; c < 64; c++) e += sig[c] * u[h * 80 + c];
        }
        if (which) ed0[j][h] = e; else es0[j][h] = e;
    }
    __syncthreads();

    if (tid < 64) {
        int n = tid >> 2, h = tid & 3;
        float base = ed0[n][h];
        float ev[16];
        float mx = -1e30f;
#pragma unroll
        for (int j = 0; j < 16; j++) {
            float e = es0[j][h] + base;
            e = e > 0.f ? e : 0.2f * e;
            ev[j] = e;
            mx = fmaxf(mx, e);
        }
        float sum = 0.f;
#pragma unroll
        for (int j = 0; j < 16; j++) { ev[j] = __expf(ev[j] - mx); sum += ev[j]; }
        float inv = 1.f / sum;
#pragma unroll
        for (int j = 0; j < 16; j++) alpha0[n][j][h] = ev[j] * inv;
    }
    __syncthreads();

    {
        int n = tid >> 4, h = (tid >> 2) & 3, kg = tid & 3;
        float bacc[4] = {0.f, 0.f, 0.f, 0.f};
#pragma unroll
        for (int j = 0; j < 16; j++) {
            float a = alpha0[n][j][h];
#pragma unroll
            for (int kk = 0; kk < 4; kk++) bacc[kk] += a * acts[j][kg * 4 + kk];
        }
#pragma unroll
        for (int kk = 0; kk < 4; kk++) beta[n][h][kg * 4 + kk] = bacc[kk];
        if (kg == 0) gam[n][h] = alpha0[n][0][h];
    }
    __syncthreads();

    int hd = tid >> 6;
    float x1r[16];
    {
        float sp = sigproj[tid];
#pragma unroll
        for (int n = 0; n < 16; n++) {
            float acc = gam[n][hd] * sp;
#pragma unroll
            for (int k = 0; k < 16; k++) acc += beta[n][hd][k] * Wa[k];
            acc = fmaxf(acc + b0, 0.f);
            x1r[n] = acc;
            x1s[n][tid] = acc;
        }
    }
    __syncthreads();

    {
        int p = tid >> 2, q = tid & 3;
        int j = p >> 2, h = p & 3;
        float acc = 0.f;
#pragma unroll
        for (int c = q * 64; c < q * 64 + 64; c++) acc += x1s[j][c] * vs1[h][c];
        acc += __shfl_xor_sync(0xffffffffu, acc, 1);
        acc += __shfl_xor_sync(0xffffffffu, acc, 2);
        if (q == 0) es1[j][h] = acc;
    }
    if (tid < 32) {
        int h = tid >> 3, q = tid & 7;
        float acc = 0.f;
#pragma unroll
        for (int c = q * 32; c < q * 32 + 32; c++) acc += x1s[0][c] * vd1[h][c];
        acc += __shfl_xor_sync(0xffffffffu, acc, 1);
        acc += __shfl_xor_sync(0xffffffffu, acc, 2);
        acc += __shfl_xor_sync(0xffffffffu, acc, 4);
        if (q == 0) ed1s[h] = acc;
    }
    __syncthreads();

    if (tid < 4) {
        int h = tid;
        float base = ed1s[h];
        float ev[16];
        float mx = -1e30f;
#pragma unroll
        for (int j = 0; j < 16; j++) {
            float e = es1[j][h] + base;
            e = e > 0.f ? e : 0.2f * e;
            ev[j] = e;
            mx = fmaxf(mx, e);
        }
        float sum = 0.f;
#pragma unroll
        for (int j = 0; j < 16; j++) { ev[j] = __expf(ev[j] - mx); sum += ev[j]; }
        float inv = 1.f / sum;
#pragma unroll
        for (int j = 0; j < 16; j++) alpha1[j][h] = ev[j] * inv;
    }
    __syncthreads();

#pragma unroll
    for (int h = 0; h < 4; h++) {
        float acc = 0.f;
#pragma unroll
        for (int j = 0; j < 16; j++) acc += alpha1[j][h] * x1r[j];
        y[(((size_t)g * kT + t) * 4 + h) * kFD + tid] = acc;
    }
}

// ===================================================================
// TF32 mma helpers
// ===================================================================
__device__ __forceinline__ unsigned f2tf(float x) {
    unsigned u;
    asm("cvt.rna.tf32.f32 %0, %1;" : "=r"(u) : "f"(x));
    return u;
}

// ---------------- 128x64 tile (R8 config: warps 4x2, warp tile 32x32) ----------
#define SA(b,r,c) sA[(b)*(128*20) + (r)*20 + (c)]
#define SB(b,r,c) sB[(b)*(64*20)  + (r)*20 + (c)]

__device__ __forceinline__
void tf32_tile128(const float* __restrict__ A, int lda,
                  const float* __restrict__ Wt, const float* __restrict__ bias,
                  float* __restrict__ C, int ldc, int row0, int relu,
                  unsigned* sA, unsigned* sB) {
    int tid = threadIdx.x;
    int lane = tid & 31, warp = tid >> 5;
    int wm = warp & 3, wn = warp >> 2;
    int g4 = lane >> 2, l4 = lane & 3;

    float c[2][4][4];
#pragma unroll
    for (int mt = 0; mt < 2; mt++)
#pragma unroll
        for (int nt = 0; nt < 4; nt++)
#pragma unroll
            for (int i = 0; i < 4; i++) c[mt][nt][i] = 0.f;

    {
#pragma unroll
        for (int i = 0; i < 2; i++) {
            int idx = tid + i * 256;
            int r = idx >> 2, c4 = idx & 3;
            float4 v = *(const float4*)&A[(size_t)(row0 + r) * lda + c4 * 4];
            SA(0, r, c4 * 4 + 0) = f2tf(v.x); SA(0, r, c4 * 4 + 1) = f2tf(v.y);
            SA(0, r, c4 * 4 + 2) = f2tf(v.z); SA(0, r, c4 * 4 + 3) = f2tf(v.w);
        }
        int r = tid >> 2, c4 = tid & 3;
        float4 w = *(const float4*)&Wt[(size_t)r * 256 + c4 * 4];
        SB(0, r, c4 * 4 + 0) = f2tf(w.x); SB(0, r, c4 * 4 + 1) = f2tf(w.y);
        SB(0, r, c4 * 4 + 2) = f2tf(w.z); SB(0, r, c4 * 4 + 3) = f2tf(w.w);
    }
    __syncthreads();

    for (int ch = 0; ch < 16; ch++) {
        int buf = ch & 1;
        float4 pa0, pa1, pb;
        if (ch < 15) {
            int k0 = (ch + 1) * 16;
            {
                int r = tid >> 2, c4 = tid & 3;
                pa0 = *(const float4*)&A[(size_t)(row0 + r) * lda + k0 + c4 * 4];
            }
            {
                int idx = tid + 256;
                int r = idx >> 2, c4 = idx & 3;
                pa1 = *(const float4*)&A[(size_t)(row0 + r) * lda + k0 + c4 * 4];
            }
            {
                int r = tid >> 2, c4 = tid & 3;
                pb = *(const float4*)&Wt[(size_t)r * 256 + k0 + c4 * 4];
            }
        }
#pragma unroll
        for (int kk = 0; kk < 2; kk++) {
            unsigned af[2][4], bf[4][2];
#pragma unroll
            for (int mt = 0; mt < 2; mt++) {
                int ar = wm * 32 + mt * 16 + g4;
                int ac = kk * 8 + l4;
                af[mt][0] = SA(buf, ar, ac);
                af[mt][1] = SA(buf, ar + 8, ac);
                af[mt][2] = SA(buf, ar, ac + 4);
                af[mt][3] = SA(buf, ar + 8, ac + 4);
            }
#pragma unroll
            for (int nt = 0; nt < 4; nt++) {
                int br = wn * 32 + nt * 8 + g4;
                bf[nt][0] = SB(buf, br, kk * 8 + l4);
                bf[nt][1] = SB(buf, br, kk * 8 + l4 + 4);
            }
#pragma unroll
            for (int mt = 0; mt < 2; mt++)
#pragma unroll
                for (int nt = 0; nt < 4; nt++) {
                    asm volatile(
                        "mma.sync.aligned.m16n8k8.row.col.f32.tf32.tf32.f32 "
                        "{%0,%1,%2,%3}, {%4,%5,%6,%7}, {%8,%9}, {%0,%1,%2,%3};"
                        : "+f"(c[mt][nt][0]), "+f"(c[mt][nt][1]),
                          "+f"(c[mt][nt][2]), "+f"(c[mt][nt][3])
                        : "r"(af[mt][0]), "r"(af[mt][1]), "r"(af[mt][2]), "r"(af[mt][3]),
                          "r"(bf[nt][0]), "r"(bf[nt][1]));
                }
        }
        if (ch < 15) {
            int nb = buf ^ 1;
            {
                int r = tid >> 2, c4 = tid & 3;
                SA(nb, r, c4 * 4 + 0) = f2tf(pa0.x); SA(nb, r, c4 * 4 + 1) = f2tf(pa0.y);
                SA(nb, r, c4 * 4 + 2) = f2tf(pa0.z); SA(nb, r, c4 * 4 + 3) = f2tf(pa0.w);
            }
            {
                int idx = tid + 256;
                int r = idx >> 2, c4 = idx & 3;
                SA(nb, r, c4 * 4 + 0) = f2tf(pa1.x); SA(nb, r, c4 * 4 + 1) = f2tf(pa1.y);
                SA(nb, r, c4 * 4 + 2) = f2tf(pa1.z); SA(nb, r, c4 * 4 + 3) = f2tf(pa1.w);
            }
            {
                int r = tid >> 2, c4 = tid & 3;
                SB(nb, r, c4 * 4 + 0) = f2tf(pb.x); SB(nb, r, c4 * 4 + 1) = f2tf(pb.y);
                SB(nb, r, c4 * 4 + 2) = f2tf(pb.z); SB(nb, r, c4 * 4 + 3) = f2tf(pb.w);
            }
        }
        __syncthreads();
    }

#pragma unroll
    for (int mt = 0; mt < 2; mt++) {
        int r = row0 + wm * 32 + mt * 16 + g4;
#pragma unroll
        for (int nt = 0; nt < 4; nt++) {
            int cc = wn * 32 + nt * 8 + 2 * l4;
            float b0v = bias[cc], b1v = bias[cc + 1];
            float v0 = c[mt][nt][0] + b0v, v1 = c[mt][nt][1] + b1v;
            float v2 = c[mt][nt][2] + b0v, v3 = c[mt][nt][3] + b1v;
            if (relu) {
                v0 = fmaxf(v0, 0.f); v1 = fmaxf(v1, 0.f);
                v2 = fmaxf(v2, 0.f); v3 = fmaxf(v3, 0.f);
            }
            C[(size_t)r * ldc + cc] = v0;
            C[(size_t)r * ldc + cc + 1] = v1;
            C[(size_t)(r + 8) * ldc + cc] = v2;
            C[(size_t)(r + 8) * ldc + cc + 1] = v3;
        }
    }
}

// ---------------- 64x64 tile (R9 config) ----------------
#define SA64(b,r,c) sA[(b)*(64*20) + (r)*20 + (c)]
#define SB64(b,r,c) sB[(b)*(64*20) + (r)*20 + (c)]

__device__ __forceinline__
void tf32_tile64(const float* __restrict__ A, int lda,
                 const float* __restrict__ Wt, const float* __restrict__ bias,
                 float* __restrict__ C, int ldc, int row0, int relu,
                 unsigned* sA, unsigned* sB) {
    int tid = threadIdx.x;
    int lane = tid & 31, warp = tid >> 5;
    int wm = warp & 1, wn = warp >> 1;
    int g4 = lane >> 2, l4 = lane & 3;
    int r = tid >> 2, c4 = tid & 3;

    float c[2][2][4];
#pragma unroll
    for (int mt = 0; mt < 2; mt++)
#pragma unroll
        for (int nt = 0; nt < 2; nt++)
#pragma unroll
            for (int i = 0; i < 4; i++) c[mt][nt][i] = 0.f;

    {
        float4 v = *(const float4*)&A[(size_t)(row0 + r) * lda + c4 * 4];
        SA64(0, r, c4 * 4 + 0) = f2tf(v.x); SA64(0, r, c4 * 4 + 1) = f2tf(v.y);
        SA64(0, r, c4 * 4 + 2) = f2tf(v.z); SA64(0, r, c4 * 4 + 3) = f2tf(v.w);
        float4 w = *(const float4*)&Wt[(size_t)r * 256 + c4 * 4];
        SB64(0, r, c4 * 4 + 0) = f2tf(w.x); SB64(0, r, c4 * 4 + 1) = f2tf(w.y);
        SB64(0, r, c4 * 4 + 2) = f2tf(w.z); SB64(0, r, c4 * 4 + 3) = f2tf(w.w);
    }
    __syncthreads();

    for (int ch = 0; ch < 16; ch++) {
        int buf = ch & 1;
        float4 pa, pb;
        if (ch < 15) {
            int k0 = (ch + 1) * 16;
            pa = *(const float4*)&A[(size_t)(row0 + r) * lda + k0 + c4 * 4];
            pb = *(const float4*)&Wt[(size_t)r * 256 + k0 + c4 * 4];
        }
#pragma unroll
        for (int kk = 0; kk < 2; kk++) {
            unsigned af[2][4], bf[2][2];
#pragma unroll
            for (int mt = 0; mt < 2; mt++) {
                int ar = wm * 32 + mt * 16 + g4;
                int ac = kk * 8 + l4;
                af[mt][0] = SA64(buf, ar, ac);
                af[mt][1] = SA64(buf, ar + 8, ac);
                af[mt][2] = SA64(buf, ar, ac + 4);
                af[mt][3] = SA64(buf, ar + 8, ac + 4);
            }
#pragma unroll
            for (int nt = 0; nt < 2; nt++) {
                int br = wn * 16 + nt * 8 + g4;
                bf[nt][0] = SB64(buf, br, kk * 8 + l4);
                bf[nt][1] = SB64(buf, br, kk * 8 + l4 + 4);
            }
#pragma unroll
            for (int mt = 0; mt < 2; mt++)
#pragma unroll
                for (int nt = 0; nt < 2; nt++) {
                    asm volatile(
                        "mma.sync.aligned.m16n8k8.row.col.f32.tf32.tf32.f32 "
                        "{%0,%1,%2,%3}, {%4,%5,%6,%7}, {%8,%9}, {%0,%1,%2,%3};"
                        : "+f"(c[mt][nt][0]), "+f"(c[mt][nt][1]),
                          "+f"(c[mt][nt][2]), "+f"(c[mt][nt][3])
                        : "r"(af[mt][0]), "r"(af[mt][1]), "r"(af[mt][2]), "r"(af[mt][3]),
                          "r"(bf[nt][0]), "r"(bf[nt][1]));
                }
        }
        if (ch < 15) {
            int nb = buf ^ 1;
            SA64(nb, r, c4 * 4 + 0) = f2tf(pa.x); SA64(nb, r, c4 * 4 + 1) = f2tf(pa.y);
            SA64(nb, r, c4 * 4 + 2) = f2tf(pa.z); SA64(nb, r, c4 * 4 + 3) = f2tf(pa.w);
            SB64(nb, r, c4 * 4 + 0) = f2tf(pb.x); SB64(nb, r, c4 * 4 + 1) = f2tf(pb.y);
            SB64(nb, r, c4 * 4 + 2) = f2tf(pb.z); SB64(nb, r, c4 * 4 + 3) = f2tf(pb.w);
        }
        __syncthreads();
    }

#pragma unroll
    for (int mt = 0; mt < 2; mt++) {
        int rr = row0 + wm * 32 + mt * 16 + g4;
#pragma unroll
        for (int nt = 0; nt < 2; nt++) {
            int cc = wn * 16 + nt * 8 + 2 * l4;
            float b0v = bias[cc], b1v = bias[cc + 1];
            float v0 = c[mt][nt][0] + b0v, v1 = c[mt][nt][1] + b1v;
            float v2 = c[mt][nt][2] + b0v, v3 = c[mt][nt][3] + b1v;
            if (relu) {
                v0 = fmaxf(v0, 0.f); v1 = fmaxf(v1, 0.f);
                v2 = fmaxf(v2, 0.f); v3 = fmaxf(v3, 0.f);
            }
            C[(size_t)rr * ldc + cc] = v0;
            C[(size_t)rr * ldc + cc + 1] = v1;
            C[(size_t)(rr + 8) * ldc + cc] = v2;
            C[(size_t)(rr + 8) * ldc + cc + 1] = v3;
        }
    }
}

// layer-1 projection: grid (20, 4)
__global__ __launch_bounds__(256)
void proj_tf32(const float* __restrict__ y, const float* __restrict__ w1,
               const float* __restrict__ bias1, float* __restrict__ seq) {
    __shared__ unsigned sA[2 * 128 * 20], sB[2 * 64 * 20];
    int h = blockIdx.y;
    tf32_tile128(y + h * kFD, 4 * kFD,
                 w1 + (size_t)h * 64 * kFD, bias1 + h * 64,
                 seq + h * 64, kFD, blockIdx.x * 128, 1, sA, sB);
}

// q+kv projection: grid (20, 9)
__global__ __launch_bounds__(256)
void qkv_tf32(const float* __restrict__ seq, const float* __restrict__ inw,
              const float* __restrict__ inb, float* __restrict__ kv,
              float* __restrict__ q4) {
    __shared__ unsigned sA[2 * 128 * 20], sB[2 * 64 * 20];
    int by = blockIdx.y, bx = blockIdx.x;
    if (by < 8) {
        tf32_tile128(seq, kFD,
                     inw + (size_t)(256 + by * 64) * kFD, inb + 256 + by * 64,
                     kv + by * 64, 2 * kFD, bx * 128, 0, sA, sB);
    } else {
        if (bx >= 16) return;
        int rt = bx & 3, ct = bx >> 2;
        tf32_tile128(seq + 4 * kFD, kT * kFD,
                     inw + (size_t)ct * 64 * kFD, inb + ct * 64,
                     q4 + ct * 64, kFD, rt * 128, 0, sA, sB);
    }
}

// out_proj: grid (8, 4)
__global__ __launch_bounds__(256)
void outproj_tf32(const float* __restrict__ ctx4, const float* __restrict__ outw,
                  const float* __restrict__ outb, float* __restrict__ feat) {
    __shared__ unsigned sA[2 * 64 * 20], sB[2 * 64 * 20];
    int ct = blockIdx.y;
    tf32_tile64(ctx4, kFD, outw + (size_t)ct * 64 * kFD, outb + ct * 64,
                feat + ct * 64, kFD, blockIdx.x * 64, 0, sA, sB);
}

// heads: grid (8, 5). by 0-1 mean tiles, 2-3 logvar, 4 belief (+softmax).
__global__ __launch_bounds__(256)
void heads_tf32(const float* __restrict__ feat,
                const float* __restrict__ wmean, const float* __restrict__ bmean,
                const float* __restrict__ wlogv, const float* __restrict__ blogv,
                const float* __restrict__ wbel,  const float* __restrict__ bbel,
                float* __restrict__ out, float* __restrict__ blog) {
    __shared__ unsigned sA[2 * 64 * 20], sB[2 * 64 * 20];
    int by = blockIdx.y;
    int row0 = blockIdx.x * 64;
    if (by < 2) {
        tf32_tile64(feat, kFD, wmean + (size_t)by * 64 * kFD, bmean + by * 64,
                    out + by * 64, kLAT, row0, 0, sA, sB);
        return;
    }
    if (by < 4) {
        int ct = by - 2;
        tf32_tile64(feat, kFD, wlogv + (size_t)ct * 64 * kFD, blogv + ct * 64,
                    out + (size_t)kB * kLAT + ct * 64, kLAT, row0, 0, sA, sB);
        return;
    }
    // belief logits (N=64 = full row) -> blog, then in-block softmax -> out
    tf32_tile64(feat, kFD, wbel, bbel, blog, kS, row0, 0, sA, sB);
    __syncthreads();   // own-block gmem writes visible within block
    int tid = threadIdx.x;
    int r = row0 + (tid >> 2);         // 64 rows, 4 threads/row
    int q = tid & 3;                   // 16 cols each
    float v[16];
    float mx = -1e30f;
#pragma unroll
    for (int i = 0; i < 4; i++) {
        float4 x = *(const float4*)&blog[(size_t)r * kS + q * 16 + i * 4];
        v[i * 4 + 0] = x.x; v[i * 4 + 1] = x.y; v[i * 4 + 2] = x.z; v[i * 4 + 3] = x.w;
        mx = fmaxf(fmaxf(fmaxf(mx, x.x), fmaxf(x.y, x.z)), x.w);
    }
    mx = fmaxf(mx, __shfl_xor_sync(0xffffffffu, mx, 1));
    mx = fmaxf(mx, __shfl_xor_sync(0xffffffffu, mx, 2));
    float sum = 0.f;
#pragma unroll
    for (int i = 0; i < 16; i++) { v[i] = __expf(v[i] - mx); sum += v[i]; }
    sum += __shfl_xor_sync(0xffffffffu, sum, 1);
    sum += __shfl_xor_sync(0xffffffffu, sum, 2);
    float inv = 1.f / sum;
    float* ob = out + (size_t)2 * kB * kLAT;
#pragma unroll
    for (int i = 0; i < 16; i++)
        ob[(size_t)r * kS + q * 16 + i] = v[i] * inv;
}

// ===================================================================
// Attention (unchanged)
// ===================================================================
__global__ __launch_bounds__(256)
void attn_kernel(const float* __restrict__ kv, const float* __restrict__ q4g,
                 float* __restrict__ ctx4) {
    int b = blockIdx.x;
    __shared__ float ks[kT][256], vs[kT][256], q4[256];
    __shared__ float sc[4][kT], attnw[4][kT];
    int tid = threadIdx.x;
#pragma unroll
    for (int t = 0; t < kT; t++) {
        size_t base = ((size_t)(b * kT + t)) * (2 * kFD);
        ks[t][tid] = kv[base + tid];
        vs[t][tid] = kv[base + kFD + tid];
    }
    q4[tid] = q4g[(size_t)b * kFD + tid];
    __syncthreads();
    int warp = tid >> 5, lane = tid & 31;
    for (int p = warp; p < 4 * kT; p += 8) {
        int h = p / kT, kt = p % kT;
        float s = 0.f;
        for (int d = lane; d < 64; d += 32) s += q4[h * 64 + d] * ks[kt][h * 64 + d];
#pragma unroll
        for (int m = 16; m; m >>= 1) s += __shfl_xor_sync(0xffffffffu, s, m);
        if (lane == 0) sc[h][kt] = s * 0.125f;
    }
    __syncthreads();
    if (tid < 4) {
        int h = tid;
        float mx = -1e30f;
#pragma unroll
        for (int kt = 0; kt < kT; kt++) mx = fmaxf(mx, sc[h][kt]);
        float e[kT], sum = 0.f;
#pragma unroll
        for (int kt = 0; kt < kT; kt++) { e[kt] = __expf(sc[h][kt] - mx); sum += e[kt]; }
#pragma unroll
        for (int kt = 0; kt < kT; kt++) attnw[h][kt] = e[kt] / sum;
    }
    __syncthreads();
    int h = tid >> 6;
    float acc = 0.f;
#pragma unroll
    for (int kt = 0; kt < kT; kt++) acc += attnw[h][kt] * vs[kt][tid];
    ctx4[(size_t)b * kFD + tid] = acc;
}

// ===================================================================
extern "C" void kernel_launch(void* const* d_in, const int* in_sizes, int n_in,
                              void* d_out, int out_size) {
    const float* signals = (const float*)d_in[0];
    const float* nact    = (const float*)d_in[1];
    const float* w0      = (const float*)d_in[2];
    const float* asrc0   = (const float*)d_in[3];
    const float* adst0   = (const float*)d_in[4];
    const float* bias0   = (const float*)d_in[5];
    const float* w1      = (const float*)d_in[6];
    const float* asrc1   = (const float*)d_in[7];
    const float* adst1   = (const float*)d_in[8];
    const float* bias1   = (const float*)d_in[9];
    const float* inw     = (const float*)d_in[10];
    const float* inb     = (const float*)d_in[11];
    const float* outw    = (const float*)d_in[12];
    const float* outb    = (const float*)d_in[13];
    const float* wmean   = (const float*)d_in[14];
    const float* bmean   = (const float*)d_in[15];
    const float* wlogv   = (const float*)d_in[16];
    const float* blogv   = (const float*)d_in[17];
    const float* wbel    = (const float*)d_in[18];
    const float* bbel    = (const float*)d_in[19];
    float* out = (float*)d_out;

    float *y, *seq, *kv, *q4, *ctx4, *feat, *blg, *v1, *u0, *w0t;
    cudaGetSymbolAddress((void**)&y,    g_y);
    cudaGetSymbolAddress((void**)&seq,  g_seq);
    cudaGetSymbolAddress((void**)&kv,   g_kv);
    cudaGetSymbolAddress((void**)&q4,   g_q4);
    cudaGetSymbolAddress((void**)&ctx4, g_ctx4);
    cudaGetSymbolAddress((void**)&feat, g_feat);
    cudaGetSymbolAddress((void**)&blg,  g_blog);
    cudaGetSymbolAddress((void**)&v1,   g_v1);
    cudaGetSymbolAddress((void**)&u0,   g_u0);
    cudaGetSymbolAddress((void**)&w0t,  g_w0t);

    // 1. prep
    prep_kernel<<<91, 256>>>(w1, asrc1, adst1, w0, asrc0, adst0, v1, w0t, u0);
    // 2. GNN phase 1 -> y
    gnn_phase1<<<kT * kB, 256>>>(signals, nact, w0t, u0, bias0, v1, y);
    // 3. layer-1 projection (tf32, 128x64) -> seq
    proj_tf32<<<dim3(kB * kT / 128, 4), 256>>>(y, w1, bias1, seq);
    // 4. q + kv projection (tf32, 128x64)
    qkv_tf32<<<dim3(kB * kT / 128, 9), 256>>>(seq, inw, inb, kv, q4);
    // 5. attention
    attn_kernel<<<kB, 256>>>(kv, q4, ctx4);
    // 6. out_proj (tf32, 64x64)
    outproj_tf32<<<dim3(kB / 64, 4), 256>>>(ctx4, outw, outb, feat);
    // 7. heads (tf32, 64x64; belief softmax fused)
    heads_tf32<<<dim3(kB / 64, 5), 256>>>(feat, wmean, bmean, wlogv, blogv, wbel, bbel,
                                          out, blg);
}

// round 13
// speedup vs baseline: 3.8787x; 1.0117x over previous
#include <cuda_runtime.h>
#include <math.h>

static constexpr int kT = 5, kB = 512, kNA = 16, kS = 64, kA = 16;
static constexpr int kHID = 64, kH = 4, kFD = 256, kLAT = 128;
static constexpr int kN = kB * kNA;
static constexpr int kFIN = 80;

// -------- scratch (static device globals) --------
__device__ float g_y   [(size_t)kB * kT * 4 * kFD];
__device__ float g_seq [(size_t)kB * kT * kFD];
__device__ float g_kv  [(size_t)kB * kT * 2 * kFD];
__device__ float g_q4  [(size_t)kB * kFD];
__device__ float g_ctx4[(size_t)kB * kFD];
__device__ float g_feat[(size_t)kB * kFD];
__device__ float g_blog[(size_t)kB * kS];
__device__ float g_v1  [2 * 4 * kFD];
__device__ float g_u0  [2 * 4 * kFIN];
__device__ float g_w0t [kFIN * kFD];
__device__ float g_sigp[(size_t)kT * kB * kFD];   // sigproj: (t*512+g, 256)

// ===================================================================
// Prep: v1 + w0t + u0 + sigproj GEMM. grid = 251.
// ===================================================================
__global__ __launch_bounds__(256)
void prep_kernel(const float* __restrict__ w1, const float* __restrict__ asrc1,
                 const float* __restrict__ adst1, const float* __restrict__ w0,
                 const float* __restrict__ asrc0, const float* __restrict__ adst0,
                 const float* __restrict__ signals,
                 float* __restrict__ v1, float* __restrict__ w0t,
                 float* __restrict__ u0, float* __restrict__ sigp) {
    int bid = blockIdx.x, tid = threadIdx.x;
    if (bid < 8) {
        int idx = bid * 256 + tid;
        int which = idx >> 10;
        int h = (idx >> 8) & 3;
        int k = idx & 255;
        const float* a = which ? adst1 : asrc1;
        float acc = 0.f;
#pragma unroll
        for (int c = 0; c < 64; c++)
            acc += a[h * 64 + c] * w1[(size_t)(h * 64 + c) * kFD + k];
        v1[which * 1024 + h * 256 + k] = acc;
        return;
    }
    if (bid < 88) {
        int c = bid - 8;
        w0t[(size_t)c * kFD + tid] = w0[(size_t)tid * kFIN + c];
        return;
    }
    if (bid < 91) {
        int idx = (bid - 88) * 256 + tid;
        if (idx >= 640) return;
        int which = idx / 320;
        int r = idx % 320;
        int h = r / 80, f = r % 80;
        const float* a = which ? adst0 : asrc0;
        float acc = 0.f;
#pragma unroll
        for (int c = 0; c < 64; c++)
            acc += a[h * 64 + c] * w0[(size_t)(h * 64 + c) * kFIN + f];
        u0[idx] = acc;
        return;
    }
    // sigproj: 16 rows per block; sigp[r][d] = sum_c signals[r][c] * w0[d*80+c]
    {
        __shared__ float sigs[16][64];
        int r0 = (bid - 91) * 16;
#pragma unroll
        for (int i = 0; i < 4; i++) {
            int idx = tid + i * 256;
            sigs[idx >> 6][idx & 63] = signals[(size_t)(r0 + (idx >> 6)) * kS + (idx & 63)];
        }
        __syncthreads();
        float acc[16];
#pragma unroll
        for (int i = 0; i < 16; i++) acc[i] = 0.f;
        for (int c = 0; c < 64; c++) {
            float w = w0[(size_t)tid * kFIN + c];
#pragma unroll
            for (int i = 0; i < 16; i++) acc[i] += sigs[i][c] * w;
        }
#pragma unroll
        for (int i = 0; i < 16; i++)
            sigp[(size_t)(r0 + i) * kFD + tid] = acc[i];
    }
}

// ===================================================================
// GNN phase 1: one block per (t, g). 2560 blocks. sigproj precomputed.
// ===================================================================
__global__ __launch_bounds__(256)
void gnn_phase1(const float* __restrict__ signals, const float* __restrict__ nact,
                const float* __restrict__ w0t, const float* __restrict__ u0,
                const float* __restrict__ bias0, const float* __restrict__ v1,
                const float* __restrict__ sigp, float* __restrict__ y) {
    __shared__ float acts[16][16];
    __shared__ float sig[64];
    __shared__ float us[320], ud[320];
    __shared__ float es0[16][4], ed0[16][4];
    __shared__ float alpha0[16][16][4];
    __shared__ float beta[16][4][16];
    __shared__ float gam[16][4];
    __shared__ float x1s[16][256];
    __shared__ float vs1[4][256], vd1[4][256];
    __shared__ float es1[16][4], ed1s[4], alpha1[16][4];

    int bid = blockIdx.x;
    int t = bid >> 9;
    int g = bid & 511;
    int tid = threadIdx.x;

    float Wa[16];
#pragma unroll
    for (int k = 0; k < 16; k++) Wa[k] = w0t[(size_t)(64 + k) * kFD + tid];
    float b0 = bias0[tid];
    float sp = sigp[(size_t)bid * kFD + tid];

    acts[tid >> 4][tid & 15] = nact[((size_t)t * kB + g) * (kNA * kA) + tid];
    if (tid < 64) sig[tid] = signals[((size_t)t * kB + g) * kS + tid];
#pragma unroll
    for (int i = 0; i < 2; i++) {
        int f = tid + i * 256;
        if (f < 320) { us[f] = u0[f]; ud[f] = u0[320 + f]; }
    }
#pragma unroll
    for (int h = 0; h < 4; h++) {
        vs1[h][tid] = v1[h * 256 + tid];
        vd1[h][tid] = v1[1024 + h * 256 + tid];
    }
    __syncthreads();

    if (tid < 128) {
        int which = tid >> 6;
        int p = tid & 63;
        int j = p >> 2, h = p & 3;
        const float* u = which ? ud : us;
        float e = 0.f;
#pragma unroll
        for (int k = 0; k < 16; k++) e += acts[j][k] * u[h * 80 + 64 + k];
        if (j == 0) {
#pragma unroll
            for (int c = 0; c < 64; c++) e += sig[c] * u[h * 80 + c];
        }
        if (which) ed0[j][h] = e; else es0[j][h] = e;
    }
    __syncthreads();

    if (tid < 64) {
        int n = tid >> 2, h = tid & 3;
        float base = ed0[n][h];
        float ev[16];
        float mx = -1e30f;
#pragma unroll
        for (int j = 0; j < 16; j++) {
            float e = es0[j][h] + base;
            e = e > 0.f ? e : 0.2f * e;
            ev[j] = e;
            mx = fmaxf(mx, e);
        }
        float sum = 0.f;
#pragma unroll
        for (int j = 0; j < 16; j++) { ev[j] = __expf(ev[j] - mx); sum += ev[j]; }
        float inv = 1.f / sum;
#pragma unroll
        for (int j = 0; j < 16; j++) alpha0[n][j][h] = ev[j] * inv;
    }
    __syncthreads();

    {
        int n = tid >> 4, h = (tid >> 2) & 3, kg = tid & 3;
        float bacc[4] = {0.f, 0.f, 0.f, 0.f};
#pragma unroll
        for (int j = 0; j < 16; j++) {
            float a = alpha0[n][j][h];
#pragma unroll
            for (int kk = 0; kk < 4; kk++) bacc[kk] += a * acts[j][kg * 4 + kk];
        }
#pragma unroll
        for (int kk = 0; kk < 4; kk++) beta[n][h][kg * 4 + kk] = bacc[kk];
        if (kg == 0) gam[n][h] = alpha0[n][0][h];
    }
    __syncthreads();

    int hd = tid >> 6;
    float x1r[16];
    {
#pragma unroll
        for (int n = 0; n < 16; n++) {
            float acc = gam[n][hd] * sp;
#pragma unroll
            for (int k = 0; k < 16; k++) acc += beta[n][hd][k] * Wa[k];
            acc = fmaxf(acc + b0, 0.f);
            x1r[n] = acc;
            x1s[n][tid] = acc;
        }
    }
    __syncthreads();

    {
        int p = tid >> 2, q = tid & 3;
        int j = p >> 2, h = p & 3;
        float acc = 0.f;
#pragma unroll
        for (int c = q * 64; c < q * 64 + 64; c++) acc += x1s[j][c] * vs1[h][c];
        acc += __shfl_xor_sync(0xffffffffu, acc, 1);
        acc += __shfl_xor_sync(0xffffffffu, acc, 2);
        if (q == 0) es1[j][h] = acc;
    }
    if (tid < 32) {
        int h = tid >> 3, q = tid & 7;
        float acc = 0.f;
#pragma unroll
        for (int c = q * 32; c < q * 32 + 32; c++) acc += x1s[0][c] * vd1[h][c];
        acc += __shfl_xor_sync(0xffffffffu, acc, 1);
        acc += __shfl_xor_sync(0xffffffffu, acc, 2);
        acc += __shfl_xor_sync(0xffffffffu, acc, 4);
        if (q == 0) ed1s[h] = acc;
    }
    __syncthreads();

    if (tid < 4) {
        int h = tid;
        float base = ed1s[h];
        float ev[16];
        float mx = -1e30f;
#pragma unroll
        for (int j = 0; j < 16; j++) {
            float e = es1[j][h] + base;
            e = e > 0.f ? e : 0.2f * e;
            ev[j] = e;
            mx = fmaxf(mx, e);
        }
        float sum = 0.f;
#pragma unroll
        for (int j = 0; j < 16; j++) { ev[j] = __expf(ev[j] - mx); sum += ev[j]; }
        float inv = 1.f / sum;
#pragma unroll
        for (int j = 0; j < 16; j++) alpha1[j][h] = ev[j] * inv;
    }
    __syncthreads();

#pragma unroll
    for (int h = 0; h < 4; h++) {
        float acc = 0.f;
#pragma unroll
        for (int j = 0; j < 16; j++) acc += alpha1[j][h] * x1r[j];
        y[(((size_t)g * kT + t) * 4 + h) * kFD + tid] = acc;
    }
}

// ===================================================================
// TF32 mma helpers
// ===================================================================
__device__ __forceinline__ unsigned f2tf(float x) {
    unsigned u;
    asm("cvt.rna.tf32.f32 %0, %1;" : "=r"(u) : "f"(x));
    return u;
}

// ---------------- 128x64 tile, K-chunk 32, XOR-swizzled smem ----------------
// sA: 2 x 128 x 32 u32 (32KB); sB: 2 x 64 x 32 u32 (16KB). 48KB total.
// addr(r, c4, e) = buf*RC + r*32 + 4*(c4 ^ (r&7)) + e  — conflict-free frag LDS.
#define IA(b,r,c4) ((b)*4096 + (r)*32 + 4*((c4) ^ ((r)&7)))
#define IB(b,r,c4) ((b)*2048 + (r)*32 + 4*((c4) ^ ((r)&7)))

__device__ __forceinline__
void tf32_tile128(const float* __restrict__ A, int lda,
                  const float* __restrict__ Wt, const float* __restrict__ bias,
                  float* __restrict__ C, int ldc, int row0, int relu,
                  unsigned* sA, unsigned* sB) {
    int tid = threadIdx.x;
    int lane = tid & 31, warp = tid >> 5;
    int wm = warp & 3, wn = warp >> 2;
    int g4 = lane >> 2, l4 = lane & 3;

    float c[2][4][4];
#pragma unroll
    for (int mt = 0; mt < 2; mt++)
#pragma unroll
        for (int nt = 0; nt < 4; nt++)
#pragma unroll
            for (int i = 0; i < 4; i++) c[mt][nt][i] = 0.f;

    // chunk 0 direct load
#pragma unroll
    for (int i = 0; i < 4; i++) {
        int idx = tid + i * 256;
        int r = idx >> 3, c4 = idx & 7;
        float4 v = *(const float4*)&A[(size_t)(row0 + r) * lda + c4 * 4];
        unsigned* p = &sA[IA(0, r, c4)];
        p[0] = f2tf(v.x); p[1] = f2tf(v.y); p[2] = f2tf(v.z); p[3] = f2tf(v.w);
    }
#pragma unroll
    for (int i = 0; i < 2; i++) {
        int idx = tid + i * 256;
        int r = idx >> 3, c4 = idx & 7;
        float4 w = *(const float4*)&Wt[(size_t)r * 256 + c4 * 4];
        unsigned* p = &sB[IB(0, r, c4)];
        p[0] = f2tf(w.x); p[1] = f2tf(w.y); p[2] = f2tf(w.z); p[3] = f2tf(w.w);
    }
    __syncthreads();

    for (int ch = 0; ch < 8; ch++) {
        int buf = ch & 1;
        float4 pa[4], pw[2];
        if (ch < 7) {
            int k0 = (ch + 1) * 32;
#pragma unroll
            for (int i = 0; i < 4; i++) {
                int idx = tid + i * 256;
                int r = idx >> 3, c4 = idx & 7;
                pa[i] = *(const float4*)&A[(size_t)(row0 + r) * lda + k0 + c4 * 4];
            }
#pragma unroll
            for (int i = 0; i < 2; i++) {
                int idx = tid + i * 256;
                int r = idx >> 3, c4 = idx & 7;
                pw[i] = *(const float4*)&Wt[(size_t)r * 256 + k0 + c4 * 4];
            }
        }
#pragma unroll
        for (int kk = 0; kk < 4; kk++) {
            unsigned af[2][4], bf[4][2];
#pragma unroll
            for (int mt = 0; mt < 2; mt++) {
                int ar = wm * 32 + mt * 16 + g4;
                af[mt][0] = sA[IA(buf, ar,     kk * 2    ) + l4];
                af[mt][1] = sA[IA(buf, ar + 8, kk * 2    ) + l4];
                af[mt][2] = sA[IA(buf, ar,     kk * 2 + 1) + l4];
                af[mt][3] = sA[IA(buf, ar + 8, kk * 2 + 1) + l4];
            }
#pragma unroll
            for (int nt = 0; nt < 4; nt++) {
                int br = wn * 32 + nt * 8 + g4;
                bf[nt][0] = sB[IB(buf, br, kk * 2    ) + l4];
                bf[nt][1] = sB[IB(buf, br, kk * 2 + 1) + l4];
            }
#pragma unroll
            for (int mt = 0; mt < 2; mt++)
#pragma unroll
                for (int nt = 0; nt < 4; nt++) {
                    asm volatile(
                        "mma.sync.aligned.m16n8k8.row.col.f32.tf32.tf32.f32 "
                        "{%0,%1,%2,%3}, {%4,%5,%6,%7}, {%8,%9}, {%0,%1,%2,%3};"
                        : "+f"(c[mt][nt][0]), "+f"(c[mt][nt][1]),
                          "+f"(c[mt][nt][2]), "+f"(c[mt][nt][3])
                        : "r"(af[mt][0]), "r"(af[mt][1]), "r"(af[mt][2]), "r"(af[mt][3]),
                          "r"(bf[nt][0]), "r"(bf[nt][1]));
                }
        }
        if (ch < 7) {
            int nb = buf ^ 1;
#pragma unroll
            for (int i = 0; i < 4; i++) {
                int idx = tid + i * 256;
                int r = idx >> 3, c4 = idx & 7;
                unsigned* p = &sA[IA(nb, r, c4)];
                p[0] = f2tf(pa[i].x); p[1] = f2tf(pa[i].y);
                p[2] = f2tf(pa[i].z); p[3] = f2tf(pa[i].w);
            }
#pragma unroll
            for (int i = 0; i < 2; i++) {
                int idx = tid + i * 256;
                int r = idx >> 3, c4 = idx & 7;
                unsigned* p = &sB[IB(nb, r, c4)];
                p[0] = f2tf(pw[i].x); p[1] = f2tf(pw[i].y);
                p[2] = f2tf(pw[i].z); p[3] = f2tf(pw[i].w);
            }
        }
        __syncthreads();
    }

#pragma unroll
    for (int mt = 0; mt < 2; mt++) {
        int r = row0 + wm * 32 + mt * 16 + g4;
#pragma unroll
        for (int nt = 0; nt < 4; nt++) {
            int cc = wn * 32 + nt * 8 + 2 * l4;
            float b0v = bias[cc], b1v = bias[cc + 1];
            float v0 = c[mt][nt][0] + b0v, v1 = c[mt][nt][1] + b1v;
            float v2 = c[mt][nt][2] + b0v, v3 = c[mt][nt][3] + b1v;
            if (relu) {
                v0 = fmaxf(v0, 0.f); v1 = fmaxf(v1, 0.f);
                v2 = fmaxf(v2, 0.f); v3 = fmaxf(v3, 0.f);
            }
            C[(size_t)r * ldc + cc] = v0;
            C[(size_t)r * ldc + cc + 1] = v1;
            C[(size_t)(r + 8) * ldc + cc] = v2;
            C[(size_t)(r + 8) * ldc + cc + 1] = v3;
        }
    }
}

// ---------------- 64x64 tile (R9 config, unchanged) ----------------
#define SA64(b,r,c) sA[(b)*(64*20) + (r)*20 + (c)]
#define SB64(b,r,c) sB[(b)*(64*20) + (r)*20 + (c)]

__device__ __forceinline__
void tf32_tile64(const float* __restrict__ A, int lda,
                 const float* __restrict__ Wt, const float* __restrict__ bias,
                 float* __restrict__ C, int ldc, int row0, int relu,
                 unsigned* sA, unsigned* sB) {
    int tid = threadIdx.x;
    int lane = tid & 31, warp = tid >> 5;
    int wm = warp & 1, wn = warp >> 1;
    int g4 = lane >> 2, l4 = lane & 3;
    int r = tid >> 2, c4 = tid & 3;

    float c[2][2][4];
#pragma unroll
    for (int mt = 0; mt < 2; mt++)
#pragma unroll
        for (int nt = 0; nt < 2; nt++)
#pragma unroll
            for (int i = 0; i < 4; i++) c[mt][nt][i] = 0.f;

    {
        float4 v = *(const float4*)&A[(size_t)(row0 + r) * lda + c4 * 4];
        SA64(0, r, c4 * 4 + 0) = f2tf(v.x); SA64(0, r, c4 * 4 + 1) = f2tf(v.y);
        SA64(0, r, c4 * 4 + 2) = f2tf(v.z); SA64(0, r, c4 * 4 + 3) = f2tf(v.w);
        float4 w = *(const float4*)&Wt[(size_t)r * 256 + c4 * 4];
        SB64(0, r, c4 * 4 + 0) = f2tf(w.x); SB64(0, r, c4 * 4 + 1) = f2tf(w.y);
        SB64(0, r, c4 * 4 + 2) = f2tf(w.z); SB64(0, r, c4 * 4 + 3) = f2tf(w.w);
    }
    __syncthreads();

    for (int ch = 0; ch < 16; ch++) {
        int buf = ch & 1;
        float4 pa, pb;
        if (ch < 15) {
            int k0 = (ch + 1) * 16;
            pa = *(const float4*)&A[(size_t)(row0 + r) * lda + k0 + c4 * 4];
            pb = *(const float4*)&Wt[(size_t)r * 256 + k0 + c4 * 4];
        }
#pragma unroll
        for (int kk = 0; kk < 2; kk++) {
            unsigned af[2][4], bf[2][2];
#pragma unroll
            for (int mt = 0; mt < 2; mt++) {
                int ar = wm * 32 + mt * 16 + g4;
                int ac = kk * 8 + l4;
                af[mt][0] = SA64(buf, ar, ac);
                af[mt][1] = SA64(buf, ar + 8, ac);
                af[mt][2] = SA64(buf, ar, ac + 4);
                af[mt][3] = SA64(buf, ar + 8, ac + 4);
            }
#pragma unroll
            for (int nt = 0; nt < 2; nt++) {
                int br = wn * 16 + nt * 8 + g4;
                bf[nt][0] = SB64(buf, br, kk * 8 + l4);
                bf[nt][1] = SB64(buf, br, kk * 8 + l4 + 4);
            }
#pragma unroll
            for (int mt = 0; mt < 2; mt++)
#pragma unroll
                for (int nt = 0; nt < 2; nt++) {
                    asm volatile(
                        "mma.sync.aligned.m16n8k8.row.col.f32.tf32.tf32.f32 "
                        "{%0,%1,%2,%3}, {%4,%5,%6,%7}, {%8,%9}, {%0,%1,%2,%3};"
                        : "+f"(c[mt][nt][0]), "+f"(c[mt][nt][1]),
                          "+f"(c[mt][nt][2]), "+f"(c[mt][nt][3])
                        : "r"(af[mt][0]), "r"(af[mt][1]), "r"(af[mt][2]), "r"(af[mt][3]),
                          "r"(bf[nt][0]), "r"(bf[nt][1]));
                }
        }
        if (ch < 15) {
            int nb = buf ^ 1;
            SA64(nb, r, c4 * 4 + 0) = f2tf(pa.x); SA64(nb, r, c4 * 4 + 1) = f2tf(pa.y);
            SA64(nb, r, c4 * 4 + 2) = f2tf(pa.z); SA64(nb, r, c4 * 4 + 3) = f2tf(pa.w);
            SB64(nb, r, c4 * 4 + 0) = f2tf(pb.x); SB64(nb, r, c4 * 4 + 1) = f2tf(pb.y);
            SB64(nb, r, c4 * 4 + 2) = f2tf(pb.z); SB64(nb, r, c4 * 4 + 3) = f2tf(pb.w);
        }
        __syncthreads();
    }

#pragma unroll
    for (int mt = 0; mt < 2; mt++) {
        int rr = row0 + wm * 32 + mt * 16 + g4;
#pragma unroll
        for (int nt = 0; nt < 2; nt++) {
            int cc = wn * 16 + nt * 8 + 2 * l4;
            float b0v = bias[cc], b1v = bias[cc + 1];
            float v0 = c[mt][nt][0] + b0v, v1 = c[mt][nt][1] + b1v;
            float v2 = c[mt][nt][2] + b0v, v3 = c[mt][nt][3] + b1v;
            if (relu) {
                v0 = fmaxf(v0, 0.f); v1 = fmaxf(v1, 0.f);
                v2 = fmaxf(v2, 0.f); v3 = fmaxf(v3, 0.f);
            }
            C[(size_t)rr * ldc + cc] = v0;
            C[(size_t)rr * ldc + cc + 1] = v1;
            C[(size_t)(rr + 8) * ldc + cc] = v2;
            C[(size_t)(rr + 8) * ldc + cc + 1] = v3;
        }
    }
}

// layer-1 projection: grid (20, 4)
__global__ __launch_bounds__(256)
void proj_tf32(const float* __restrict__ y, const float* __restrict__ w1,
               const float* __restrict__ bias1, float* __restrict__ seq) {
    __shared__ unsigned sA[2 * 128 * 32], sB[2 * 64 * 32];
    int h = blockIdx.y;
    tf32_tile128(y + h * kFD, 4 * kFD,
                 w1 + (size_t)h * 64 * kFD, bias1 + h * 64,
                 seq + h * 64, kFD, blockIdx.x * 128, 1, sA, sB);
}

// q+kv projection: grid (20, 9)
__global__ __launch_bounds__(256)
void qkv_tf32(const float* __restrict__ seq, const float* __restrict__ inw,
              const float* __restrict__ inb, float* __restrict__ kv,
              float* __restrict__ q4) {
    __shared__ unsigned sA[2 * 128 * 32], sB[2 * 64 * 32];
    int by = blockIdx.y, bx = blockIdx.x;
    if (by < 8) {
        tf32_tile128(seq, kFD,
                     inw + (size_t)(256 + by * 64) * kFD, inb + 256 + by * 64,
                     kv + by * 64, 2 * kFD, bx * 128, 0, sA, sB);
    } else {
        if (bx >= 16) return;
        int rt = bx & 3, ct = bx >> 2;
        tf32_tile128(seq + 4 * kFD, kT * kFD,
                     inw + (size_t)ct * 64 * kFD, inb + ct * 64,
                     q4 + ct * 64, kFD, rt * 128, 0, sA, sB);
    }
}

// out_proj: grid (8, 4)
__global__ __launch_bounds__(256)
void outproj_tf32(const float* __restrict__ ctx4, const float* __restrict__ outw,
                  const float* __restrict__ outb, float* __restrict__ feat) {
    __shared__ unsigned sA[2 * 64 * 20], sB[2 * 64 * 20];
    int ct = blockIdx.y;
    tf32_tile64(ctx4, kFD, outw + (size_t)ct * 64 * kFD, outb + ct * 64,
                feat + ct * 64, kFD, blockIdx.x * 64, 0, sA, sB);
}

// heads: grid (8, 5)
__global__ __launch_bounds__(256)
void heads_tf32(const float* __restrict__ feat,
                const float* __restrict__ wmean, const float* __restrict__ bmean,
                const float* __restrict__ wlogv, const float* __restrict__ blogv,
                const float* __restrict__ wbel,  const float* __restrict__ bbel,
                float* __restrict__ out, float* __restrict__ blog) {
    __shared__ unsigned sA[2 * 64 * 20], sB[2 * 64 * 20];
    int by = blockIdx.y;
    int row0 = blockIdx.x * 64;
    if (by < 2) {
        tf32_tile64(feat, kFD, wmean + (size_t)by * 64 * kFD, bmean + by * 64,
                    out + by * 64, kLAT, row0, 0, sA, sB);
        return;
    }
    if (by < 4) {
        int ct = by - 2;
        tf32_tile64(feat, kFD, wlogv + (size_t)ct * 64 * kFD, blogv + ct * 64,
                    out + (size_t)kB * kLAT + ct * 64, kLAT, row0, 0, sA, sB);
        return;
    }
    tf32_tile64(feat, kFD, wbel, bbel, blog, kS, row0, 0, sA, sB);
    __syncthreads();
    int tid = threadIdx.x;
    int r = row0 + (tid >> 2);
    int q = tid & 3;
    float v[16];
    float mx = -1e30f;
#pragma unroll
    for (int i = 0; i < 4; i++) {
        float4 x = *(const float4*)&blog[(size_t)r * kS + q * 16 + i * 4];
        v[i * 4 + 0] = x.x; v[i * 4 + 1] = x.y; v[i * 4 + 2] = x.z; v[i * 4 + 3] = x.w;
        mx = fmaxf(fmaxf(fmaxf(mx, x.x), fmaxf(x.y, x.z)), x.w);
    }
    mx = fmaxf(mx, __shfl_xor_sync(0xffffffffu, mx, 1));
    mx = fmaxf(mx, __shfl_xor_sync(0xffffffffu, mx, 2));
    float sum = 0.f;
#pragma unroll
    for (int i = 0; i < 16; i++) { v[i] = __expf(v[i] - mx); sum += v[i]; }
    sum += __shfl_xor_sync(0xffffffffu, sum, 1);
    sum += __shfl_xor_sync(0xffffffffu, sum, 2);
    float inv = 1.f / sum;
    float* ob = out + (size_t)2 * kB * kLAT;
#pragma unroll
    for (int i = 0; i < 16; i++)
        ob[(size_t)r * kS + q * 16 + i] = v[i] * inv;
}

// ===================================================================
// Attention (unchanged)
// ===================================================================
__global__ __launch_bounds__(256)
void attn_kernel(const float* __restrict__ kv, const float* __restrict__ q4g,
                 float* __restrict__ ctx4) {
    int b = blockIdx.x;
    __shared__ float ks[kT][256], vs[kT][256], q4[256];
    __shared__ float sc[4][kT], attnw[4][kT];
    int tid = threadIdx.x;
#pragma unroll
    for (int t = 0; t < kT; t++) {
        size_t base = ((size_t)(b * kT + t)) * (2 * kFD);
        ks[t][tid] = kv[base + tid];
        vs[t][tid] = kv[base + kFD + tid];
    }
    q4[tid] = q4g[(size_t)b * kFD + tid];
    __syncthreads();
    int warp = tid >> 5, lane = tid & 31;
    for (int p = warp; p < 4 * kT; p += 8) {
        int h = p / kT, kt = p % kT;
        float s = 0.f;
        for (int d = lane; d < 64; d += 32) s += q4[h * 64 + d] * ks[kt][h * 64 + d];
#pragma unroll
        for (int m = 16; m; m >>= 1) s += __shfl_xor_sync(0xffffffffu, s, m);
        if (lane == 0) sc[h][kt] = s * 0.125f;
    }
    __syncthreads();
    if (tid < 4) {
        int h = tid;
        float mx = -1e30f;
#pragma unroll
        for (int kt = 0; kt < kT; kt++) mx = fmaxf(mx, sc[h][kt]);
        float e[kT], sum = 0.f;
#pragma unroll
        for (int kt = 0; kt < kT; kt++) { e[kt] = __expf(sc[h][kt] - mx); sum += e[kt]; }
#pragma unroll
        for (int kt = 0; kt < kT; kt++) attnw[h][kt] = e[kt] / sum;
    }
    __syncthreads();
    int h = tid >> 6;
    float acc = 0.f;
#pragma unroll
    for (int kt = 0; kt < kT; kt++) acc += attnw[h][kt] * vs[kt][tid];
    ctx4[(size_t)b * kFD + tid] = acc;
}

// ===================================================================
extern "C" void kernel_launch(void* const* d_in, const int* in_sizes, int n_in,
                              void* d_out, int out_size) {
    const float* signals = (const float*)d_in[0];
    const float* nact    = (const float*)d_in[1];
    const float* w0      = (const float*)d_in[2];
    const float* asrc0   = (const float*)d_in[3];
    const float* adst0   = (const float*)d_in[4];
    const float* bias0   = (const float*)d_in[5];
    const float* w1      = (const float*)d_in[6];
    const float* asrc1   = (const float*)d_in[7];
    const float* adst1   = (const float*)d_in[8];
    const float* bias1   = (const float*)d_in[9];
    const float* inw     = (const float*)d_in[10];
    const float* inb     = (const float*)d_in[11];
    const float* outw    = (const float*)d_in[12];
    const float* outb    = (const float*)d_in[13];
    const float* wmean   = (const float*)d_in[14];
    const float* bmean   = (const float*)d_in[15];
    const float* wlogv   = (const float*)d_in[16];
    const float* blogv   = (const float*)d_in[17];
    const float* wbel    = (const float*)d_in[18];
    const float* bbel    = (const float*)d_in[19];
    float* out = (float*)d_out;

    float *y, *seq, *kv, *q4, *ctx4, *feat, *blg, *v1, *u0, *w0t, *sigp;
    cudaGetSymbolAddress((void**)&y,    g_y);
    cudaGetSymbolAddress((void**)&seq,  g_seq);
    cudaGetSymbolAddress((void**)&kv,   g_kv);
    cudaGetSymbolAddress((void**)&q4,   g_q4);
    cudaGetSymbolAddress((void**)&ctx4, g_ctx4);
    cudaGetSymbolAddress((void**)&feat, g_feat);
    cudaGetSymbolAddress((void**)&blg,  g_blog);
    cudaGetSymbolAddress((void**)&v1,   g_v1);
    cudaGetSymbolAddress((void**)&u0,   g_u0);
    cudaGetSymbolAddress((void**)&w0t,  g_w0t);
    cudaGetSymbolAddress((void**)&sigp, g_sigp);

    // 1. prep (v1, w0t, u0, sigproj GEMM)
    prep_kernel<<<251, 256>>>(w1, asrc1, adst1, w0, asrc0, adst0, signals,
                              v1, w0t, u0, sigp);
    // 2. GNN phase 1 -> y
    gnn_phase1<<<kT * kB, 256>>>(signals, nact, w0t, u0, bias0, v1, sigp, y);
    // 3. layer-1 projection (tf32, KC=32) -> seq
    proj_tf32<<<dim3(kB * kT / 128, 4), 256>>>(y, w1, bias1, seq);
    // 4. q + kv projection (tf32, KC=32)
    qkv_tf32<<<dim3(kB * kT / 128, 9), 256>>>(seq, inw, inb, kv, q4);
    // 5. attention
    attn_kernel<<<kB, 256>>>(kv, q4, ctx4);
    // 6. out_proj
    outproj_tf32<<<dim3(kB / 64, 4), 256>>>(ctx4, outw, outb, feat);
    // 7. heads
    heads_tf32<<<dim3(kB / 64, 5), 256>>>(feat, wmean, bmean, wlogv, blogv, wbel, bbel,
                                          out, blg);
}